// round 1
// baseline (speedup 1.0000x reference)
#include <cuda_runtime.h>

#define Bv 2
#define Sv 2048
#define Dv 1024
#define Hv 16
#define HDv 64
#define FFv 4096
#define Ev 8
#define NTOK (Bv*Sv)          // 4096
#define MAXP 9216             // 2*NTOK + 8*128 padding
#define LNEPS 1e-5f

// ---------------- scratch (device globals; no runtime alloc) ----------------
__device__ float g_qkv[(size_t)NTOK * 3 * Dv];     // 48 MB
__device__ float g_ctx[(size_t)NTOK * Dv];         // 16 MB
__device__ float g_attnout[(size_t)NTOK * Dv];     // 16 MB
__device__ float g_x1[(size_t)NTOK * Dv];          // 16 MB
__device__ float g_logits[(size_t)NTOK * Ev];
__device__ float g_topw[(size_t)NTOK * 2];
__device__ int   g_topE[(size_t)NTOK * 2];
__device__ int   g_pos[(size_t)NTOK * 2];
__device__ int   g_counts[Ev];
__device__ int   g_cursor[Ev];
__device__ int   g_off[Ev + 1];
__device__ int   g_Mpad[1];
__device__ int   g_gather[MAXP];
__device__ float g_h[(size_t)MAXP * FFv];          // 151 MB
__device__ float g_eo[(size_t)MAXP * Dv];          // 37.7 MB

// ---------------- init: zero routing state, poison gather ----------------
__global__ void k_init() {
    int i = blockIdx.x * blockDim.x + threadIdx.x;
    if (i < MAXP) g_gather[i] = -1;
    if (i < Ev) g_counts[i] = 0;
}

// ---------------- generic NT SGEMM: C[M,N] = A[M,K] * B[N,K]^T + bias ------
// Optional: dM (device actual-M), row_map (A row gather, -1 => zero row),
// exp_off (9 entries, 128-aligned expert segments -> B/bias offset), relu.
__global__ __launch_bounds__(256) void sgemm_nt(
    const float* __restrict__ A, const float* __restrict__ Bm,
    const float* __restrict__ bias, float* __restrict__ C,
    int M, int Kd, int lda, int ldb, int ldc,
    const int* __restrict__ dM, const int* __restrict__ row_map,
    const int* __restrict__ exp_off, long bStride, int biasStride, int relu)
{
    int Mact = dM ? *dM : M;
    int row0 = blockIdx.y * 128;
    if (row0 >= Mact) return;
    int col0 = blockIdx.x * 128;

    if (exp_off) {
        int e = 0;
        while (row0 >= exp_off[e + 1]) e++;
        Bm += (long)e * bStride;
        bias += (long)e * biasStride;
    }

    __shared__ float As[8][132];
    __shared__ float Bs[8][132];

    int tid = threadIdx.x;
    int tx = tid & 15, ty = tid >> 4;
    int lr = tid >> 1;           // 0..127
    int lk = (tid & 1) * 4;      // 0 or 4

    int ar = row0 + lr;
    const float* Aptr = A;
    bool aval = (ar < Mact);
    if (aval) {
        if (row_map) {
            int rg = row_map[ar];
            if (rg < 0) aval = false; else Aptr = A + (long)rg * lda;
        } else {
            Aptr = A + (long)ar * lda;
        }
    }
    const float* Bptr = Bm + (long)(col0 + lr) * ldb;

    float acc[8][8];
    #pragma unroll
    for (int i = 0; i < 8; i++)
        #pragma unroll
        for (int j = 0; j < 8; j++) acc[i][j] = 0.f;

    for (int k0 = 0; k0 < Kd; k0 += 8) {
        float4 av = aval ? *(const float4*)(Aptr + k0 + lk) : make_float4(0.f,0.f,0.f,0.f);
        float4 bv = *(const float4*)(Bptr + k0 + lk);
        __syncthreads();
        As[lk + 0][lr] = av.x; As[lk + 1][lr] = av.y;
        As[lk + 2][lr] = av.z; As[lk + 3][lr] = av.w;
        Bs[lk + 0][lr] = bv.x; Bs[lk + 1][lr] = bv.y;
        Bs[lk + 2][lr] = bv.z; Bs[lk + 3][lr] = bv.w;
        __syncthreads();
        #pragma unroll
        for (int kk = 0; kk < 8; kk++) {
            float a[8], b[8];
            *(float4*)(a)     = *(const float4*)&As[kk][ty * 8];
            *(float4*)(a + 4) = *(const float4*)&As[kk][ty * 8 + 4];
            *(float4*)(b)     = *(const float4*)&Bs[kk][tx * 8];
            *(float4*)(b + 4) = *(const float4*)&Bs[kk][tx * 8 + 4];
            #pragma unroll
            for (int i = 0; i < 8; i++)
                #pragma unroll
                for (int j = 0; j < 8; j++)
                    acc[i][j] += a[i] * b[j];
        }
    }

    #pragma unroll
    for (int i = 0; i < 8; i++) {
        int r = row0 + ty * 8 + i;
        if (r >= Mact) continue;
        float* Crow = C + (long)r * ldc + col0 + tx * 8;
        float o[8];
        #pragma unroll
        for (int j = 0; j < 8; j++) {
            float c = acc[i][j] + (bias ? bias[col0 + tx * 8 + j] : 0.f);
            if (relu) c = fmaxf(c, 0.f);
            o[j] = c;
        }
        *(float4*)(Crow)     = *(float4*)(o);
        *(float4*)(Crow + 4) = *(float4*)(o + 4);
    }
}

// ---------------- flash attention, fp32, 1 q-row/thread -------------------
__global__ __launch_bounds__(128) void k_attn(const float* __restrict__ qkv,
                                              float* __restrict__ ctx)
{
    int bh = blockIdx.y;
    int b = bh >> 4, h = bh & 15;
    int tid = threadIdx.x;
    int qrow = blockIdx.x * 128 + tid;

    const float* qp = qkv + ((long)(b * Sv + qrow)) * (3 * Dv) + h * HDv;
    float q[64];
    #pragma unroll
    for (int d = 0; d < 64; d += 4) {
        float4 v = *(const float4*)(qp + d);
        q[d] = v.x * 0.125f; q[d+1] = v.y * 0.125f;
        q[d+2] = v.z * 0.125f; q[d+3] = v.w * 0.125f;
    }

    __shared__ float Ks[64][68];
    __shared__ float Vs[64][68];

    float o[64];
    #pragma unroll
    for (int d = 0; d < 64; d++) o[d] = 0.f;
    float m = -1e30f, l = 0.f;

    for (int kt = 0; kt < Sv / 64; kt++) {
        __syncthreads();
        {
            int j = tid >> 1, half = (tid & 1) * 32;
            const float* kp = qkv + ((long)(b * Sv + kt * 64 + j)) * (3 * Dv) + Dv + h * HDv + half;
            const float* vp = kp + Dv;
            #pragma unroll
            for (int t = 0; t < 32; t += 4) {
                *(float4*)&Ks[j][half + t] = *(const float4*)(kp + t);
                *(float4*)&Vs[j][half + t] = *(const float4*)(vp + t);
            }
        }
        __syncthreads();
        #pragma unroll 2
        for (int jj = 0; jj < 64; jj++) {
            float s = 0.f;
            #pragma unroll
            for (int d = 0; d < 64; d++) s += q[d] * Ks[jj][d];
            float mn = fmaxf(m, s);
            float corr = __expf(m - mn);
            float p = __expf(s - mn);
            l = l * corr + p;
            #pragma unroll
            for (int d = 0; d < 64; d++) o[d] = o[d] * corr + p * Vs[jj][d];
            m = mn;
        }
    }
    float inv = 1.f / l;
    float* op = ctx + ((long)(b * Sv + qrow)) * Dv + h * HDv;
    #pragma unroll
    for (int d = 0; d < 64; d += 4) {
        float4 v; v.x = o[d]*inv; v.y = o[d+1]*inv; v.z = o[d+2]*inv; v.w = o[d+3]*inv;
        *(float4*)(op + d) = v;
    }
}

// ---------------- residual add + layernorm (row of 1024, 256 thr) ----------
__global__ __launch_bounds__(256) void k_addln(const float* __restrict__ xa,
                                               const float* __restrict__ xb,
                                               const float* __restrict__ g,
                                               const float* __restrict__ bt,
                                               float* __restrict__ out)
{
    __shared__ float red[256];
    int n = blockIdx.x, tid = threadIdx.x;
    const float* pa = xa + (long)n * Dv;
    const float* pb = xb + (long)n * Dv;
    float v[4]; float s = 0.f;
    #pragma unroll
    for (int i = 0; i < 4; i++) {
        int d = tid + i * 256;
        v[i] = pa[d] + pb[d];
        s += v[i];
    }
    red[tid] = s; __syncthreads();
    for (int st = 128; st > 0; st >>= 1) { if (tid < st) red[tid] += red[tid + st]; __syncthreads(); }
    float mean = red[0] * (1.f / Dv);
    __syncthreads();
    float vs = 0.f;
    #pragma unroll
    for (int i = 0; i < 4; i++) { float t = v[i] - mean; vs += t * t; }
    red[tid] = vs; __syncthreads();
    for (int st = 128; st > 0; st >>= 1) { if (tid < st) red[tid] += red[tid + st]; __syncthreads(); }
    float rstd = rsqrtf(red[0] * (1.f / Dv) + LNEPS);
    #pragma unroll
    for (int i = 0; i < 4; i++) {
        int d = tid + i * 256;
        out[(long)n * Dv + d] = (v[i] - mean) * rstd * g[d] + bt[d];
    }
}

// ---------------- gate: logits, top-2, softmax weights ---------------------
__global__ __launch_bounds__(256) void k_gate(const float* __restrict__ x1,
                                              const float* __restrict__ gw,
                                              const float* __restrict__ gb)
{
    int n = blockIdx.x;
    int w = threadIdx.x >> 5, lane = threadIdx.x & 31;
    const float* xp = x1 + (long)n * Dv;
    const float* wp = gw + (long)w * Dv;
    float s = 0.f;
    for (int d = lane; d < Dv; d += 32) s += xp[d] * wp[d];
    #pragma unroll
    for (int off = 16; off; off >>= 1) s += __shfl_down_sync(0xffffffff, s, off);
    __shared__ float lg[Ev];
    if (lane == 0) lg[w] = s + gb[w];
    __syncthreads();
    if (threadIdx.x == 0) {
        float l[Ev];
        #pragma unroll
        for (int e = 0; e < Ev; e++) { l[e] = lg[e]; g_logits[(long)n * Ev + e] = l[e]; }
        int i0 = 0;
        #pragma unroll
        for (int e = 1; e < Ev; e++) if (l[e] > l[i0]) i0 = e;
        int i1 = -1;
        #pragma unroll
        for (int e = 0; e < Ev; e++) { if (e == i0) continue; if (i1 < 0 || l[e] > l[i1]) i1 = e; }
        float e1 = expf(l[i1] - l[i0]);
        float denom = 1.f + e1;
        g_topE[n * 2 + 0] = i0; g_topE[n * 2 + 1] = i1;
        g_topw[n * 2 + 0] = 1.f / denom; g_topw[n * 2 + 1] = e1 / denom;
        atomicAdd(&g_counts[i0], 1);
        atomicAdd(&g_counts[i1], 1);
    }
}

// ---------------- scan: 128-aligned expert segments ------------------------
__global__ void k_scan() {
    if (threadIdx.x == 0) {
        int t = 0;
        for (int e = 0; e < Ev; e++) {
            g_off[e] = t; g_cursor[e] = t;
            t += (g_counts[e] + 127) & ~127;
        }
        g_off[Ev] = t;
        g_Mpad[0] = t;
    }
}

// ---------------- assign: token -> slot ------------------------------------
__global__ void k_assign() {
    int i = blockIdx.x * blockDim.x + threadIdx.x;
    if (i >= NTOK * 2) return;
    int e = g_topE[i];
    int p = atomicAdd(&g_cursor[e], 1);
    g_gather[p] = i >> 1;
    g_pos[i] = p;
}

// ---------------- scatter + residual + LN2 -> output -----------------------
__global__ __launch_bounds__(256) void k_scatter_ln2(const float* __restrict__ x1,
                                                     const float* __restrict__ g,
                                                     const float* __restrict__ bt,
                                                     float* __restrict__ out)
{
    __shared__ float red[256];
    int n = blockIdx.x, tid = threadIdx.x;
    int p0 = g_pos[n * 2 + 0], p1 = g_pos[n * 2 + 1];
    float w0 = g_topw[n * 2 + 0], w1 = g_topw[n * 2 + 1];
    const float* px = x1 + (long)n * Dv;
    const float* pe0 = g_eo + (long)p0 * Dv;
    const float* pe1 = g_eo + (long)p1 * Dv;
    float v[4]; float s = 0.f;
    #pragma unroll
    for (int i = 0; i < 4; i++) {
        int d = tid + i * 256;
        v[i] = px[d] + w0 * pe0[d] + w1 * pe1[d];
        s += v[i];
    }
    red[tid] = s; __syncthreads();
    for (int st = 128; st > 0; st >>= 1) { if (tid < st) red[tid] += red[tid + st]; __syncthreads(); }
    float mean = red[0] * (1.f / Dv);
    __syncthreads();
    float vs = 0.f;
    #pragma unroll
    for (int i = 0; i < 4; i++) { float t = v[i] - mean; vs += t * t; }
    red[tid] = vs; __syncthreads();
    for (int st = 128; st > 0; st >>= 1) { if (tid < st) red[tid] += red[tid + st]; __syncthreads(); }
    float rstd = rsqrtf(red[0] * (1.f / Dv) + LNEPS);
    #pragma unroll
    for (int i = 0; i < 4; i++) {
        int d = tid + i * 256;
        out[(long)n * Dv + d] = (v[i] - mean) * rstd * g[d] + bt[d];
    }
}

// ---------------- load-balance loss ----------------------------------------
__global__ __launch_bounds__(256) void k_lb(float* __restrict__ out) {
    __shared__ float sm[256][Ev];
    int tid = threadIdx.x;
    float u[Ev];
    #pragma unroll
    for (int e = 0; e < Ev; e++) u[e] = 0.f;
    for (int n = tid; n < NTOK; n += 256) {
        float l[Ev], mx = -1e30f, s = 0.f;
        #pragma unroll
        for (int e = 0; e < Ev; e++) { l[e] = g_logits[(long)n * Ev + e]; mx = fmaxf(mx, l[e]); }
        #pragma unroll
        for (int e = 0; e < Ev; e++) { l[e] = expf(l[e] - mx); s += l[e]; }
        float inv = 1.f / s;
        #pragma unroll
        for (int e = 0; e < Ev; e++) u[e] += l[e] * inv;
    }
    #pragma unroll
    for (int e = 0; e < Ev; e++) sm[tid][e] = u[e];
    __syncthreads();
    for (int st = 128; st > 0; st >>= 1) {
        if (tid < st)
            #pragma unroll
            for (int e = 0; e < Ev; e++) sm[tid][e] += sm[tid + st][e];
        __syncthreads();
    }
    if (tid == 0) {
        float lb = 0.f;
        #pragma unroll
        for (int e = 0; e < Ev; e++) { float us = sm[0][e] * (1.f / NTOK); lb += us * us; }
        out[0] = (float)Ev * lb;
    }
}

// ---------------- launch ----------------------------------------------------
static void* symaddr(const void* s) { void* p = nullptr; cudaGetSymbolAddress(&p, s); return p; }

extern "C" void kernel_launch(void* const* d_in, const int* in_sizes, int n_in,
                              void* d_out, int out_size)
{
    (void)in_sizes; (void)n_in;
    const float* x    = (const float*)d_in[0];
    const float* inw  = (const float*)d_in[1];
    const float* inb  = (const float*)d_in[2];
    const float* outw = (const float*)d_in[3];
    const float* outb = (const float*)d_in[4];
    const float* ln1g = (const float*)d_in[5];
    const float* ln1b = (const float*)d_in[6];
    const float* gw   = (const float*)d_in[7];
    const float* gb   = (const float*)d_in[8];
    const float* w1   = (const float*)d_in[9];
    const float* b1   = (const float*)d_in[10];
    const float* w2   = (const float*)d_in[11];
    const float* b2   = (const float*)d_in[12];
    const float* ln2g = (const float*)d_in[13];
    const float* ln2b = (const float*)d_in[14];
    float* out = (float*)d_out;

    float* p_qkv  = (float*)symaddr(g_qkv);
    float* p_ctx  = (float*)symaddr(g_ctx);
    float* p_ao   = (float*)symaddr(g_attnout);
    float* p_x1   = (float*)symaddr(g_x1);
    float* p_h    = (float*)symaddr(g_h);
    float* p_eo   = (float*)symaddr(g_eo);
    int*   p_Mpad = (int*)symaddr(g_Mpad);
    int*   p_gath = (int*)symaddr(g_gather);
    int*   p_off  = (int*)symaddr(g_off);

    // 1. routing state init
    k_init<<<(MAXP + 255) / 256, 256>>>();

    // 2. qkv = x @ in_proj_w^T + b   [4096, 3072]
    sgemm_nt<<<dim3(3 * Dv / 128, NTOK / 128), 256>>>(
        x, inw, inb, p_qkv, NTOK, Dv, Dv, Dv, 3 * Dv,
        nullptr, nullptr, nullptr, 0, 0, 0);

    // 3. attention -> ctx
    k_attn<<<dim3(Sv / 128, Bv * Hv), 128>>>(p_qkv, p_ctx);

    // 4. attn_out = ctx @ out_w^T + b
    sgemm_nt<<<dim3(Dv / 128, NTOK / 128), 256>>>(
        p_ctx, outw, outb, p_ao, NTOK, Dv, Dv, Dv, Dv,
        nullptr, nullptr, nullptr, 0, 0, 0);

    // 5. x1 = LN1(x + attn_out)
    k_addln<<<NTOK, 256>>>(x, p_ao, ln1g, ln1b, p_x1);

    // 6. gate: logits + top-2
    k_gate<<<NTOK, 256>>>(p_x1, gw, gb);

    // 7-8. routing
    k_scan<<<1, 32>>>();
    k_assign<<<(NTOK * 2 + 255) / 256, 256>>>();

    // 9. h = relu(gather(x1) @ w1[e]^T + b1[e])   [Mpad, 4096]
    sgemm_nt<<<dim3(FFv / 128, MAXP / 128), 256>>>(
        p_x1, w1, b1, p_h, MAXP, Dv, Dv, Dv, FFv,
        p_Mpad, p_gath, p_off, (long)FFv * Dv, FFv, 1);

    // 10. eo = h @ w2[e]^T + b2[e]    [Mpad, 1024]
    sgemm_nt<<<dim3(Dv / 128, MAXP / 128), 256>>>(
        p_h, w2, b2, p_eo, MAXP, FFv, FFv, FFv, Dv,
        p_Mpad, nullptr, p_off, (long)Dv * FFv, Dv, 0);

    // 11. out = LN2(x1 + combine-weighted expert outputs)
    k_scatter_ln2<<<NTOK, 256>>>(p_x1, ln2g, ln2b, out);

    // 12. lb_loss appended after x2
    if (out_size > NTOK * Dv) {
        k_lb<<<1, 256>>>(out + (size_t)NTOK * Dv);
    }
}

// round 3
// speedup vs baseline: 2.4780x; 2.4780x over previous
#include <cuda_runtime.h>
#include <cstdint>

#define Bv 2
#define Sv 2048
#define Dv 1024
#define Hv 16
#define HDv 64
#define FFv 4096
#define Ev 8
#define NTOK (Bv*Sv)          // 4096
#define MAXP 9216             // 2*NTOK + 8*128 padding
#define LNEPS 1e-5f

typedef unsigned long long u64;

// ---------------- scratch (device globals; no runtime alloc) ----------------
__device__ float g_qkv[(size_t)NTOK * 3 * Dv];
__device__ float g_ctx[(size_t)NTOK * Dv];
__device__ float g_attnout[(size_t)NTOK * Dv];
__device__ float g_x1[(size_t)NTOK * Dv];
__device__ float g_xg[(size_t)MAXP * Dv];
__device__ float g_logits[(size_t)NTOK * Ev];
__device__ float g_topw[(size_t)NTOK * 2];
__device__ int   g_topE[(size_t)NTOK * 2];
__device__ int   g_pos[(size_t)NTOK * 2];
__device__ int   g_counts[Ev];
__device__ int   g_cursor[Ev];
__device__ int   g_off[Ev + 1];
__device__ int   g_Mpad[1];
__device__ int   g_gather[MAXP];
__device__ float g_h[(size_t)MAXP * FFv];
__device__ float g_eo[(size_t)MAXP * Dv];

// ======================= PTX helpers =======================
__device__ __forceinline__ unsigned smem_u32(const void* p) {
    unsigned a;
    asm("{ .reg .u64 t; cvta.to.shared.u64 t, %1; cvt.u32.u64 %0, t; }" : "=r"(a) : "l"(p));
    return a;
}

__device__ __forceinline__ void cpa16(unsigned dst, const void* src) {
    asm volatile("cp.async.cg.shared.global [%0], [%1], 16;" :: "r"(dst), "l"(src));
}

__device__ __forceinline__ unsigned to_tf32(float f) {
    unsigned r;
    asm("cvt.rna.tf32.f32 %0, %1;" : "=r"(r) : "f"(f));
    return r;
}

__device__ __forceinline__ void mma_tf32(float* c,
    unsigned a0, unsigned a1, unsigned a2, unsigned a3,
    unsigned b0, unsigned b1)
{
    asm volatile(
        "mma.sync.aligned.m16n8k8.row.col.f32.tf32.tf32.f32 "
        "{%0,%1,%2,%3}, {%4,%5,%6,%7}, {%8,%9}, {%0,%1,%2,%3};"
        : "+f"(c[0]), "+f"(c[1]), "+f"(c[2]), "+f"(c[3])
        : "r"(a0), "r"(a1), "r"(a2), "r"(a3), "r"(b0), "r"(b1));
}

// f32x2 packed math
#define FMA2(d,a,b,c) asm("fma.rn.f32x2 %0, %1, %2, %3;" : "=l"(d) : "l"(a), "l"(b), "l"(c))
#define ADD2(d,a,b)   asm("add.rn.f32x2 %0, %1, %2;" : "=l"(d) : "l"(a), "l"(b))
#define MUL2(d,a,b)   asm("mul.rn.f32x2 %0, %1, %2;" : "=l"(d) : "l"(a), "l"(b))
#define PACK2(d,lo,hi) asm("mov.b64 %0, {%1, %2};" : "=l"(d) : "f"(lo), "f"(hi))
#define UNPK2(lo,hi,v) asm("mov.b64 {%0, %1}, %2;" : "=f"(lo), "=f"(hi) : "l"(v))

// ======================= mma.sync tf32 GEMM =======================
// C[M,N] = A[M,K] * B[N,K]^T + bias. 128x128 CTA tile, K-tile 32, 256 thr.
// 8 warps in 2(m) x 4(n) grid; each warp 64x32 via m16n8k8.
#define KT 32
#define LDS_W 36                       // smem row stride in floats (padded)
#define AB_W (128 * LDS_W)             // one matrix tile in floats (4608)
#define STAGE_W (2 * AB_W)             // A + B (9216 floats)
#define GSMEM (2 * STAGE_W * 4)        // 2 stages, bytes (73728)

__device__ __forceinline__ void load_tile(unsigned sBase,
    const float* __restrict__ A, int lda, const float* __restrict__ Bm, int ldb,
    int row0, int col0, int k0, int tid)
{
    #pragma unroll
    for (int i = 0; i < 4; i++) {
        int idx = i * 256 + tid;
        int r = idx >> 3, c = idx & 7;           // 128 rows x 8 float4
        unsigned doff = (unsigned)((r * LDS_W + c * 4) * 4);
        cpa16(sBase + doff, A + (long)(row0 + r) * lda + k0 + c * 4);
        cpa16(sBase + AB_W * 4 + doff, Bm + (long)(col0 + r) * ldb + k0 + c * 4);
    }
}

extern __shared__ float smem_f[];

__global__ __launch_bounds__(256) void gemm_tc(
    const float* __restrict__ A, const float* __restrict__ Bm,
    const float* __restrict__ bias, float* __restrict__ C,
    int Kd, int lda, int ldb, int ldc,
    const int* __restrict__ dM, const int* __restrict__ exp_off,
    long bStride, int biasStride, int relu)
{
    int row0 = blockIdx.y * 128;
    if (dM && row0 >= *dM) return;
    int col0 = blockIdx.x * 128;
    if (exp_off) {
        int e = 0;
        while (row0 >= exp_off[e + 1]) e++;
        Bm += (long)e * bStride;
        bias += (long)e * biasStride;
    }
    int tid = threadIdx.x, lane = tid & 31, wid = tid >> 5;
    int warp_m = wid >> 2, warp_n = wid & 3;
    unsigned sb = smem_u32(smem_f);

    float acc[4][4][4];
    #pragma unroll
    for (int mt = 0; mt < 4; mt++)
        #pragma unroll
        for (int nt = 0; nt < 4; nt++)
            #pragma unroll
            for (int j = 0; j < 4; j++) acc[mt][nt][j] = 0.f;

    int nK = Kd / KT;
    load_tile(sb, A, lda, Bm, ldb, row0, col0, 0, tid);
    asm volatile("cp.async.commit_group;" ::: "memory");

    for (int kt = 0; kt < nK; kt++) {
        if (kt + 1 < nK) {
            load_tile(sb + ((kt + 1) & 1) * STAGE_W * 4,
                      A, lda, Bm, ldb, row0, col0, (kt + 1) * KT, tid);
            asm volatile("cp.async.commit_group;" ::: "memory");
            asm volatile("cp.async.wait_group 1;" ::: "memory");
        } else {
            asm volatile("cp.async.wait_group 0;" ::: "memory");
        }
        __syncthreads();

        const float* As = smem_f + (kt & 1) * STAGE_W;
        const float* Bs = As + AB_W;
        int rbase = warp_m * 64 + (lane >> 2);
        int nbase = warp_n * 32 + (lane >> 2);
        int kq = lane & 3;

        #pragma unroll
        for (int ks = 0; ks < 4; ks++) {
            unsigned af[4][4], bf[4][2];
            #pragma unroll
            for (int mt = 0; mt < 4; mt++) {
                const float* ap = As + (rbase + mt * 16) * LDS_W + ks * 8 + kq;
                af[mt][0] = to_tf32(ap[0]);
                af[mt][1] = to_tf32(ap[8 * LDS_W]);
                af[mt][2] = to_tf32(ap[4]);
                af[mt][3] = to_tf32(ap[8 * LDS_W + 4]);
            }
            #pragma unroll
            for (int nt = 0; nt < 4; nt++) {
                const float* bp = Bs + (nbase + nt * 8) * LDS_W + ks * 8 + kq;
                bf[nt][0] = to_tf32(bp[0]);
                bf[nt][1] = to_tf32(bp[4]);
            }
            #pragma unroll
            for (int mt = 0; mt < 4; mt++)
                #pragma unroll
                for (int nt = 0; nt < 4; nt++)
                    mma_tf32(acc[mt][nt], af[mt][0], af[mt][1], af[mt][2], af[mt][3],
                             bf[nt][0], bf[nt][1]);
        }
        __syncthreads();
    }

    // epilogue
    #pragma unroll
    for (int mt = 0; mt < 4; mt++) {
        int r = row0 + warp_m * 64 + mt * 16 + (lane >> 2);
        #pragma unroll
        for (int nt = 0; nt < 4; nt++) {
            int cg = col0 + warp_n * 32 + nt * 8 + (lane & 3) * 2;
            float b0 = bias[cg], b1 = bias[cg + 1];
            float v0 = acc[mt][nt][0] + b0, v1 = acc[mt][nt][1] + b1;
            float v2 = acc[mt][nt][2] + b0, v3 = acc[mt][nt][3] + b1;
            if (relu) {
                v0 = fmaxf(v0, 0.f); v1 = fmaxf(v1, 0.f);
                v2 = fmaxf(v2, 0.f); v3 = fmaxf(v3, 0.f);
            }
            *(float2*)(C + (long)r * ldc + cg) = make_float2(v0, v1);
            *(float2*)(C + (long)(r + 8) * ldc + cg) = make_float2(v2, v3);
        }
    }
}

// ======================= flash attention, f32x2 packed =======================
__global__ __launch_bounds__(128) void k_attn(const float* __restrict__ qkv,
                                              float* __restrict__ ctx)
{
    int bh = blockIdx.y;
    int b = bh >> 4, h = bh & 15;
    int tid = threadIdx.x;
    int qrow = blockIdx.x * 128 + tid;

    const float* qp = qkv + ((long)(b * Sv + qrow)) * (3 * Dv) + h * HDv;
    u64 q2[32];
    #pragma unroll
    for (int t = 0; t < 16; t++) {
        float4 v = *(const float4*)(qp + t * 4);
        v.x *= 0.125f; v.y *= 0.125f; v.z *= 0.125f; v.w *= 0.125f;
        PACK2(q2[2 * t], v.x, v.y);
        PACK2(q2[2 * t + 1], v.z, v.w);
    }

    __shared__ float Ks[32][64];
    __shared__ float Vs[32][64];

    u64 o2[32];
    #pragma unroll
    for (int d = 0; d < 32; d++) o2[d] = 0ull;
    float m = -1e30f, l = 0.f;

    union F4U { float4 f; u64 u[2]; };

    for (int kt = 0; kt < Sv / 32; kt++) {
        __syncthreads();
        #pragma unroll
        for (int i = 0; i < 4; i++) {
            int idx = i * 128 + tid;
            int row = idx >> 4, c = idx & 15;
            const float* kp = qkv + ((long)(b * Sv + kt * 32 + row)) * (3 * Dv) + Dv + h * HDv + c * 4;
            *(float4*)&Ks[row][c * 4] = *(const float4*)kp;
            *(float4*)&Vs[row][c * 4] = *(const float4*)(kp + Dv);
        }
        __syncthreads();

        float s[32];
        #pragma unroll
        for (int jj = 0; jj < 32; jj++) {
            u64 a0 = 0ull, a1 = 0ull, a2 = 0ull, a3 = 0ull;
            #pragma unroll
            for (int t = 0; t < 16; t += 2) {
                F4U k0, k1;
                k0.f = *(const float4*)&Ks[jj][t * 4];
                k1.f = *(const float4*)&Ks[jj][t * 4 + 4];
                FMA2(a0, q2[2 * t],     k0.u[0], a0);
                FMA2(a1, q2[2 * t + 1], k0.u[1], a1);
                FMA2(a2, q2[2 * t + 2], k1.u[0], a2);
                FMA2(a3, q2[2 * t + 3], k1.u[1], a3);
            }
            ADD2(a0, a0, a2); ADD2(a1, a1, a3); ADD2(a0, a0, a1);
            float lo, hi; UNPK2(lo, hi, a0);
            s[jj] = lo + hi;
        }

        float mt = s[0];
        #pragma unroll
        for (int jj = 1; jj < 32; jj++) mt = fmaxf(mt, s[jj]);
        float mn = fmaxf(m, mt);
        float corr = __expf(m - mn);
        m = mn;
        float lsum = 0.f;
        #pragma unroll
        for (int jj = 0; jj < 32; jj++) {
            float p = __expf(s[jj] - mn);
            s[jj] = p; lsum += p;
        }
        l = l * corr + lsum;
        u64 corr2; PACK2(corr2, corr, corr);
        #pragma unroll
        for (int d = 0; d < 32; d++) MUL2(o2[d], o2[d], corr2);

        #pragma unroll
        for (int jj = 0; jj < 32; jj++) {
            u64 p2; PACK2(p2, s[jj], s[jj]);
            #pragma unroll
            for (int t = 0; t < 16; t++) {
                F4U v; v.f = *(const float4*)&Vs[jj][t * 4];
                FMA2(o2[2 * t],     p2, v.u[0], o2[2 * t]);
                FMA2(o2[2 * t + 1], p2, v.u[1], o2[2 * t + 1]);
            }
        }
    }
    float inv = 1.f / l;
    float* op = ctx + ((long)(b * Sv + qrow)) * Dv + h * HDv;
    #pragma unroll
    for (int t = 0; t < 16; t++) {
        float a, bb, c, d;
        UNPK2(a, bb, o2[2 * t]);
        UNPK2(c, d, o2[2 * t + 1]);
        float4 v; v.x = a * inv; v.y = bb * inv; v.z = c * inv; v.w = d * inv;
        *(float4*)(op + t * 4) = v;
    }
}

// ======================= small kernels =======================
__global__ void k_init() {
    int i = blockIdx.x * blockDim.x + threadIdx.x;
    if (i < MAXP) g_gather[i] = -1;
    if (i < Ev) g_counts[i] = 0;
}

__global__ __launch_bounds__(256) void k_addln(const float* __restrict__ xa,
                                               const float* __restrict__ xb,
                                               const float* __restrict__ g,
                                               const float* __restrict__ bt,
                                               float* __restrict__ out)
{
    __shared__ float red[256];
    int n = blockIdx.x, tid = threadIdx.x;
    const float* pa = xa + (long)n * Dv;
    const float* pb = xb + (long)n * Dv;
    float v[4]; float s = 0.f;
    #pragma unroll
    for (int i = 0; i < 4; i++) { int d = tid + i * 256; v[i] = pa[d] + pb[d]; s += v[i]; }
    red[tid] = s; __syncthreads();
    for (int st = 128; st > 0; st >>= 1) { if (tid < st) red[tid] += red[tid + st]; __syncthreads(); }
    float mean = red[0] * (1.f / Dv);
    __syncthreads();
    float vs = 0.f;
    #pragma unroll
    for (int i = 0; i < 4; i++) { float t = v[i] - mean; vs += t * t; }
    red[tid] = vs; __syncthreads();
    for (int st = 128; st > 0; st >>= 1) { if (tid < st) red[tid] += red[tid + st]; __syncthreads(); }
    float rstd = rsqrtf(red[0] * (1.f / Dv) + LNEPS);
    #pragma unroll
    for (int i = 0; i < 4; i++) {
        int d = tid + i * 256;
        out[(long)n * Dv + d] = (v[i] - mean) * rstd * g[d] + bt[d];
    }
}

__global__ __launch_bounds__(256) void k_gate(const float* __restrict__ x1,
                                              const float* __restrict__ gw,
                                              const float* __restrict__ gb)
{
    int n = blockIdx.x;
    int w = threadIdx.x >> 5, lane = threadIdx.x & 31;
    const float* xp = x1 + (long)n * Dv;
    const float* wp = gw + (long)w * Dv;
    float s = 0.f;
    for (int d = lane; d < Dv; d += 32) s += xp[d] * wp[d];
    #pragma unroll
    for (int off = 16; off; off >>= 1) s += __shfl_down_sync(0xffffffff, s, off);
    __shared__ float lg[Ev];
    if (lane == 0) lg[w] = s + gb[w];
    __syncthreads();
    if (threadIdx.x == 0) {
        float l[Ev];
        #pragma unroll
        for (int e = 0; e < Ev; e++) { l[e] = lg[e]; g_logits[(long)n * Ev + e] = l[e]; }
        int i0 = 0;
        #pragma unroll
        for (int e = 1; e < Ev; e++) if (l[e] > l[i0]) i0 = e;
        int i1 = -1;
        #pragma unroll
        for (int e = 0; e < Ev; e++) { if (e == i0) continue; if (i1 < 0 || l[e] > l[i1]) i1 = e; }
        float e1 = expf(l[i1] - l[i0]);
        float denom = 1.f + e1;
        g_topE[n * 2 + 0] = i0; g_topE[n * 2 + 1] = i1;
        g_topw[n * 2 + 0] = 1.f / denom; g_topw[n * 2 + 1] = e1 / denom;
        atomicAdd(&g_counts[i0], 1);
        atomicAdd(&g_counts[i1], 1);
    }
}

__global__ void k_scan() {
    if (threadIdx.x == 0) {
        int t = 0;
        for (int e = 0; e < Ev; e++) {
            g_off[e] = t; g_cursor[e] = t;
            t += (g_counts[e] + 127) & ~127;
        }
        g_off[Ev] = t;
        g_Mpad[0] = t;
    }
}

__global__ void k_assign() {
    int i = blockIdx.x * blockDim.x + threadIdx.x;
    if (i >= NTOK * 2) return;
    int e = g_topE[i];
    int p = atomicAdd(&g_cursor[e], 1);
    g_gather[p] = i >> 1;
    g_pos[i] = p;
}

__global__ __launch_bounds__(256) void k_gather(const float* __restrict__ x1,
                                                float* __restrict__ xg)
{
    int p = blockIdx.x;
    int g = g_gather[p];
    float4* dst = (float4*)(xg + (long)p * Dv);
    if (g >= 0) {
        const float4* src = (const float4*)(x1 + (long)g * Dv);
        dst[threadIdx.x] = src[threadIdx.x];
    } else {
        dst[threadIdx.x] = make_float4(0.f, 0.f, 0.f, 0.f);
    }
}

__global__ __launch_bounds__(256) void k_scatter_ln2(const float* __restrict__ x1,
                                                     const float* __restrict__ g,
                                                     const float* __restrict__ bt,
                                                     float* __restrict__ out)
{
    __shared__ float red[256];
    int n = blockIdx.x, tid = threadIdx.x;
    int p0 = g_pos[n * 2 + 0], p1 = g_pos[n * 2 + 1];
    float w0 = g_topw[n * 2 + 0], w1 = g_topw[n * 2 + 1];
    const float* px = x1 + (long)n * Dv;
    const float* pe0 = g_eo + (long)p0 * Dv;
    const float* pe1 = g_eo + (long)p1 * Dv;
    float v[4]; float s = 0.f;
    #pragma unroll
    for (int i = 0; i < 4; i++) {
        int d = tid + i * 256;
        v[i] = px[d] + w0 * pe0[d] + w1 * pe1[d];
        s += v[i];
    }
    red[tid] = s; __syncthreads();
    for (int st = 128; st > 0; st >>= 1) { if (tid < st) red[tid] += red[tid + st]; __syncthreads(); }
    float mean = red[0] * (1.f / Dv);
    __syncthreads();
    float vs = 0.f;
    #pragma unroll
    for (int i = 0; i < 4; i++) { float t = v[i] - mean; vs += t * t; }
    red[tid] = vs; __syncthreads();
    for (int st = 128; st > 0; st >>= 1) { if (tid < st) red[tid] += red[tid + st]; __syncthreads(); }
    float rstd = rsqrtf(red[0] * (1.f / Dv) + LNEPS);
    #pragma unroll
    for (int i = 0; i < 4; i++) {
        int d = tid + i * 256;
        out[(long)n * Dv + d] = (v[i] - mean) * rstd * g[d] + bt[d];
    }
}

__global__ __launch_bounds__(256) void k_lb(float* __restrict__ out) {
    __shared__ float sm[256][Ev];
    int tid = threadIdx.x;
    float u[Ev];
    #pragma unroll
    for (int e = 0; e < Ev; e++) u[e] = 0.f;
    for (int n = tid; n < NTOK; n += 256) {
        float l[Ev], mx = -1e30f, s = 0.f;
        #pragma unroll
        for (int e = 0; e < Ev; e++) { l[e] = g_logits[(long)n * Ev + e]; mx = fmaxf(mx, l[e]); }
        #pragma unroll
        for (int e = 0; e < Ev; e++) { l[e] = expf(l[e] - mx); s += l[e]; }
        float inv = 1.f / s;
        #pragma unroll
        for (int e = 0; e < Ev; e++) u[e] += l[e] * inv;
    }
    #pragma unroll
    for (int e = 0; e < Ev; e++) sm[tid][e] = u[e];
    __syncthreads();
    for (int st = 128; st > 0; st >>= 1) {
        if (tid < st)
            #pragma unroll
            for (int e = 0; e < Ev; e++) sm[tid][e] += sm[tid + st][e];
        __syncthreads();
    }
    if (tid == 0) {
        float lb = 0.f;
        #pragma unroll
        for (int e = 0; e < Ev; e++) { float us = sm[0][e] * (1.f / NTOK); lb += us * us; }
        out[0] = (float)Ev * lb;
    }
}

// ======================= launch =======================
static void* symaddr(const void* s) { void* p = nullptr; cudaGetSymbolAddress(&p, s); return p; }

extern "C" void kernel_launch(void* const* d_in, const int* in_sizes, int n_in,
                              void* d_out, int out_size)
{
    (void)in_sizes; (void)n_in;
    const float* x    = (const float*)d_in[0];
    const float* inw  = (const float*)d_in[1];
    const float* inb  = (const float*)d_in[2];
    const float* outw = (const float*)d_in[3];
    const float* outb = (const float*)d_in[4];
    const float* ln1g = (const float*)d_in[5];
    const float* ln1b = (const float*)d_in[6];
    const float* gw   = (const float*)d_in[7];
    const float* gb   = (const float*)d_in[8];
    const float* w1   = (const float*)d_in[9];
    const float* b1   = (const float*)d_in[10];
    const float* w2   = (const float*)d_in[11];
    const float* b2   = (const float*)d_in[12];
    const float* ln2g = (const float*)d_in[13];
    const float* ln2b = (const float*)d_in[14];
    float* out = (float*)d_out;

    float* p_qkv  = (float*)symaddr(g_qkv);
    float* p_ctx  = (float*)symaddr(g_ctx);
    float* p_ao   = (float*)symaddr(g_attnout);
    float* p_x1   = (float*)symaddr(g_x1);
    float* p_xg   = (float*)symaddr(g_xg);
    float* p_h    = (float*)symaddr(g_h);
    float* p_eo   = (float*)symaddr(g_eo);
    int*   p_Mpad = (int*)symaddr(g_Mpad);
    int*   p_off  = (int*)symaddr(g_off);

    cudaFuncSetAttribute(gemm_tc, cudaFuncAttributeMaxDynamicSharedMemorySize, GSMEM);

    // 1. routing state init
    k_init<<<(MAXP + 255) / 256, 256>>>();

    // 2. qkv = x @ in_proj_w^T + b
    gemm_tc<<<dim3(3 * Dv / 128, NTOK / 128), 256, GSMEM>>>(
        x, inw, inb, p_qkv, Dv, Dv, Dv, 3 * Dv, nullptr, nullptr, 0, 0, 0);

    // 3. attention -> ctx
    k_attn<<<dim3(Sv / 128, Bv * Hv), 128>>>(p_qkv, p_ctx);

    // 4. attn_out = ctx @ out_w^T + b
    gemm_tc<<<dim3(Dv / 128, NTOK / 128), 256, GSMEM>>>(
        p_ctx, outw, outb, p_ao, Dv, Dv, Dv, Dv, nullptr, nullptr, 0, 0, 0);

    // 5. x1 = LN1(x + attn_out)
    k_addln<<<NTOK, 256>>>(x, p_ao, ln1g, ln1b, p_x1);

    // 6. gate
    k_gate<<<NTOK, 256>>>(p_x1, gw, gb);

    // 7-8. routing
    k_scan<<<1, 32>>>();
    k_assign<<<(NTOK * 2 + 255) / 256, 256>>>();

    // 9. gather tokens
    k_gather<<<MAXP, 256>>>(p_x1, p_xg);

    // 10. h = relu(xg @ w1[e]^T + b1[e])
    gemm_tc<<<dim3(FFv / 128, MAXP / 128), 256, GSMEM>>>(
        p_xg, w1, b1, p_h, Dv, Dv, Dv, FFv,
        p_Mpad, p_off, (long)FFv * Dv, FFv, 1);

    // 11. eo = h @ w2[e]^T + b2[e]
    gemm_tc<<<dim3(Dv / 128, MAXP / 128), 256, GSMEM>>>(
        p_h, w2, b2, p_eo, FFv, FFv, FFv, Dv,
        p_Mpad, p_off, (long)Dv * FFv, Dv, 0);

    // 12. out = LN2(x1 + moe)
    k_scatter_ln2<<<NTOK, 256>>>(p_x1, ln2g, ln2b, out);

    // 13. lb_loss
    if (out_size > NTOK * Dv) {
        k_lb<<<1, 256>>>(out + (size_t)NTOK * Dv);
    }
}

// round 4
// speedup vs baseline: 3.7401x; 1.5093x over previous
#include <cuda_runtime.h>
#include <cstdint>

#define Bv 2
#define Sv 2048
#define Dv 1024
#define Hv 16
#define HDv 64
#define FFv 4096
#define Ev 8
#define NTOK (Bv*Sv)          // 4096
#define MAXP 9216             // 2*NTOK + 8*128 padding
#define LNEPS 1e-5f

typedef unsigned long long u64;

// ---------------- scratch (device globals; no runtime alloc) ----------------
__device__ float g_qkv[(size_t)NTOK * 3 * Dv];
__device__ float g_ctx[(size_t)NTOK * Dv];
__device__ float g_attnout[(size_t)NTOK * Dv];
__device__ float g_x1[(size_t)NTOK * Dv];
__device__ float g_xg[(size_t)MAXP * Dv];
__device__ float g_logits[(size_t)NTOK * Ev];
__device__ float g_topw[(size_t)NTOK * 2];
__device__ int   g_topE[(size_t)NTOK * 2];
__device__ int   g_pos[(size_t)NTOK * 2];
__device__ int   g_counts[Ev];
__device__ int   g_cursor[Ev];
__device__ int   g_off[Ev + 1];
__device__ int   g_Mpad[1];
__device__ int   g_gather[MAXP];
__device__ float g_h[(size_t)MAXP * FFv];
__device__ float g_eo[(size_t)MAXP * Dv];

// ======================= PTX helpers =======================
__device__ __forceinline__ unsigned smem_u32(const void* p) {
    unsigned a;
    asm("{ .reg .u64 t; cvta.to.shared.u64 t, %1; cvt.u32.u64 %0, t; }" : "=r"(a) : "l"(p));
    return a;
}

__device__ __forceinline__ void cpa16(unsigned dst, const void* src) {
    asm volatile("cp.async.cg.shared.global [%0], [%1], 16;" :: "r"(dst), "l"(src));
}

__device__ __forceinline__ unsigned to_tf32(float f) {
    unsigned r;
    asm("cvt.rna.tf32.f32 %0, %1;" : "=r"(r) : "f"(f));
    return r;
}

__device__ __forceinline__ void mma_tf32(float* c,
    unsigned a0, unsigned a1, unsigned a2, unsigned a3,
    unsigned b0, unsigned b1)
{
    asm volatile(
        "mma.sync.aligned.m16n8k8.row.col.f32.tf32.tf32.f32 "
        "{%0,%1,%2,%3}, {%4,%5,%6,%7}, {%8,%9}, {%0,%1,%2,%3};"
        : "+f"(c[0]), "+f"(c[1]), "+f"(c[2]), "+f"(c[3])
        : "r"(a0), "r"(a1), "r"(a2), "r"(a3), "r"(b0), "r"(b1));
}

extern __shared__ float smem_f[];

// ======================= mma.sync tf32 GEMM =======================
#define KT 32
#define LDS_W 36
#define AB_W (128 * LDS_W)
#define STAGE_W (2 * AB_W)
#define GSMEM (2 * STAGE_W * 4)

__device__ __forceinline__ void load_tile(unsigned sBase,
    const float* __restrict__ A, int lda, const float* __restrict__ Bm, int ldb,
    int row0, int col0, int k0, int tid)
{
    #pragma unroll
    for (int i = 0; i < 4; i++) {
        int idx = i * 256 + tid;
        int r = idx >> 3, c = idx & 7;
        unsigned doff = (unsigned)((r * LDS_W + c * 4) * 4);
        cpa16(sBase + doff, A + (long)(row0 + r) * lda + k0 + c * 4);
        cpa16(sBase + AB_W * 4 + doff, Bm + (long)(col0 + r) * ldb + k0 + c * 4);
    }
}

__global__ __launch_bounds__(256, 2) void gemm_tc(
    const float* __restrict__ A, const float* __restrict__ Bm,
    const float* __restrict__ bias, float* __restrict__ C,
    int Kd, int lda, int ldb, int ldc,
    const int* __restrict__ dM, const int* __restrict__ exp_off,
    long bStride, int biasStride, int relu)
{
    int row0 = blockIdx.y * 128;
    if (dM && row0 >= *dM) return;
    int col0 = blockIdx.x * 128;
    if (exp_off) {
        int e = 0;
        while (row0 >= exp_off[e + 1]) e++;
        Bm += (long)e * bStride;
        bias += (long)e * biasStride;
    }
    int tid = threadIdx.x, lane = tid & 31, wid = tid >> 5;
    int warp_m = wid >> 2, warp_n = wid & 3;
    unsigned sb = smem_u32(smem_f);

    float acc[4][4][4];
    #pragma unroll
    for (int mt = 0; mt < 4; mt++)
        #pragma unroll
        for (int nt = 0; nt < 4; nt++)
            #pragma unroll
            for (int j = 0; j < 4; j++) acc[mt][nt][j] = 0.f;

    int nK = Kd / KT;
    load_tile(sb, A, lda, Bm, ldb, row0, col0, 0, tid);
    asm volatile("cp.async.commit_group;" ::: "memory");

    for (int kt = 0; kt < nK; kt++) {
        if (kt + 1 < nK) {
            load_tile(sb + ((kt + 1) & 1) * STAGE_W * 4,
                      A, lda, Bm, ldb, row0, col0, (kt + 1) * KT, tid);
            asm volatile("cp.async.commit_group;" ::: "memory");
            asm volatile("cp.async.wait_group 1;" ::: "memory");
        } else {
            asm volatile("cp.async.wait_group 0;" ::: "memory");
        }
        __syncthreads();

        const float* As = smem_f + (kt & 1) * STAGE_W;
        const float* Bs = As + AB_W;
        int rbase = warp_m * 64 + (lane >> 2);
        int nbase = warp_n * 32 + (lane >> 2);
        int kq = lane & 3;

        #pragma unroll
        for (int ks = 0; ks < 4; ks++) {
            unsigned af[4][4], bf[4][2];
            #pragma unroll
            for (int mt = 0; mt < 4; mt++) {
                const float* ap = As + (rbase + mt * 16) * LDS_W + ks * 8 + kq;
                af[mt][0] = to_tf32(ap[0]);
                af[mt][1] = to_tf32(ap[8 * LDS_W]);
                af[mt][2] = to_tf32(ap[4]);
                af[mt][3] = to_tf32(ap[8 * LDS_W + 4]);
            }
            #pragma unroll
            for (int nt = 0; nt < 4; nt++) {
                const float* bp = Bs + (nbase + nt * 8) * LDS_W + ks * 8 + kq;
                bf[nt][0] = to_tf32(bp[0]);
                bf[nt][1] = to_tf32(bp[4]);
            }
            #pragma unroll
            for (int mt = 0; mt < 4; mt++)
                #pragma unroll
                for (int nt = 0; nt < 4; nt++)
                    mma_tf32(acc[mt][nt], af[mt][0], af[mt][1], af[mt][2], af[mt][3],
                             bf[nt][0], bf[nt][1]);
        }
        __syncthreads();
    }

    #pragma unroll
    for (int mt = 0; mt < 4; mt++) {
        int r = row0 + warp_m * 64 + mt * 16 + (lane >> 2);
        #pragma unroll
        for (int nt = 0; nt < 4; nt++) {
            int cg = col0 + warp_n * 32 + nt * 8 + (lane & 3) * 2;
            float b0 = bias[cg], b1 = bias[cg + 1];
            float v0 = acc[mt][nt][0] + b0, v1 = acc[mt][nt][1] + b1;
            float v2 = acc[mt][nt][2] + b0, v3 = acc[mt][nt][3] + b1;
            if (relu) {
                v0 = fmaxf(v0, 0.f); v1 = fmaxf(v1, 0.f);
                v2 = fmaxf(v2, 0.f); v3 = fmaxf(v3, 0.f);
            }
            *(float2*)(C + (long)r * ldc + cg) = make_float2(v0, v1);
            *(float2*)(C + (long)(r + 8) * ldc + cg) = make_float2(v2, v3);
        }
    }
}

// ======================= tensor-core flash attention =======================
// CTA: 128 queries (4 warps x 32 rows), loop over 32-key tiles, double-buffered.
#define AQ_STR 68
#define AK_STR 68
#define AV_STR 72
#define AT_QS 0
#define AT_KS (128 * AQ_STR)                    // 8704
#define AT_VS (AT_KS + 2 * 32 * AK_STR)         // 13056
#define AT_TOT (AT_VS + 2 * 32 * AV_STR)        // 17664 floats
#define ASMEM (AT_TOT * 4)                      // 70656 bytes

__global__ __launch_bounds__(128) void k_attn_tc(const float* __restrict__ qkv,
                                                 float* __restrict__ ctx)
{
    int tid = threadIdx.x, lane = tid & 31, wid = tid >> 5;
    int b = blockIdx.y >> 4, h = blockIdx.y & 15;
    int q0 = blockIdx.x * 128;
    const float* base = qkv + (long)b * Sv * (3 * Dv) + h * HDv;
    unsigned sb = smem_u32(smem_f);
    int g = lane >> 2, j = lane & 3;
    int qb = wid * 32;

    // load Q tile + K/V tile 0
    #pragma unroll
    for (int i = 0; i < 16; i++) {
        int idx = i * 128 + tid;
        int r = idx >> 4, c = idx & 15;
        cpa16(sb + (AT_QS + r * AQ_STR + c * 4) * 4, base + (long)(q0 + r) * (3 * Dv) + c * 4);
    }
    #pragma unroll
    for (int i = 0; i < 4; i++) {
        int idx = i * 128 + tid;
        int r = idx >> 4, c = idx & 15;
        cpa16(sb + (AT_KS + r * AK_STR + c * 4) * 4, base + (long)r * (3 * Dv) + Dv + c * 4);
        cpa16(sb + (AT_VS + r * AV_STR + c * 4) * 4, base + (long)r * (3 * Dv) + 2 * Dv + c * 4);
    }
    asm volatile("cp.async.commit_group;" ::: "memory");
    asm volatile("cp.async.wait_group 0;" ::: "memory");
    __syncthreads();

    // pre-convert Q to tf32 (rna) in place — reused by all 64 key tiles
    #pragma unroll
    for (int i = 0; i < 16; i++) {
        int idx = i * 128 + tid;
        int r = idx >> 4, c = idx & 15;
        float4 v = *(float4*)(smem_f + AT_QS + r * AQ_STR + c * 4);
        v.x = __uint_as_float(to_tf32(v.x)); v.y = __uint_as_float(to_tf32(v.y));
        v.z = __uint_as_float(to_tf32(v.z)); v.w = __uint_as_float(to_tf32(v.w));
        *(float4*)(smem_f + AT_QS + r * AQ_STR + c * 4) = v;
    }
    __syncthreads();

    float Oa[2][8][4];
    float mrow[4], lrow[4];
    #pragma unroll
    for (int i = 0; i < 4; i++) { mrow[i] = -1e30f; lrow[i] = 0.f; }
    #pragma unroll
    for (int mt = 0; mt < 2; mt++)
        #pragma unroll
        for (int nt = 0; nt < 8; nt++)
            #pragma unroll
            for (int q = 0; q < 4; q++) Oa[mt][nt][q] = 0.f;

    for (int kt = 0; kt < Sv / 32; kt++) {
        int st = kt & 1;
        if (kt + 1 < Sv / 32) {
            int st2 = (kt + 1) & 1;
            #pragma unroll
            for (int i = 0; i < 4; i++) {
                int idx = i * 128 + tid;
                int r = idx >> 4, c = idx & 15;
                long gr = (long)((kt + 1) * 32 + r) * (3 * Dv);
                cpa16(sb + (AT_KS + st2 * 32 * AK_STR + r * AK_STR + c * 4) * 4, base + gr + Dv + c * 4);
                cpa16(sb + (AT_VS + st2 * 32 * AV_STR + r * AV_STR + c * 4) * 4, base + gr + 2 * Dv + c * 4);
            }
            asm volatile("cp.async.commit_group;" ::: "memory");
            asm volatile("cp.async.wait_group 1;" ::: "memory");
        } else {
            asm volatile("cp.async.wait_group 0;" ::: "memory");
        }
        __syncthreads();

        const float* Ks = smem_f + AT_KS + st * 32 * AK_STR;
        const float* Vs = smem_f + AT_VS + st * 32 * AV_STR;
        const float* Qs = smem_f + AT_QS;

        // ---- S = Q K^T ----
        float sacc[2][4][4];
        #pragma unroll
        for (int mt = 0; mt < 2; mt++)
            #pragma unroll
            for (int nt = 0; nt < 4; nt++)
                #pragma unroll
                for (int q = 0; q < 4; q++) sacc[mt][nt][q] = 0.f;

        #pragma unroll
        for (int ks = 0; ks < 8; ks++) {
            unsigned af[2][4], bf[4][2];
            #pragma unroll
            for (int mt = 0; mt < 2; mt++) {
                const float* ap = Qs + (qb + mt * 16 + g) * AQ_STR + ks * 8 + j;
                af[mt][0] = __float_as_uint(ap[0]);
                af[mt][1] = __float_as_uint(ap[8 * AQ_STR]);
                af[mt][2] = __float_as_uint(ap[4]);
                af[mt][3] = __float_as_uint(ap[8 * AQ_STR + 4]);
            }
            #pragma unroll
            for (int nt = 0; nt < 4; nt++) {
                const float* bp = Ks + (nt * 8 + g) * AK_STR + ks * 8 + j;
                bf[nt][0] = to_tf32(bp[0]);
                bf[nt][1] = to_tf32(bp[4]);
            }
            #pragma unroll
            for (int mt = 0; mt < 2; mt++)
                #pragma unroll
                for (int nt = 0; nt < 4; nt++)
                    mma_tf32(sacc[mt][nt], af[mt][0], af[mt][1], af[mt][2], af[mt][3],
                             bf[nt][0], bf[nt][1]);
        }

        // ---- online softmax (scale by 1/sqrt(64)=0.125) ----
        #pragma unroll
        for (int mt = 0; mt < 2; mt++)
            #pragma unroll
            for (int hh = 0; hh < 2; hh++) {
                int ri = mt * 2 + hh;
                float rmax = -1e30f;
                #pragma unroll
                for (int nt = 0; nt < 4; nt++) {
                    float v0 = sacc[mt][nt][hh * 2] * 0.125f;
                    float v1 = sacc[mt][nt][hh * 2 + 1] * 0.125f;
                    sacc[mt][nt][hh * 2] = v0; sacc[mt][nt][hh * 2 + 1] = v1;
                    rmax = fmaxf(rmax, fmaxf(v0, v1));
                }
                rmax = fmaxf(rmax, __shfl_xor_sync(0xffffffffu, rmax, 1));
                rmax = fmaxf(rmax, __shfl_xor_sync(0xffffffffu, rmax, 2));
                float mnew = fmaxf(mrow[ri], rmax);
                float corr = __expf(mrow[ri] - mnew);
                mrow[ri] = mnew;
                float ps = 0.f;
                #pragma unroll
                for (int nt = 0; nt < 4; nt++) {
                    float p0 = __expf(sacc[mt][nt][hh * 2] - mnew);
                    float p1 = __expf(sacc[mt][nt][hh * 2 + 1] - mnew);
                    sacc[mt][nt][hh * 2] = p0; sacc[mt][nt][hh * 2 + 1] = p1;
                    ps += p0 + p1;
                }
                ps += __shfl_xor_sync(0xffffffffu, ps, 1);
                ps += __shfl_xor_sync(0xffffffffu, ps, 2);
                lrow[ri] = lrow[ri] * corr + ps;
                #pragma unroll
                for (int nt = 0; nt < 8; nt++) {
                    Oa[mt][nt][hh * 2] *= corr;
                    Oa[mt][nt][hh * 2 + 1] *= corr;
                }
            }

        // ---- O += P V ----
        #pragma unroll
        for (int kk = 0; kk < 4; kk++) {
            // accumulator-layout -> A-fragment permutation via quad shuffles
            unsigned pa[2][4];
            int s0 = (lane & ~3) | (j >> 1);
            bool odd = (j & 1);
            #pragma unroll
            for (int mt = 0; mt < 2; mt++) {
                float c0 = sacc[mt][kk][0], c1 = sacc[mt][kk][1];
                float c2 = sacc[mt][kk][2], c3 = sacc[mt][kk][3];
                float t0 = __shfl_sync(0xffffffffu, c0, s0);
                float t1 = __shfl_sync(0xffffffffu, c1, s0);
                float t2 = __shfl_sync(0xffffffffu, c2, s0);
                float t3 = __shfl_sync(0xffffffffu, c3, s0);
                float u0 = __shfl_sync(0xffffffffu, c0, s0 + 2);
                float u1 = __shfl_sync(0xffffffffu, c1, s0 + 2);
                float u2 = __shfl_sync(0xffffffffu, c2, s0 + 2);
                float u3 = __shfl_sync(0xffffffffu, c3, s0 + 2);
                pa[mt][0] = to_tf32(odd ? t1 : t0);
                pa[mt][1] = to_tf32(odd ? t3 : t2);
                pa[mt][2] = to_tf32(odd ? u1 : u0);
                pa[mt][3] = to_tf32(odd ? u3 : u2);
            }
            #pragma unroll
            for (int nt = 0; nt < 8; nt++) {
                const float* vp = Vs + (kk * 8 + j) * AV_STR + nt * 8 + g;
                unsigned b0 = to_tf32(vp[0]);
                unsigned b1 = to_tf32(vp[4 * AV_STR]);
                #pragma unroll
                for (int mt = 0; mt < 2; mt++)
                    mma_tf32(Oa[mt][nt], pa[mt][0], pa[mt][1], pa[mt][2], pa[mt][3], b0, b1);
            }
        }
        __syncthreads();
    }

    // ---- write ctx ----
    #pragma unroll
    for (int mt = 0; mt < 2; mt++)
        #pragma unroll
        for (int hh = 0; hh < 2; hh++) {
            float inv = 1.f / lrow[mt * 2 + hh];
            int qrow = q0 + qb + mt * 16 + g + hh * 8;
            float* op = ctx + ((long)(b * Sv) + qrow) * Dv + h * HDv;
            #pragma unroll
            for (int nt = 0; nt < 8; nt++) {
                float2 v;
                v.x = Oa[mt][nt][hh * 2] * inv;
                v.y = Oa[mt][nt][hh * 2 + 1] * inv;
                *(float2*)(op + nt * 8 + 2 * j) = v;
            }
        }
}

// ======================= small kernels =======================
__global__ void k_init() {
    int i = blockIdx.x * blockDim.x + threadIdx.x;
    if (i < MAXP) g_gather[i] = -1;
    if (i < Ev) g_counts[i] = 0;
}

__global__ __launch_bounds__(256) void k_addln(const float* __restrict__ xa,
                                               const float* __restrict__ xb,
                                               const float* __restrict__ g,
                                               const float* __restrict__ bt,
                                               float* __restrict__ out)
{
    __shared__ float red[256];
    int n = blockIdx.x, tid = threadIdx.x;
    const float* pa = xa + (long)n * Dv;
    const float* pb = xb + (long)n * Dv;
    float v[4]; float s = 0.f;
    #pragma unroll
    for (int i = 0; i < 4; i++) { int d = tid + i * 256; v[i] = pa[d] + pb[d]; s += v[i]; }
    red[tid] = s; __syncthreads();
    for (int st = 128; st > 0; st >>= 1) { if (tid < st) red[tid] += red[tid + st]; __syncthreads(); }
    float mean = red[0] * (1.f / Dv);
    __syncthreads();
    float vs = 0.f;
    #pragma unroll
    for (int i = 0; i < 4; i++) { float t = v[i] - mean; vs += t * t; }
    red[tid] = vs; __syncthreads();
    for (int st = 128; st > 0; st >>= 1) { if (tid < st) red[tid] += red[tid + st]; __syncthreads(); }
    float rstd = rsqrtf(red[0] * (1.f / Dv) + LNEPS);
    #pragma unroll
    for (int i = 0; i < 4; i++) {
        int d = tid + i * 256;
        out[(long)n * Dv + d] = (v[i] - mean) * rstd * g[d] + bt[d];
    }
}

__global__ __launch_bounds__(256) void k_gate(const float* __restrict__ x1,
                                              const float* __restrict__ gw,
                                              const float* __restrict__ gb)
{
    int n = blockIdx.x;
    int w = threadIdx.x >> 5, lane = threadIdx.x & 31;
    const float* xp = x1 + (long)n * Dv;
    const float* wp = gw + (long)w * Dv;
    float s = 0.f;
    for (int d = lane; d < Dv; d += 32) s += xp[d] * wp[d];
    #pragma unroll
    for (int off = 16; off; off >>= 1) s += __shfl_down_sync(0xffffffff, s, off);
    __shared__ float lg[Ev];
    if (lane == 0) lg[w] = s + gb[w];
    __syncthreads();
    if (threadIdx.x == 0) {
        float l[Ev];
        #pragma unroll
        for (int e = 0; e < Ev; e++) { l[e] = lg[e]; g_logits[(long)n * Ev + e] = l[e]; }
        int i0 = 0;
        #pragma unroll
        for (int e = 1; e < Ev; e++) if (l[e] > l[i0]) i0 = e;
        int i1 = -1;
        #pragma unroll
        for (int e = 0; e < Ev; e++) { if (e == i0) continue; if (i1 < 0 || l[e] > l[i1]) i1 = e; }
        float e1 = expf(l[i1] - l[i0]);
        float denom = 1.f + e1;
        g_topE[n * 2 + 0] = i0; g_topE[n * 2 + 1] = i1;
        g_topw[n * 2 + 0] = 1.f / denom; g_topw[n * 2 + 1] = e1 / denom;
        atomicAdd(&g_counts[i0], 1);
        atomicAdd(&g_counts[i1], 1);
    }
}

__global__ void k_scan() {
    if (threadIdx.x == 0) {
        int t = 0;
        for (int e = 0; e < Ev; e++) {
            g_off[e] = t; g_cursor[e] = t;
            t += (g_counts[e] + 127) & ~127;
        }
        g_off[Ev] = t;
        g_Mpad[0] = t;
    }
}

__global__ void k_assign() {
    int i = blockIdx.x * blockDim.x + threadIdx.x;
    if (i >= NTOK * 2) return;
    int e = g_topE[i];
    int p = atomicAdd(&g_cursor[e], 1);
    g_gather[p] = i >> 1;
    g_pos[i] = p;
}

__global__ __launch_bounds__(256) void k_gather(const float* __restrict__ x1,
                                                float* __restrict__ xg)
{
    int p = blockIdx.x;
    int g = g_gather[p];
    float4* dst = (float4*)(xg + (long)p * Dv);
    if (g >= 0) {
        const float4* src = (const float4*)(x1 + (long)g * Dv);
        dst[threadIdx.x] = src[threadIdx.x];
    } else {
        dst[threadIdx.x] = make_float4(0.f, 0.f, 0.f, 0.f);
    }
}

__global__ __launch_bounds__(256) void k_scatter_ln2(const float* __restrict__ x1,
                                                     const float* __restrict__ g,
                                                     const float* __restrict__ bt,
                                                     float* __restrict__ out)
{
    __shared__ float red[256];
    int n = blockIdx.x, tid = threadIdx.x;
    int p0 = g_pos[n * 2 + 0], p1 = g_pos[n * 2 + 1];
    float w0 = g_topw[n * 2 + 0], w1 = g_topw[n * 2 + 1];
    const float* px = x1 + (long)n * Dv;
    const float* pe0 = g_eo + (long)p0 * Dv;
    const float* pe1 = g_eo + (long)p1 * Dv;
    float v[4]; float s = 0.f;
    #pragma unroll
    for (int i = 0; i < 4; i++) {
        int d = tid + i * 256;
        v[i] = px[d] + w0 * pe0[d] + w1 * pe1[d];
        s += v[i];
    }
    red[tid] = s; __syncthreads();
    for (int st = 128; st > 0; st >>= 1) { if (tid < st) red[tid] += red[tid + st]; __syncthreads(); }
    float mean = red[0] * (1.f / Dv);
    __syncthreads();
    float vs = 0.f;
    #pragma unroll
    for (int i = 0; i < 4; i++) { float t = v[i] - mean; vs += t * t; }
    red[tid] = vs; __syncthreads();
    for (int st = 128; st > 0; st >>= 1) { if (tid < st) red[tid] += red[tid + st]; __syncthreads(); }
    float rstd = rsqrtf(red[0] * (1.f / Dv) + LNEPS);
    #pragma unroll
    for (int i = 0; i < 4; i++) {
        int d = tid + i * 256;
        out[(long)n * Dv + d] = (v[i] - mean) * rstd * g[d] + bt[d];
    }
}

__global__ __launch_bounds__(256) void k_lb(float* __restrict__ out) {
    __shared__ float sm[256][Ev];
    int tid = threadIdx.x;
    float u[Ev];
    #pragma unroll
    for (int e = 0; e < Ev; e++) u[e] = 0.f;
    for (int n = tid; n < NTOK; n += 256) {
        float l[Ev], mx = -1e30f, s = 0.f;
        #pragma unroll
        for (int e = 0; e < Ev; e++) { l[e] = g_logits[(long)n * Ev + e]; mx = fmaxf(mx, l[e]); }
        #pragma unroll
        for (int e = 0; e < Ev; e++) { l[e] = expf(l[e] - mx); s += l[e]; }
        float inv = 1.f / s;
        #pragma unroll
        for (int e = 0; e < Ev; e++) u[e] += l[e] * inv;
    }
    #pragma unroll
    for (int e = 0; e < Ev; e++) sm[tid][e] = u[e];
    __syncthreads();
    for (int st = 128; st > 0; st >>= 1) {
        if (tid < st)
            #pragma unroll
            for (int e = 0; e < Ev; e++) sm[tid][e] += sm[tid + st][e];
        __syncthreads();
    }
    if (tid == 0) {
        float lb = 0.f;
        #pragma unroll
        for (int e = 0; e < Ev; e++) { float us = sm[0][e] * (1.f / NTOK); lb += us * us; }
        out[0] = (float)Ev * lb;
    }
}

// ======================= launch =======================
static void* symaddr(const void* s) { void* p = nullptr; cudaGetSymbolAddress(&p, s); return p; }

extern "C" void kernel_launch(void* const* d_in, const int* in_sizes, int n_in,
                              void* d_out, int out_size)
{
    (void)in_sizes; (void)n_in;
    const float* x    = (const float*)d_in[0];
    const float* inw  = (const float*)d_in[1];
    const float* inb  = (const float*)d_in[2];
    const float* outw = (const float*)d_in[3];
    const float* outb = (const float*)d_in[4];
    const float* ln1g = (const float*)d_in[5];
    const float* ln1b = (const float*)d_in[6];
    const float* gw   = (const float*)d_in[7];
    const float* gb   = (const float*)d_in[8];
    const float* w1   = (const float*)d_in[9];
    const float* b1   = (const float*)d_in[10];
    const float* w2   = (const float*)d_in[11];
    const float* b2   = (const float*)d_in[12];
    const float* ln2g = (const float*)d_in[13];
    const float* ln2b = (const float*)d_in[14];
    float* out = (float*)d_out;

    float* p_qkv  = (float*)symaddr(g_qkv);
    float* p_ctx  = (float*)symaddr(g_ctx);
    float* p_ao   = (float*)symaddr(g_attnout);
    float* p_x1   = (float*)symaddr(g_x1);
    float* p_xg   = (float*)symaddr(g_xg);
    float* p_h    = (float*)symaddr(g_h);
    float* p_eo   = (float*)symaddr(g_eo);
    int*   p_Mpad = (int*)symaddr(g_Mpad);
    int*   p_off  = (int*)symaddr(g_off);

    cudaFuncSetAttribute(gemm_tc, cudaFuncAttributeMaxDynamicSharedMemorySize, GSMEM);
    cudaFuncSetAttribute(k_attn_tc, cudaFuncAttributeMaxDynamicSharedMemorySize, ASMEM);

    // 1. routing state init
    k_init<<<(MAXP + 255) / 256, 256>>>();

    // 2. qkv = x @ in_proj_w^T + b
    gemm_tc<<<dim3(3 * Dv / 128, NTOK / 128), 256, GSMEM>>>(
        x, inw, inb, p_qkv, Dv, Dv, Dv, 3 * Dv, nullptr, nullptr, 0, 0, 0);

    // 3. attention -> ctx (tensor-core flash attention)
    k_attn_tc<<<dim3(Sv / 128, Bv * Hv), 128, ASMEM>>>(p_qkv, p_ctx);

    // 4. attn_out = ctx @ out_w^T + b
    gemm_tc<<<dim3(Dv / 128, NTOK / 128), 256, GSMEM>>>(
        p_ctx, outw, outb, p_ao, Dv, Dv, Dv, Dv, nullptr, nullptr, 0, 0, 0);

    // 5. x1 = LN1(x + attn_out)
    k_addln<<<NTOK, 256>>>(x, p_ao, ln1g, ln1b, p_x1);

    // 6. gate
    k_gate<<<NTOK, 256>>>(p_x1, gw, gb);

    // 7-8. routing
    k_scan<<<1, 32>>>();
    k_assign<<<(NTOK * 2 + 255) / 256, 256>>>();

    // 9. gather tokens
    k_gather<<<MAXP, 256>>>(p_x1, p_xg);

    // 10. h = relu(xg @ w1[e]^T + b1[e])
    gemm_tc<<<dim3(FFv / 128, MAXP / 128), 256, GSMEM>>>(
        p_xg, w1, b1, p_h, Dv, Dv, Dv, FFv,
        p_Mpad, p_off, (long)FFv * Dv, FFv, 1);

    // 11. eo = h @ w2[e]^T + b2[e]
    gemm_tc<<<dim3(Dv / 128, MAXP / 128), 256, GSMEM>>>(
        p_h, w2, b2, p_eo, FFv, FFv, FFv, Dv,
        p_Mpad, p_off, (long)Dv * FFv, Dv, 0);

    // 12. out = LN2(x1 + moe)
    k_scatter_ln2<<<NTOK, 256>>>(p_x1, ln2g, ln2b, out);

    // 13. lb_loss
    if (out_size > NTOK * Dv) {
        k_lb<<<1, 256>>>(out + (size_t)NTOK * Dv);
    }
}

// round 5
// speedup vs baseline: 6.3860x; 1.7075x over previous
#include <cuda_runtime.h>
#include <cuda_fp16.h>
#include <cstdint>

#define Bv 2
#define Sv 2048
#define Dv 1024
#define Hv 16
#define HDv 64
#define FFv 4096
#define Ev 8
#define NTOK (Bv*Sv)          // 4096
#define MAXP 9216             // 2*NTOK + 8*128 padding
#define LNEPS 1e-5f

// ---------------- scratch (device globals; no runtime alloc) ----------------
__device__ __half g_xh[(size_t)NTOK * Dv];
__device__ __half g_qkvh[(size_t)NTOK * 3 * Dv];
__device__ __half g_ctxh[(size_t)NTOK * Dv];
__device__ __half g_xgh[(size_t)MAXP * Dv];
__device__ __half g_hh[(size_t)MAXP * FFv];
__device__ __half g_inwh[(size_t)3 * Dv * Dv];
__device__ __half g_outwh[(size_t)Dv * Dv];
__device__ __half g_w1h[(size_t)Ev * FFv * Dv];
__device__ __half g_w2h[(size_t)Ev * Dv * FFv];
__device__ float g_attnout[(size_t)NTOK * Dv];
__device__ float g_x1[(size_t)NTOK * Dv];
__device__ float g_eo[(size_t)MAXP * Dv];
__device__ float g_logits[(size_t)NTOK * Ev];
__device__ float g_topw[(size_t)NTOK * 2];
__device__ int   g_topE[(size_t)NTOK * 2];
__device__ int   g_pos[(size_t)NTOK * 2];
__device__ int   g_counts[Ev];
__device__ int   g_cursor[Ev];
__device__ int   g_off[Ev + 1];
__device__ int   g_Mpad[1];
__device__ int   g_gather[MAXP];

// ======================= PTX helpers =======================
__device__ __forceinline__ unsigned smem_u32(const void* p) {
    unsigned a;
    asm("{ .reg .u64 t; cvta.to.shared.u64 t, %1; cvt.u32.u64 %0, t; }" : "=r"(a) : "l"(p));
    return a;
}
__device__ __forceinline__ void cpa16(unsigned dst, const void* src) {
    asm volatile("cp.async.cg.shared.global [%0], [%1], 16;" :: "r"(dst), "l"(src));
}
__device__ __forceinline__ void ldsm_x4(unsigned& r0, unsigned& r1, unsigned& r2, unsigned& r3, unsigned a) {
    asm volatile("ldmatrix.sync.aligned.m8n8.x4.shared.b16 {%0,%1,%2,%3}, [%4];"
        : "=r"(r0), "=r"(r1), "=r"(r2), "=r"(r3) : "r"(a));
}
__device__ __forceinline__ void ldsm_x2(unsigned& r0, unsigned& r1, unsigned a) {
    asm volatile("ldmatrix.sync.aligned.m8n8.x2.shared.b16 {%0,%1}, [%2];"
        : "=r"(r0), "=r"(r1) : "r"(a));
}
__device__ __forceinline__ void ldsm_x2t(unsigned& r0, unsigned& r1, unsigned a) {
    asm volatile("ldmatrix.sync.aligned.m8n8.x2.trans.shared.b16 {%0,%1}, [%2];"
        : "=r"(r0), "=r"(r1) : "r"(a));
}
__device__ __forceinline__ void mma_f16(float* c,
    unsigned a0, unsigned a1, unsigned a2, unsigned a3, unsigned b0, unsigned b1)
{
    asm volatile(
        "mma.sync.aligned.m16n8k16.row.col.f32.f16.f16.f32 "
        "{%0,%1,%2,%3}, {%4,%5,%6,%7}, {%8,%9}, {%0,%1,%2,%3};"
        : "+f"(c[0]), "+f"(c[1]), "+f"(c[2]), "+f"(c[3])
        : "r"(a0), "r"(a1), "r"(a2), "r"(a3), "r"(b0), "r"(b1));
}
__device__ __forceinline__ unsigned pack_h2(float a, float b) {
    __half2 h = __floats2half2_rn(a, b);
    return *reinterpret_cast<unsigned*>(&h);
}

extern __shared__ float smem_f[];

// ======================= fp32 -> fp16 converter =======================
__global__ __launch_bounds__(256) void k_f2h(const float4* __restrict__ in,
                                             __half2* __restrict__ out, int n4)
{
    int i = blockIdx.x * blockDim.x + threadIdx.x;
    if (i >= n4) return;
    float4 v = in[i];
    out[2 * i]     = __floats2half2_rn(v.x, v.y);
    out[2 * i + 1] = __floats2half2_rn(v.z, v.w);
}

// ======================= fp16 mma GEMM =======================
// C[M,N] = A[M,K]h * B[N,K]h^T + bias. 128x128 CTA, K-tile 32, 4 stages.
#define GSTR 40                         // smem row stride in halfs
#define GTILE_H (128 * GSTR)            // 5120 halfs per matrix
#define GSTAGE_H (2 * GTILE_H)          // 10240 halfs per stage
#define NST 4
#define GSMEMH (NST * GSTAGE_H * 2)     // 81920 bytes

__device__ __forceinline__ void load_tile_h(unsigned sBase,
    const __half* __restrict__ A, int lda, const __half* __restrict__ Bm, int ldb,
    int row0, int col0, int k0, int tid)
{
    #pragma unroll
    for (int i = 0; i < 2; i++) {
        int idx = i * 256 + tid;
        int r = idx >> 2, c = idx & 3;
        unsigned doff = (unsigned)((r * GSTR + c * 8) * 2);
        cpa16(sBase + doff, A + (long)(row0 + r) * lda + k0 + c * 8);
        cpa16(sBase + GTILE_H * 2 + doff, Bm + (long)(col0 + r) * ldb + k0 + c * 8);
    }
}

__global__ __launch_bounds__(256, 2) void gemm_h(
    const __half* __restrict__ A, const __half* __restrict__ Bm,
    const float* __restrict__ bias, float* __restrict__ C, __half* __restrict__ Ch,
    int Kd, int lda, int ldb, int ldc,
    const int* __restrict__ dM, const int* __restrict__ exp_off,
    long bStride, int biasStride, int relu)
{
    int row0 = blockIdx.y * 128;
    if (dM && row0 >= *dM) return;
    int col0 = blockIdx.x * 128;
    if (exp_off) {
        int e = 0;
        while (row0 >= exp_off[e + 1]) e++;
        Bm += (long)e * bStride;
        bias += (long)e * biasStride;
    }
    int tid = threadIdx.x, lane = tid & 31, wid = tid >> 5;
    int warp_m = wid >> 2, warp_n = wid & 3;
    unsigned sb = smem_u32(smem_f);

    float acc[4][4][4];
    #pragma unroll
    for (int mt = 0; mt < 4; mt++)
        #pragma unroll
        for (int nt = 0; nt < 4; nt++)
            #pragma unroll
            for (int j = 0; j < 4; j++) acc[mt][nt][j] = 0.f;

    int nK = Kd / 32;
    #pragma unroll
    for (int s = 0; s < 3; s++) {
        load_tile_h(sb + s * GSTAGE_H * 2, A, lda, Bm, ldb, row0, col0, s * 32, tid);
        asm volatile("cp.async.commit_group;" ::: "memory");
    }

    // per-lane ldmatrix row offsets
    int arow = (lane & 7) + ((lane >> 3) & 1) * 8;   // 0..15
    int akb = (lane >> 4) & 1;                        // k-block for x4
    int l2 = lane & 15;
    int brow = l2 & 7;
    int bkb = l2 >> 3;

    for (int kt = 0; kt < nK; kt++) {
        if (kt + 3 < nK)
            load_tile_h(sb + ((kt + 3) & 3) * GSTAGE_H * 2, A, lda, Bm, ldb, row0, col0, (kt + 3) * 32, tid);
        asm volatile("cp.async.commit_group;" ::: "memory");
        asm volatile("cp.async.wait_group 3;" ::: "memory");
        __syncthreads();

        unsigned sA = sb + (kt & 3) * GSTAGE_H * 2;
        unsigned sB = sA + GTILE_H * 2;

        #pragma unroll
        for (int ks = 0; ks < 2; ks++) {
            unsigned af[4][4], bf[4][2];
            #pragma unroll
            for (int mt = 0; mt < 4; mt++) {
                unsigned addr = sA + (unsigned)(((warp_m * 64 + mt * 16 + arow) * GSTR
                                 + ks * 16 + akb * 8) * 2);
                ldsm_x4(af[mt][0], af[mt][1], af[mt][2], af[mt][3], addr);
            }
            #pragma unroll
            for (int nt = 0; nt < 4; nt++) {
                unsigned addr = sB + (unsigned)(((warp_n * 32 + nt * 8 + brow) * GSTR
                                 + ks * 16 + bkb * 8) * 2);
                ldsm_x2(bf[nt][0], bf[nt][1], addr);
            }
            #pragma unroll
            for (int mt = 0; mt < 4; mt++)
                #pragma unroll
                for (int nt = 0; nt < 4; nt++)
                    mma_f16(acc[mt][nt], af[mt][0], af[mt][1], af[mt][2], af[mt][3],
                            bf[nt][0], bf[nt][1]);
        }
        __syncthreads();
    }

    int g = lane >> 2, j = lane & 3;
    #pragma unroll
    for (int mt = 0; mt < 4; mt++) {
        int r = row0 + warp_m * 64 + mt * 16 + g;
        #pragma unroll
        for (int nt = 0; nt < 4; nt++) {
            int cg = col0 + warp_n * 32 + nt * 8 + j * 2;
            float b0 = bias[cg], b1 = bias[cg + 1];
            float v0 = acc[mt][nt][0] + b0, v1 = acc[mt][nt][1] + b1;
            float v2 = acc[mt][nt][2] + b0, v3 = acc[mt][nt][3] + b1;
            if (relu) {
                v0 = fmaxf(v0, 0.f); v1 = fmaxf(v1, 0.f);
                v2 = fmaxf(v2, 0.f); v3 = fmaxf(v3, 0.f);
            }
            if (Ch) {
                *(__half2*)(Ch + (long)r * ldc + cg) = __floats2half2_rn(v0, v1);
                *(__half2*)(Ch + (long)(r + 8) * ldc + cg) = __floats2half2_rn(v2, v3);
            } else {
                *(float2*)(C + (long)r * ldc + cg) = make_float2(v0, v1);
                *(float2*)(C + (long)(r + 8) * ldc + cg) = make_float2(v2, v3);
            }
        }
    }
}

// ======================= fp16 tensor-core flash attention =======================
// CTA: 128 queries (4 warps x 32 rows), 32-key tiles, double-buffered.
#define ASTR 72
#define AQ_OFF 0
#define AK_OFF (128 * ASTR)                 // 9216
#define AV_OFF (AK_OFF + 2 * 32 * ASTR)     // 13824
#define ASMEMH ((AV_OFF + 2 * 32 * ASTR) * 2)   // 36864 bytes

__global__ __launch_bounds__(128) void k_attn_h(const __half* __restrict__ qkv,
                                                __half* __restrict__ ctx)
{
    __half* sm = (__half*)smem_f;
    int tid = threadIdx.x, lane = tid & 31, wid = tid >> 5;
    int b = blockIdx.y >> 4, h = blockIdx.y & 15;
    int q0 = blockIdx.x * 128;
    const __half* base = qkv + (long)b * Sv * (3 * Dv) + h * HDv;
    unsigned sb = smem_u32(sm);
    int g = lane >> 2, j = lane & 3;
    int qb = wid * 32;
    int arow = (lane & 7) + ((lane >> 3) & 1) * 8;
    int akb = (lane >> 4) & 1;
    int l2 = lane & 15;

    // load Q tile + K/V tile 0
    #pragma unroll
    for (int i = 0; i < 8; i++) {
        int idx = i * 128 + tid;
        int r = idx >> 3, c = idx & 7;
        cpa16(sb + (unsigned)((AQ_OFF + r * ASTR + c * 8) * 2),
              base + (long)(q0 + r) * (3 * Dv) + c * 8);
    }
    #pragma unroll
    for (int i = 0; i < 2; i++) {
        int idx = i * 128 + tid;
        int r = idx >> 3, c = idx & 7;
        cpa16(sb + (unsigned)((AK_OFF + r * ASTR + c * 8) * 2), base + (long)r * (3 * Dv) + Dv + c * 8);
        cpa16(sb + (unsigned)((AV_OFF + r * ASTR + c * 8) * 2), base + (long)r * (3 * Dv) + 2 * Dv + c * 8);
    }
    asm volatile("cp.async.commit_group;" ::: "memory");
    asm volatile("cp.async.wait_group 0;" ::: "memory");
    __syncthreads();

    // hoist Q fragments (constant over key loop)
    unsigned qf[2][4][4];
    #pragma unroll
    for (int mt = 0; mt < 2; mt++)
        #pragma unroll
        for (int ks = 0; ks < 4; ks++) {
            unsigned addr = sb + (unsigned)(((qb + mt * 16 + arow) * ASTR + ks * 16 + akb * 8) * 2);
            ldsm_x4(qf[mt][ks][0], qf[mt][ks][1], qf[mt][ks][2], qf[mt][ks][3], addr);
        }

    float Oa[2][8][4];
    float mrow[4], lrow[4];
    #pragma unroll
    for (int i = 0; i < 4; i++) { mrow[i] = -1e30f; lrow[i] = 0.f; }
    #pragma unroll
    for (int mt = 0; mt < 2; mt++)
        #pragma unroll
        for (int nt = 0; nt < 8; nt++)
            #pragma unroll
            for (int q = 0; q < 4; q++) Oa[mt][nt][q] = 0.f;

    for (int kt = 0; kt < Sv / 32; kt++) {
        int st = kt & 1;
        if (kt + 1 < Sv / 32) {
            int st2 = (kt + 1) & 1;
            #pragma unroll
            for (int i = 0; i < 2; i++) {
                int idx = i * 128 + tid;
                int r = idx >> 3, c = idx & 7;
                long gr = (long)((kt + 1) * 32 + r) * (3 * Dv);
                cpa16(sb + (unsigned)((AK_OFF + st2 * 32 * ASTR + r * ASTR + c * 8) * 2), base + gr + Dv + c * 8);
                cpa16(sb + (unsigned)((AV_OFF + st2 * 32 * ASTR + r * ASTR + c * 8) * 2), base + gr + 2 * Dv + c * 8);
            }
            asm volatile("cp.async.commit_group;" ::: "memory");
            asm volatile("cp.async.wait_group 1;" ::: "memory");
        } else {
            asm volatile("cp.async.wait_group 0;" ::: "memory");
        }
        __syncthreads();

        unsigned sK = sb + (unsigned)((AK_OFF + st * 32 * ASTR) * 2);
        unsigned sV = sb + (unsigned)((AV_OFF + st * 32 * ASTR) * 2);

        // ---- S = Q K^T ----
        float sacc[2][4][4];
        #pragma unroll
        for (int mt = 0; mt < 2; mt++)
            #pragma unroll
            for (int nt = 0; nt < 4; nt++)
                #pragma unroll
                for (int q = 0; q < 4; q++) sacc[mt][nt][q] = 0.f;

        #pragma unroll
        for (int ks = 0; ks < 4; ks++) {
            unsigned bf[4][2];
            #pragma unroll
            for (int nt = 0; nt < 4; nt++) {
                unsigned addr = sK + (unsigned)(((nt * 8 + (l2 & 7)) * ASTR + ks * 16 + (l2 >> 3) * 8) * 2);
                ldsm_x2(bf[nt][0], bf[nt][1], addr);
            }
            #pragma unroll
            for (int mt = 0; mt < 2; mt++)
                #pragma unroll
                for (int nt = 0; nt < 4; nt++)
                    mma_f16(sacc[mt][nt], qf[mt][ks][0], qf[mt][ks][1], qf[mt][ks][2], qf[mt][ks][3],
                            bf[nt][0], bf[nt][1]);
        }

        // ---- online softmax (scale 0.125) ----
        #pragma unroll
        for (int mt = 0; mt < 2; mt++)
            #pragma unroll
            for (int hh = 0; hh < 2; hh++) {
                int ri = mt * 2 + hh;
                float rmax = -1e30f;
                #pragma unroll
                for (int nt = 0; nt < 4; nt++) {
                    float v0 = sacc[mt][nt][hh * 2] * 0.125f;
                    float v1 = sacc[mt][nt][hh * 2 + 1] * 0.125f;
                    sacc[mt][nt][hh * 2] = v0; sacc[mt][nt][hh * 2 + 1] = v1;
                    rmax = fmaxf(rmax, fmaxf(v0, v1));
                }
                rmax = fmaxf(rmax, __shfl_xor_sync(0xffffffffu, rmax, 1));
                rmax = fmaxf(rmax, __shfl_xor_sync(0xffffffffu, rmax, 2));
                float mnew = fmaxf(mrow[ri], rmax);
                float corr = __expf(mrow[ri] - mnew);
                mrow[ri] = mnew;
                float ps = 0.f;
                #pragma unroll
                for (int nt = 0; nt < 4; nt++) {
                    float p0 = __expf(sacc[mt][nt][hh * 2] - mnew);
                    float p1 = __expf(sacc[mt][nt][hh * 2 + 1] - mnew);
                    sacc[mt][nt][hh * 2] = p0; sacc[mt][nt][hh * 2 + 1] = p1;
                    ps += p0 + p1;
                }
                ps += __shfl_xor_sync(0xffffffffu, ps, 1);
                ps += __shfl_xor_sync(0xffffffffu, ps, 2);
                lrow[ri] = lrow[ri] * corr + ps;
                #pragma unroll
                for (int nt = 0; nt < 8; nt++) {
                    Oa[mt][nt][hh * 2] *= corr;
                    Oa[mt][nt][hh * 2 + 1] *= corr;
                }
            }

        // ---- O += P V ---- (P packs directly into A fragments: no shuffles)
        #pragma unroll
        for (int ks = 0; ks < 2; ks++) {
            unsigned pa[2][4];
            #pragma unroll
            for (int mt = 0; mt < 2; mt++) {
                pa[mt][0] = pack_h2(sacc[mt][2 * ks][0],     sacc[mt][2 * ks][1]);
                pa[mt][1] = pack_h2(sacc[mt][2 * ks][2],     sacc[mt][2 * ks][3]);
                pa[mt][2] = pack_h2(sacc[mt][2 * ks + 1][0], sacc[mt][2 * ks + 1][1]);
                pa[mt][3] = pack_h2(sacc[mt][2 * ks + 1][2], sacc[mt][2 * ks + 1][3]);
            }
            #pragma unroll
            for (int nt = 0; nt < 8; nt++) {
                unsigned vb0, vb1;
                unsigned addr = sV + (unsigned)(((ks * 16 + (l2 & 7) + (l2 >> 3) * 8) * ASTR + nt * 8) * 2);
                ldsm_x2t(vb0, vb1, addr);
                #pragma unroll
                for (int mt = 0; mt < 2; mt++)
                    mma_f16(Oa[mt][nt], pa[mt][0], pa[mt][1], pa[mt][2], pa[mt][3], vb0, vb1);
            }
        }
        __syncthreads();
    }

    // ---- write ctx (fp16) ----
    #pragma unroll
    for (int mt = 0; mt < 2; mt++)
        #pragma unroll
        for (int hh = 0; hh < 2; hh++) {
            float inv = 1.f / lrow[mt * 2 + hh];
            int qrow = q0 + qb + mt * 16 + g + hh * 8;
            __half* op = ctx + ((long)(b * Sv) + qrow) * Dv + h * HDv;
            #pragma unroll
            for (int nt = 0; nt < 8; nt++) {
                *(__half2*)(op + nt * 8 + 2 * j) =
                    __floats2half2_rn(Oa[mt][nt][hh * 2] * inv, Oa[mt][nt][hh * 2 + 1] * inv);
            }
        }
}

// ======================= small kernels =======================
__global__ void k_init() {
    int i = blockIdx.x * blockDim.x + threadIdx.x;
    if (i < MAXP) g_gather[i] = -1;
    if (i < Ev) g_counts[i] = 0;
}

__global__ __launch_bounds__(256) void k_addln(const float* __restrict__ xa,
                                               const float* __restrict__ xb,
                                               const float* __restrict__ g,
                                               const float* __restrict__ bt,
                                               float* __restrict__ out)
{
    __shared__ float red[256];
    int n = blockIdx.x, tid = threadIdx.x;
    const float* pa = xa + (long)n * Dv;
    const float* pb = xb + (long)n * Dv;
    float v[4]; float s = 0.f;
    #pragma unroll
    for (int i = 0; i < 4; i++) { int d = tid + i * 256; v[i] = pa[d] + pb[d]; s += v[i]; }
    red[tid] = s; __syncthreads();
    for (int st = 128; st > 0; st >>= 1) { if (tid < st) red[tid] += red[tid + st]; __syncthreads(); }
    float mean = red[0] * (1.f / Dv);
    __syncthreads();
    float vs = 0.f;
    #pragma unroll
    for (int i = 0; i < 4; i++) { float t = v[i] - mean; vs += t * t; }
    red[tid] = vs; __syncthreads();
    for (int st = 128; st > 0; st >>= 1) { if (tid < st) red[tid] += red[tid + st]; __syncthreads(); }
    float rstd = rsqrtf(red[0] * (1.f / Dv) + LNEPS);
    #pragma unroll
    for (int i = 0; i < 4; i++) {
        int d = tid + i * 256;
        out[(long)n * Dv + d] = (v[i] - mean) * rstd * g[d] + bt[d];
    }
}

__global__ __launch_bounds__(256) void k_gate(const float* __restrict__ x1,
                                              const float* __restrict__ gw,
                                              const float* __restrict__ gb)
{
    int n = blockIdx.x;
    int w = threadIdx.x >> 5, lane = threadIdx.x & 31;
    const float* xp = x1 + (long)n * Dv;
    const float* wp = gw + (long)w * Dv;
    float s = 0.f;
    for (int d = lane; d < Dv; d += 32) s += xp[d] * wp[d];
    #pragma unroll
    for (int off = 16; off; off >>= 1) s += __shfl_down_sync(0xffffffff, s, off);
    __shared__ float lg[Ev];
    if (lane == 0) lg[w] = s + gb[w];
    __syncthreads();
    if (threadIdx.x == 0) {
        float l[Ev];
        #pragma unroll
        for (int e = 0; e < Ev; e++) { l[e] = lg[e]; g_logits[(long)n * Ev + e] = l[e]; }
        int i0 = 0;
        #pragma unroll
        for (int e = 1; e < Ev; e++) if (l[e] > l[i0]) i0 = e;
        int i1 = -1;
        #pragma unroll
        for (int e = 0; e < Ev; e++) { if (e == i0) continue; if (i1 < 0 || l[e] > l[i1]) i1 = e; }
        float e1 = expf(l[i1] - l[i0]);
        float denom = 1.f + e1;
        g_topE[n * 2 + 0] = i0; g_topE[n * 2 + 1] = i1;
        g_topw[n * 2 + 0] = 1.f / denom; g_topw[n * 2 + 1] = e1 / denom;
        atomicAdd(&g_counts[i0], 1);
        atomicAdd(&g_counts[i1], 1);
    }
}

__global__ void k_scan() {
    if (threadIdx.x == 0) {
        int t = 0;
        for (int e = 0; e < Ev; e++) {
            g_off[e] = t; g_cursor[e] = t;
            t += (g_counts[e] + 127) & ~127;
        }
        g_off[Ev] = t;
        g_Mpad[0] = t;
    }
}

__global__ void k_assign() {
    int i = blockIdx.x * blockDim.x + threadIdx.x;
    if (i >= NTOK * 2) return;
    int e = g_topE[i];
    int p = atomicAdd(&g_cursor[e], 1);
    g_gather[p] = i >> 1;
    g_pos[i] = p;
}

__global__ __launch_bounds__(256) void k_gather(const float* __restrict__ x1,
                                                __half* __restrict__ xg)
{
    int p = blockIdx.x;
    int g = g_gather[p];
    __half2* dst = (__half2*)(xg + (long)p * Dv);
    int t = threadIdx.x;
    if (g >= 0) {
        float4 v = ((const float4*)(x1 + (long)g * Dv))[t];
        dst[2 * t]     = __floats2half2_rn(v.x, v.y);
        dst[2 * t + 1] = __floats2half2_rn(v.z, v.w);
    } else {
        dst[2 * t] = __floats2half2_rn(0.f, 0.f);
        dst[2 * t + 1] = __floats2half2_rn(0.f, 0.f);
    }
}

__global__ __launch_bounds__(256) void k_scatter_ln2(const float* __restrict__ x1,
                                                     const float* __restrict__ g,
                                                     const float* __restrict__ bt,
                                                     float* __restrict__ out)
{
    __shared__ float red[256];
    int n = blockIdx.x, tid = threadIdx.x;
    int p0 = g_pos[n * 2 + 0], p1 = g_pos[n * 2 + 1];
    float w0 = g_topw[n * 2 + 0], w1 = g_topw[n * 2 + 1];
    const float* px = x1 + (long)n * Dv;
    const float* pe0 = g_eo + (long)p0 * Dv;
    const float* pe1 = g_eo + (long)p1 * Dv;
    float v[4]; float s = 0.f;
    #pragma unroll
    for (int i = 0; i < 4; i++) {
        int d = tid + i * 256;
        v[i] = px[d] + w0 * pe0[d] + w1 * pe1[d];
        s += v[i];
    }
    red[tid] = s; __syncthreads();
    for (int st = 128; st > 0; st >>= 1) { if (tid < st) red[tid] += red[tid + st]; __syncthreads(); }
    float mean = red[0] * (1.f / Dv);
    __syncthreads();
    float vs = 0.f;
    #pragma unroll
    for (int i = 0; i < 4; i++) { float t = v[i] - mean; vs += t * t; }
    red[tid] = vs; __syncthreads();
    for (int st = 128; st > 0; st >>= 1) { if (tid < st) red[tid] += red[tid + st]; __syncthreads(); }
    float rstd = rsqrtf(red[0] * (1.f / Dv) + LNEPS);
    #pragma unroll
    for (int i = 0; i < 4; i++) {
        int d = tid + i * 256;
        out[(long)n * Dv + d] = (v[i] - mean) * rstd * g[d] + bt[d];
    }
}

__global__ __launch_bounds__(256) void k_lb(float* __restrict__ out) {
    __shared__ float sm[256][Ev];
    int tid = threadIdx.x;
    float u[Ev];
    #pragma unroll
    for (int e = 0; e < Ev; e++) u[e] = 0.f;
    for (int n = tid; n < NTOK; n += 256) {
        float l[Ev], mx = -1e30f, s = 0.f;
        #pragma unroll
        for (int e = 0; e < Ev; e++) { l[e] = g_logits[(long)n * Ev + e]; mx = fmaxf(mx, l[e]); }
        #pragma unroll
        for (int e = 0; e < Ev; e++) { l[e] = expf(l[e] - mx); s += l[e]; }
        float inv = 1.f / s;
        #pragma unroll
        for (int e = 0; e < Ev; e++) u[e] += l[e] * inv;
    }
    #pragma unroll
    for (int e = 0; e < Ev; e++) sm[tid][e] = u[e];
    __syncthreads();
    for (int st = 128; st > 0; st >>= 1) {
        if (tid < st)
            #pragma unroll
            for (int e = 0; e < Ev; e++) sm[tid][e] += sm[tid + st][e];
        __syncthreads();
    }
    if (tid == 0) {
        float lb = 0.f;
        #pragma unroll
        for (int e = 0; e < Ev; e++) { float us = sm[0][e] * (1.f / NTOK); lb += us * us; }
        out[0] = (float)Ev * lb;
    }
}

// ======================= launch =======================
static void* symaddr(const void* s) { void* p = nullptr; cudaGetSymbolAddress(&p, s); return p; }

extern "C" void kernel_launch(void* const* d_in, const int* in_sizes, int n_in,
                              void* d_out, int out_size)
{
    (void)in_sizes; (void)n_in;
    const float* x    = (const float*)d_in[0];
    const float* inw  = (const float*)d_in[1];
    const float* inb  = (const float*)d_in[2];
    const float* outw = (const float*)d_in[3];
    const float* outb = (const float*)d_in[4];
    const float* ln1g = (const float*)d_in[5];
    const float* ln1b = (const float*)d_in[6];
    const float* gw   = (const float*)d_in[7];
    const float* gb   = (const float*)d_in[8];
    const float* w1   = (const float*)d_in[9];
    const float* b1   = (const float*)d_in[10];
    const float* w2   = (const float*)d_in[11];
    const float* b2   = (const float*)d_in[12];
    const float* ln2g = (const float*)d_in[13];
    const float* ln2b = (const float*)d_in[14];
    float* out = (float*)d_out;

    __half* p_xh    = (__half*)symaddr(g_xh);
    __half* p_qkvh  = (__half*)symaddr(g_qkvh);
    __half* p_ctxh  = (__half*)symaddr(g_ctxh);
    __half* p_xgh   = (__half*)symaddr(g_xgh);
    __half* p_hh    = (__half*)symaddr(g_hh);
    __half* p_inwh  = (__half*)symaddr(g_inwh);
    __half* p_outwh = (__half*)symaddr(g_outwh);
    __half* p_w1h   = (__half*)symaddr(g_w1h);
    __half* p_w2h   = (__half*)symaddr(g_w2h);
    float* p_ao   = (float*)symaddr(g_attnout);
    float* p_x1   = (float*)symaddr(g_x1);
    float* p_eo   = (float*)symaddr(g_eo);
    int*   p_Mpad = (int*)symaddr(g_Mpad);
    int*   p_off  = (int*)symaddr(g_off);

    cudaFuncSetAttribute(gemm_h, cudaFuncAttributeMaxDynamicSharedMemorySize, GSMEMH);
    cudaFuncSetAttribute(k_attn_h, cudaFuncAttributeMaxDynamicSharedMemorySize, ASMEMH);

    // 0. fp32 -> fp16 conversions (weights + x)
    {
        struct { const float* src; __half* dst; long n; } cv[5] = {
            { x,    p_xh,    (long)NTOK * Dv },
            { inw,  p_inwh,  (long)3 * Dv * Dv },
            { outw, p_outwh, (long)Dv * Dv },
            { w1,   p_w1h,   (long)Ev * FFv * Dv },
            { w2,   p_w2h,   (long)Ev * Dv * FFv },
        };
        for (int i = 0; i < 5; i++) {
            int n4 = (int)(cv[i].n / 4);
            k_f2h<<<(n4 + 255) / 256, 256>>>((const float4*)cv[i].src, (__half2*)cv[i].dst, n4);
        }
    }

    // 1. routing state init
    k_init<<<(MAXP + 255) / 256, 256>>>();

    // 2. qkv = x @ in_proj_w^T + b  -> fp16
    gemm_h<<<dim3(3 * Dv / 128, NTOK / 128), 256, GSMEMH>>>(
        p_xh, p_inwh, inb, nullptr, p_qkvh, Dv, Dv, Dv, 3 * Dv,
        nullptr, nullptr, 0, 0, 0);

    // 3. attention -> ctx (fp16)
    k_attn_h<<<dim3(Sv / 128, Bv * Hv), 128, ASMEMH>>>(p_qkvh, p_ctxh);

    // 4. attn_out = ctx @ out_w^T + b  -> fp32
    gemm_h<<<dim3(Dv / 128, NTOK / 128), 256, GSMEMH>>>(
        p_ctxh, p_outwh, outb, p_ao, nullptr, Dv, Dv, Dv, Dv,
        nullptr, nullptr, 0, 0, 0);

    // 5. x1 = LN1(x + attn_out)
    k_addln<<<NTOK, 256>>>(x, p_ao, ln1g, ln1b, p_x1);

    // 6. gate
    k_gate<<<NTOK, 256>>>(p_x1, gw, gb);

    // 7-8. routing
    k_scan<<<1, 32>>>();
    k_assign<<<(NTOK * 2 + 255) / 256, 256>>>();

    // 9. gather tokens -> fp16
    k_gather<<<MAXP, 256>>>(p_x1, p_xgh);

    // 10. h = relu(xg @ w1[e]^T + b1[e]) -> fp16
    gemm_h<<<dim3(FFv / 128, MAXP / 128), 256, GSMEMH>>>(
        p_xgh, p_w1h, b1, nullptr, p_hh, Dv, Dv, Dv, FFv,
        p_Mpad, p_off, (long)FFv * Dv, FFv, 1);

    // 11. eo = h @ w2[e]^T + b2[e] -> fp32
    gemm_h<<<dim3(Dv / 128, MAXP / 128), 256, GSMEMH>>>(
        p_hh, p_w2h, b2, p_eo, nullptr, FFv, FFv, FFv, Dv,
        p_Mpad, p_off, (long)Dv * FFv, Dv, 0);

    // 12. out = LN2(x1 + moe)
    k_scatter_ln2<<<NTOK, 256>>>(p_x1, ln2g, ln2b, out);

    // 13. lb_loss
    if (out_size > NTOK * Dv) {
        k_lb<<<1, 256>>>(out + (size_t)NTOK * Dv);
    }
}

// round 6
// speedup vs baseline: 7.3311x; 1.1480x over previous
#include <cuda_runtime.h>
#include <cuda_fp16.h>
#include <cstdint>

#define Bv 2
#define Sv 2048
#define Dv 1024
#define Hv 16
#define HDv 64
#define FFv 4096
#define Ev 8
#define NTOK (Bv*Sv)          // 4096
#define MAXP 9216             // 2*NTOK + 8*128 padding
#define LNEPS 1e-5f

// ---------------- scratch (device globals; no runtime alloc) ----------------
__device__ __half g_xh[(size_t)NTOK * Dv];
__device__ __half g_qkvh[(size_t)NTOK * 3 * Dv];
__device__ __half g_ctxh[(size_t)NTOK * Dv];
__device__ __half g_xgh[(size_t)MAXP * Dv];
__device__ __half g_hh[(size_t)MAXP * FFv];
__device__ __half g_inwh[(size_t)3 * Dv * Dv];
__device__ __half g_outwh[(size_t)Dv * Dv];
__device__ __half g_w1h[(size_t)Ev * FFv * Dv];
__device__ __half g_w2h[(size_t)Ev * Dv * FFv];
__device__ float g_attnout[(size_t)NTOK * Dv];
__device__ float g_x1[(size_t)NTOK * Dv];
__device__ float g_eo[(size_t)MAXP * Dv];
__device__ float g_logits[(size_t)NTOK * Ev];
__device__ float g_topw[(size_t)NTOK * 2];
__device__ int   g_topE[(size_t)NTOK * 2];
__device__ int   g_pos[(size_t)NTOK * 2];
__device__ int   g_counts[Ev];
__device__ int   g_cursor[Ev];
__device__ int   g_off[Ev + 1];
__device__ int   g_Mpad[1];
__device__ int   g_gather[MAXP];

// ======================= PTX helpers =======================
__device__ __forceinline__ unsigned smem_u32(const void* p) {
    unsigned a;
    asm("{ .reg .u64 t; cvta.to.shared.u64 t, %1; cvt.u32.u64 %0, t; }" : "=r"(a) : "l"(p));
    return a;
}
__device__ __forceinline__ void cpa16(unsigned dst, const void* src) {
    asm volatile("cp.async.cg.shared.global [%0], [%1], 16;" :: "r"(dst), "l"(src));
}
__device__ __forceinline__ void ldsm_x4(unsigned& r0, unsigned& r1, unsigned& r2, unsigned& r3, unsigned a) {
    asm volatile("ldmatrix.sync.aligned.m8n8.x4.shared.b16 {%0,%1,%2,%3}, [%4];"
        : "=r"(r0), "=r"(r1), "=r"(r2), "=r"(r3) : "r"(a));
}
__device__ __forceinline__ void ldsm_x2t(unsigned& r0, unsigned& r1, unsigned a) {
    asm volatile("ldmatrix.sync.aligned.m8n8.x2.trans.shared.b16 {%0,%1}, [%2];"
        : "=r"(r0), "=r"(r1) : "r"(a));
}
__device__ __forceinline__ void mma_f16(float* c,
    unsigned a0, unsigned a1, unsigned a2, unsigned a3, unsigned b0, unsigned b1)
{
    asm volatile(
        "mma.sync.aligned.m16n8k16.row.col.f32.f16.f16.f32 "
        "{%0,%1,%2,%3}, {%4,%5,%6,%7}, {%8,%9}, {%0,%1,%2,%3};"
        : "+f"(c[0]), "+f"(c[1]), "+f"(c[2]), "+f"(c[3])
        : "r"(a0), "r"(a1), "r"(a2), "r"(a3), "r"(b0), "r"(b1));
}
__device__ __forceinline__ unsigned pack_h2(float a, float b) {
    __half2 h = __floats2half2_rn(a, b);
    return *reinterpret_cast<unsigned*>(&h);
}

extern __shared__ float smem_f[];

// ======================= fp32 -> fp16 converter =======================
__global__ __launch_bounds__(256) void k_f2h(const float4* __restrict__ in,
                                             __half2* __restrict__ out, int n4)
{
    int i = blockIdx.x * blockDim.x + threadIdx.x;
    if (i >= n4) return;
    float4 v = in[i];
    out[2 * i]     = __floats2half2_rn(v.x, v.y);
    out[2 * i + 1] = __floats2half2_rn(v.z, v.w);
}

// ======================= fp16 mma GEMM =======================
// C[M,N] = A[M,K]h * B[N,K]h^T + bias. 128x128 CTA, K-tile 32, 4 stages,
// 128 threads: 4 warps in 2x2, each computing 64x64.
#define GSTR 40                         // smem row stride in halfs
#define GTILE_H (128 * GSTR)            // 5120 halfs per matrix
#define GSTAGE_H (2 * GTILE_H)          // 10240 halfs per stage
#define NST 4
#define GSMEMH (NST * GSTAGE_H * 2)     // 81920 bytes

__device__ __forceinline__ void load_tile_h(unsigned sBase,
    const __half* __restrict__ A, int lda, const __half* __restrict__ Bm, int ldb,
    int row0, int col0, int k0, int tid)
{
    #pragma unroll
    for (int i = 0; i < 4; i++) {
        int idx = i * 128 + tid;
        int r = idx >> 2, c = idx & 3;
        unsigned doff = (unsigned)((r * GSTR + c * 8) * 2);
        cpa16(sBase + doff, A + (long)(row0 + r) * lda + k0 + c * 8);
        cpa16(sBase + GTILE_H * 2 + doff, Bm + (long)(col0 + r) * ldb + k0 + c * 8);
    }
}

__global__ __launch_bounds__(128, 2) void gemm_h(
    const __half* __restrict__ A, const __half* __restrict__ Bm,
    const float* __restrict__ bias, float* __restrict__ C, __half* __restrict__ Ch,
    int Kd, int lda, int ldb, int ldc,
    const int* __restrict__ dM, const int* __restrict__ exp_off,
    long bStride, int biasStride, int relu)
{
    int row0 = blockIdx.y * 128;
    if (dM && row0 >= *dM) return;
    int col0 = blockIdx.x * 128;
    if (exp_off) {
        int e = 0;
        while (row0 >= exp_off[e + 1]) e++;
        Bm += (long)e * bStride;
        bias += (long)e * biasStride;
    }
    int tid = threadIdx.x, lane = tid & 31, wid = tid >> 5;
    int warp_m = wid >> 1, warp_n = wid & 1;
    unsigned sb = smem_u32(smem_f);

    float acc[4][8][4];
    #pragma unroll
    for (int mt = 0; mt < 4; mt++)
        #pragma unroll
        for (int nt = 0; nt < 8; nt++)
            #pragma unroll
            for (int j = 0; j < 4; j++) acc[mt][nt][j] = 0.f;

    int nK = Kd / 32;
    #pragma unroll
    for (int s = 0; s < 3; s++) {
        load_tile_h(sb + s * GSTAGE_H * 2, A, lda, Bm, ldb, row0, col0, s * 32, tid);
        asm volatile("cp.async.commit_group;" ::: "memory");
    }

    // ldmatrix per-lane addressing
    int arow = lane & 15, akb = lane >> 4;                 // A x4: rows m0-15, k halves
    int bnrow = (lane & 7) + ((lane >> 4) & 1) * 8;        // B x4: n row within 16
    int bkb = (lane >> 3) & 1;                             // B x4: k half

    for (int kt = 0; kt < nK; kt++) {
        if (kt + 3 < nK)
            load_tile_h(sb + ((kt + 3) & 3) * GSTAGE_H * 2, A, lda, Bm, ldb, row0, col0, (kt + 3) * 32, tid);
        asm volatile("cp.async.commit_group;" ::: "memory");
        asm volatile("cp.async.wait_group 3;" ::: "memory");
        __syncthreads();

        unsigned sA = sb + (kt & 3) * GSTAGE_H * 2;
        unsigned sB = sA + GTILE_H * 2;

        #pragma unroll
        for (int ks = 0; ks < 2; ks++) {
            unsigned af[4][4], bf[4][4];
            #pragma unroll
            for (int mt = 0; mt < 4; mt++) {
                unsigned addr = sA + (unsigned)(((warp_m * 64 + mt * 16 + arow) * GSTR
                                 + ks * 16 + akb * 8) * 2);
                ldsm_x4(af[mt][0], af[mt][1], af[mt][2], af[mt][3], addr);
            }
            #pragma unroll
            for (int nt2 = 0; nt2 < 4; nt2++) {
                unsigned addr = sB + (unsigned)(((warp_n * 64 + nt2 * 16 + bnrow) * GSTR
                                 + ks * 16 + bkb * 8) * 2);
                ldsm_x4(bf[nt2][0], bf[nt2][1], bf[nt2][2], bf[nt2][3], addr);
            }
            #pragma unroll
            for (int mt = 0; mt < 4; mt++)
                #pragma unroll
                for (int nt2 = 0; nt2 < 4; nt2++) {
                    mma_f16(acc[mt][2 * nt2],     af[mt][0], af[mt][1], af[mt][2], af[mt][3],
                            bf[nt2][0], bf[nt2][1]);
                    mma_f16(acc[mt][2 * nt2 + 1], af[mt][0], af[mt][1], af[mt][2], af[mt][3],
                            bf[nt2][2], bf[nt2][3]);
                }
        }
        __syncthreads();
    }

    int g = lane >> 2, j = lane & 3;
    #pragma unroll
    for (int mt = 0; mt < 4; mt++) {
        int r = row0 + warp_m * 64 + mt * 16 + g;
        #pragma unroll
        for (int nt = 0; nt < 8; nt++) {
            int cg = col0 + warp_n * 64 + nt * 8 + j * 2;
            float b0 = bias[cg], b1 = bias[cg + 1];
            float v0 = acc[mt][nt][0] + b0, v1 = acc[mt][nt][1] + b1;
            float v2 = acc[mt][nt][2] + b0, v3 = acc[mt][nt][3] + b1;
            if (relu) {
                v0 = fmaxf(v0, 0.f); v1 = fmaxf(v1, 0.f);
                v2 = fmaxf(v2, 0.f); v3 = fmaxf(v3, 0.f);
            }
            if (Ch) {
                *(__half2*)(Ch + (long)r * ldc + cg) = __floats2half2_rn(v0, v1);
                *(__half2*)(Ch + (long)(r + 8) * ldc + cg) = __floats2half2_rn(v2, v3);
            } else {
                *(float2*)(C + (long)r * ldc + cg) = make_float2(v0, v1);
                *(float2*)(C + (long)(r + 8) * ldc + cg) = make_float2(v2, v3);
            }
        }
    }
}

// ======================= fp16 tensor-core flash attention =======================
// CTA: 128 queries (4 warps x 32 rows), 64-key tiles, double-buffered.
#define ASTR 72
#define AQ_OFF 0
#define AK_OFF (128 * ASTR)                 // 9216
#define AV_OFF (AK_OFF + 2 * 64 * ASTR)     // 18432
#define ASMEMH ((AV_OFF + 2 * 64 * ASTR) * 2)   // 55296 bytes

__global__ __launch_bounds__(128) void k_attn_h(const __half* __restrict__ qkv,
                                                __half* __restrict__ ctx)
{
    __half* sm = (__half*)smem_f;
    int tid = threadIdx.x, lane = tid & 31, wid = tid >> 5;
    int b = blockIdx.y >> 4, h = blockIdx.y & 15;
    int q0 = blockIdx.x * 128;
    const __half* base = qkv + (long)b * Sv * (3 * Dv) + h * HDv;
    unsigned sb = smem_u32(sm);
    int g = lane >> 2, j = lane & 3;
    int qb = wid * 32;
    int arow = lane & 15;
    int akb = lane >> 4;
    int l2 = lane & 15;

    // load Q tile + K/V tile 0
    #pragma unroll
    for (int i = 0; i < 8; i++) {
        int idx = i * 128 + tid;
        int r = idx >> 3, c = idx & 7;
        cpa16(sb + (unsigned)((AQ_OFF + r * ASTR + c * 8) * 2),
              base + (long)(q0 + r) * (3 * Dv) + c * 8);
    }
    #pragma unroll
    for (int i = 0; i < 4; i++) {
        int idx = i * 128 + tid;
        int r = idx >> 3, c = idx & 7;
        cpa16(sb + (unsigned)((AK_OFF + r * ASTR + c * 8) * 2), base + (long)r * (3 * Dv) + Dv + c * 8);
        cpa16(sb + (unsigned)((AV_OFF + r * ASTR + c * 8) * 2), base + (long)r * (3 * Dv) + 2 * Dv + c * 8);
    }
    asm volatile("cp.async.commit_group;" ::: "memory");
    asm volatile("cp.async.wait_group 0;" ::: "memory");
    __syncthreads();

    // hoist Q fragments (constant over key loop)
    unsigned qf[2][4][4];
    #pragma unroll
    for (int mt = 0; mt < 2; mt++)
        #pragma unroll
        for (int ks = 0; ks < 4; ks++) {
            unsigned addr = sb + (unsigned)(((qb + mt * 16 + arow) * ASTR + ks * 16 + akb * 8) * 2);
            ldsm_x4(qf[mt][ks][0], qf[mt][ks][1], qf[mt][ks][2], qf[mt][ks][3], addr);
        }

    float Oa[2][8][4];
    float mrow[4], lrow[4];
    #pragma unroll
    for (int i = 0; i < 4; i++) { mrow[i] = -1e30f; lrow[i] = 0.f; }
    #pragma unroll
    for (int mt = 0; mt < 2; mt++)
        #pragma unroll
        for (int nt = 0; nt < 8; nt++)
            #pragma unroll
            for (int q = 0; q < 4; q++) Oa[mt][nt][q] = 0.f;

    for (int kt = 0; kt < Sv / 64; kt++) {
        int st = kt & 1;
        if (kt + 1 < Sv / 64) {
            int st2 = (kt + 1) & 1;
            #pragma unroll
            for (int i = 0; i < 4; i++) {
                int idx = i * 128 + tid;
                int r = idx >> 3, c = idx & 7;
                long gr = (long)((kt + 1) * 64 + r) * (3 * Dv);
                cpa16(sb + (unsigned)((AK_OFF + st2 * 64 * ASTR + r * ASTR + c * 8) * 2), base + gr + Dv + c * 8);
                cpa16(sb + (unsigned)((AV_OFF + st2 * 64 * ASTR + r * ASTR + c * 8) * 2), base + gr + 2 * Dv + c * 8);
            }
            asm volatile("cp.async.commit_group;" ::: "memory");
            asm volatile("cp.async.wait_group 1;" ::: "memory");
        } else {
            asm volatile("cp.async.wait_group 0;" ::: "memory");
        }
        __syncthreads();

        unsigned sK = sb + (unsigned)((AK_OFF + st * 64 * ASTR) * 2);
        unsigned sV = sb + (unsigned)((AV_OFF + st * 64 * ASTR) * 2);

        // ---- S = Q K^T  (64 keys) ----
        float sacc[2][8][4];
        #pragma unroll
        for (int mt = 0; mt < 2; mt++)
            #pragma unroll
            for (int nt = 0; nt < 8; nt++)
                #pragma unroll
                for (int q = 0; q < 4; q++) sacc[mt][nt][q] = 0.f;

        #pragma unroll
        for (int ks = 0; ks < 4; ks++) {
            unsigned bf[4][4];
            #pragma unroll
            for (int nt2 = 0; nt2 < 4; nt2++) {
                unsigned addr = sK + (unsigned)(((nt2 * 16 + (lane & 7) + ((lane >> 4) & 1) * 8) * ASTR
                                 + ks * 16 + ((lane >> 3) & 1) * 8) * 2);
                ldsm_x4(bf[nt2][0], bf[nt2][1], bf[nt2][2], bf[nt2][3], addr);
            }
            #pragma unroll
            for (int mt = 0; mt < 2; mt++)
                #pragma unroll
                for (int nt2 = 0; nt2 < 4; nt2++) {
                    mma_f16(sacc[mt][2 * nt2],     qf[mt][ks][0], qf[mt][ks][1], qf[mt][ks][2], qf[mt][ks][3],
                            bf[nt2][0], bf[nt2][1]);
                    mma_f16(sacc[mt][2 * nt2 + 1], qf[mt][ks][0], qf[mt][ks][1], qf[mt][ks][2], qf[mt][ks][3],
                            bf[nt2][2], bf[nt2][3]);
                }
        }

        // ---- online softmax (scale 0.125) ----
        #pragma unroll
        for (int mt = 0; mt < 2; mt++)
            #pragma unroll
            for (int hh = 0; hh < 2; hh++) {
                int ri = mt * 2 + hh;
                float rmax = -1e30f;
                #pragma unroll
                for (int nt = 0; nt < 8; nt++) {
                    float v0 = sacc[mt][nt][hh * 2] * 0.125f;
                    float v1 = sacc[mt][nt][hh * 2 + 1] * 0.125f;
                    sacc[mt][nt][hh * 2] = v0; sacc[mt][nt][hh * 2 + 1] = v1;
                    rmax = fmaxf(rmax, fmaxf(v0, v1));
                }
                rmax = fmaxf(rmax, __shfl_xor_sync(0xffffffffu, rmax, 1));
                rmax = fmaxf(rmax, __shfl_xor_sync(0xffffffffu, rmax, 2));
                float mnew = fmaxf(mrow[ri], rmax);
                float corr = __expf(mrow[ri] - mnew);
                mrow[ri] = mnew;
                float ps = 0.f;
                #pragma unroll
                for (int nt = 0; nt < 8; nt++) {
                    float p0 = __expf(sacc[mt][nt][hh * 2] - mnew);
                    float p1 = __expf(sacc[mt][nt][hh * 2 + 1] - mnew);
                    sacc[mt][nt][hh * 2] = p0; sacc[mt][nt][hh * 2 + 1] = p1;
                    ps += p0 + p1;
                }
                ps += __shfl_xor_sync(0xffffffffu, ps, 1);
                ps += __shfl_xor_sync(0xffffffffu, ps, 2);
                lrow[ri] = lrow[ri] * corr + ps;
                #pragma unroll
                for (int nt = 0; nt < 8; nt++) {
                    Oa[mt][nt][hh * 2] *= corr;
                    Oa[mt][nt][hh * 2 + 1] *= corr;
                }
            }

        // ---- O += P V ---- (P packs directly into A fragments)
        #pragma unroll
        for (int ks = 0; ks < 4; ks++) {
            unsigned pa[2][4];
            #pragma unroll
            for (int mt = 0; mt < 2; mt++) {
                pa[mt][0] = pack_h2(sacc[mt][2 * ks][0],     sacc[mt][2 * ks][1]);
                pa[mt][1] = pack_h2(sacc[mt][2 * ks][2],     sacc[mt][2 * ks][3]);
                pa[mt][2] = pack_h2(sacc[mt][2 * ks + 1][0], sacc[mt][2 * ks + 1][1]);
                pa[mt][3] = pack_h2(sacc[mt][2 * ks + 1][2], sacc[mt][2 * ks + 1][3]);
            }
            #pragma unroll
            for (int nt = 0; nt < 8; nt++) {
                unsigned vb0, vb1;
                unsigned addr = sV + (unsigned)(((ks * 16 + (l2 & 7) + (l2 >> 3) * 8) * ASTR + nt * 8) * 2);
                ldsm_x2t(vb0, vb1, addr);
                #pragma unroll
                for (int mt = 0; mt < 2; mt++)
                    mma_f16(Oa[mt][nt], pa[mt][0], pa[mt][1], pa[mt][2], pa[mt][3], vb0, vb1);
            }
        }
        __syncthreads();
    }

    // ---- write ctx (fp16) ----
    #pragma unroll
    for (int mt = 0; mt < 2; mt++)
        #pragma unroll
        for (int hh = 0; hh < 2; hh++) {
            float inv = 1.f / lrow[mt * 2 + hh];
            int qrow = q0 + qb + mt * 16 + g + hh * 8;
            __half* op = ctx + ((long)(b * Sv) + qrow) * Dv + h * HDv;
            #pragma unroll
            for (int nt = 0; nt < 8; nt++) {
                *(__half2*)(op + nt * 8 + 2 * j) =
                    __floats2half2_rn(Oa[mt][nt][hh * 2] * inv, Oa[mt][nt][hh * 2 + 1] * inv);
            }
        }
}

// ======================= small kernels =======================
__global__ void k_init() {
    int i = blockIdx.x * blockDim.x + threadIdx.x;
    if (i < MAXP) g_gather[i] = -1;
    if (i < Ev) g_counts[i] = 0;
}

__global__ __launch_bounds__(256) void k_addln(const float* __restrict__ xa,
                                               const float* __restrict__ xb,
                                               const float* __restrict__ g,
                                               const float* __restrict__ bt,
                                               float* __restrict__ out)
{
    __shared__ float red[256];
    int n = blockIdx.x, tid = threadIdx.x;
    const float* pa = xa + (long)n * Dv;
    const float* pb = xb + (long)n * Dv;
    float v[4]; float s = 0.f;
    #pragma unroll
    for (int i = 0; i < 4; i++) { int d = tid + i * 256; v[i] = pa[d] + pb[d]; s += v[i]; }
    red[tid] = s; __syncthreads();
    for (int st = 128; st > 0; st >>= 1) { if (tid < st) red[tid] += red[tid + st]; __syncthreads(); }
    float mean = red[0] * (1.f / Dv);
    __syncthreads();
    float vs = 0.f;
    #pragma unroll
    for (int i = 0; i < 4; i++) { float t = v[i] - mean; vs += t * t; }
    red[tid] = vs; __syncthreads();
    for (int st = 128; st > 0; st >>= 1) { if (tid < st) red[tid] += red[tid + st]; __syncthreads(); }
    float rstd = rsqrtf(red[0] * (1.f / Dv) + LNEPS);
    #pragma unroll
    for (int i = 0; i < 4; i++) {
        int d = tid + i * 256;
        out[(long)n * Dv + d] = (v[i] - mean) * rstd * g[d] + bt[d];
    }
}

__global__ __launch_bounds__(256) void k_gate(const float* __restrict__ x1,
                                              const float* __restrict__ gw,
                                              const float* __restrict__ gb)
{
    int n = blockIdx.x;
    int w = threadIdx.x >> 5, lane = threadIdx.x & 31;
    const float* xp = x1 + (long)n * Dv;
    const float* wp = gw + (long)w * Dv;
    float s = 0.f;
    for (int d = lane; d < Dv; d += 32) s += xp[d] * wp[d];
    #pragma unroll
    for (int off = 16; off; off >>= 1) s += __shfl_down_sync(0xffffffff, s, off);
    __shared__ float lg[Ev];
    if (lane == 0) lg[w] = s + gb[w];
    __syncthreads();
    if (threadIdx.x == 0) {
        float l[Ev];
        #pragma unroll
        for (int e = 0; e < Ev; e++) { l[e] = lg[e]; g_logits[(long)n * Ev + e] = l[e]; }
        int i0 = 0;
        #pragma unroll
        for (int e = 1; e < Ev; e++) if (l[e] > l[i0]) i0 = e;
        int i1 = -1;
        #pragma unroll
        for (int e = 0; e < Ev; e++) { if (e == i0) continue; if (i1 < 0 || l[e] > l[i1]) i1 = e; }
        float e1 = expf(l[i1] - l[i0]);
        float denom = 1.f + e1;
        g_topE[n * 2 + 0] = i0; g_topE[n * 2 + 1] = i1;
        g_topw[n * 2 + 0] = 1.f / denom; g_topw[n * 2 + 1] = e1 / denom;
        atomicAdd(&g_counts[i0], 1);
        atomicAdd(&g_counts[i1], 1);
    }
}

__global__ void k_scan() {
    if (threadIdx.x == 0) {
        int t = 0;
        for (int e = 0; e < Ev; e++) {
            g_off[e] = t; g_cursor[e] = t;
            t += (g_counts[e] + 127) & ~127;
        }
        g_off[Ev] = t;
        g_Mpad[0] = t;
    }
}

__global__ void k_assign() {
    int i = blockIdx.x * blockDim.x + threadIdx.x;
    if (i >= NTOK * 2) return;
    int e = g_topE[i];
    int p = atomicAdd(&g_cursor[e], 1);
    g_gather[p] = i >> 1;
    g_pos[i] = p;
}

__global__ __launch_bounds__(256) void k_gather(const float* __restrict__ x1,
                                                __half* __restrict__ xg)
{
    int p = blockIdx.x;
    int g = g_gather[p];
    __half2* dst = (__half2*)(xg + (long)p * Dv);
    int t = threadIdx.x;
    if (g >= 0) {
        float4 v = ((const float4*)(x1 + (long)g * Dv))[t];
        dst[2 * t]     = __floats2half2_rn(v.x, v.y);
        dst[2 * t + 1] = __floats2half2_rn(v.z, v.w);
    } else {
        dst[2 * t] = __floats2half2_rn(0.f, 0.f);
        dst[2 * t + 1] = __floats2half2_rn(0.f, 0.f);
    }
}

__global__ __launch_bounds__(256) void k_scatter_ln2(const float* __restrict__ x1,
                                                     const float* __restrict__ g,
                                                     const float* __restrict__ bt,
                                                     float* __restrict__ out)
{
    __shared__ float red[256];
    int n = blockIdx.x, tid = threadIdx.x;
    int p0 = g_pos[n * 2 + 0], p1 = g_pos[n * 2 + 1];
    float w0 = g_topw[n * 2 + 0], w1 = g_topw[n * 2 + 1];
    const float* px = x1 + (long)n * Dv;
    const float* pe0 = g_eo + (long)p0 * Dv;
    const float* pe1 = g_eo + (long)p1 * Dv;
    float v[4]; float s = 0.f;
    #pragma unroll
    for (int i = 0; i < 4; i++) {
        int d = tid + i * 256;
        v[i] = px[d] + w0 * pe0[d] + w1 * pe1[d];
        s += v[i];
    }
    red[tid] = s; __syncthreads();
    for (int st = 128; st > 0; st >>= 1) { if (tid < st) red[tid] += red[tid + st]; __syncthreads(); }
    float mean = red[0] * (1.f / Dv);
    __syncthreads();
    float vs = 0.f;
    #pragma unroll
    for (int i = 0; i < 4; i++) { float t = v[i] - mean; vs += t * t; }
    red[tid] = vs; __syncthreads();
    for (int st = 128; st > 0; st >>= 1) { if (tid < st) red[tid] += red[tid + st]; __syncthreads(); }
    float rstd = rsqrtf(red[0] * (1.f / Dv) + LNEPS);
    #pragma unroll
    for (int i = 0; i < 4; i++) {
        int d = tid + i * 256;
        out[(long)n * Dv + d] = (v[i] - mean) * rstd * g[d] + bt[d];
    }
}

__global__ __launch_bounds__(256) void k_lb(float* __restrict__ out) {
    __shared__ float sm[256][Ev];
    int tid = threadIdx.x;
    float u[Ev];
    #pragma unroll
    for (int e = 0; e < Ev; e++) u[e] = 0.f;
    for (int n = tid; n < NTOK; n += 256) {
        float l[Ev], mx = -1e30f, s = 0.f;
        #pragma unroll
        for (int e = 0; e < Ev; e++) { l[e] = g_logits[(long)n * Ev + e]; mx = fmaxf(mx, l[e]); }
        #pragma unroll
        for (int e = 0; e < Ev; e++) { l[e] = expf(l[e] - mx); s += l[e]; }
        float inv = 1.f / s;
        #pragma unroll
        for (int e = 0; e < Ev; e++) u[e] += l[e] * inv;
    }
    #pragma unroll
    for (int e = 0; e < Ev; e++) sm[tid][e] = u[e];
    __syncthreads();
    for (int st = 128; st > 0; st >>= 1) {
        if (tid < st)
            #pragma unroll
            for (int e = 0; e < Ev; e++) sm[tid][e] += sm[tid + st][e];
        __syncthreads();
    }
    if (tid == 0) {
        float lb = 0.f;
        #pragma unroll
        for (int e = 0; e < Ev; e++) { float us = sm[0][e] * (1.f / NTOK); lb += us * us; }
        out[0] = (float)Ev * lb;
    }
}

// ======================= launch =======================
static void* symaddr(const void* s) { void* p = nullptr; cudaGetSymbolAddress(&p, s); return p; }

extern "C" void kernel_launch(void* const* d_in, const int* in_sizes, int n_in,
                              void* d_out, int out_size)
{
    (void)in_sizes; (void)n_in;
    const float* x    = (const float*)d_in[0];
    const float* inw  = (const float*)d_in[1];
    const float* inb  = (const float*)d_in[2];
    const float* outw = (const float*)d_in[3];
    const float* outb = (const float*)d_in[4];
    const float* ln1g = (const float*)d_in[5];
    const float* ln1b = (const float*)d_in[6];
    const float* gw   = (const float*)d_in[7];
    const float* gb   = (const float*)d_in[8];
    const float* w1   = (const float*)d_in[9];
    const float* b1   = (const float*)d_in[10];
    const float* w2   = (const float*)d_in[11];
    const float* b2   = (const float*)d_in[12];
    const float* ln2g = (const float*)d_in[13];
    const float* ln2b = (const float*)d_in[14];
    float* out = (float*)d_out;

    __half* p_xh    = (__half*)symaddr(g_xh);
    __half* p_qkvh  = (__half*)symaddr(g_qkvh);
    __half* p_ctxh  = (__half*)symaddr(g_ctxh);
    __half* p_xgh   = (__half*)symaddr(g_xgh);
    __half* p_hh    = (__half*)symaddr(g_hh);
    __half* p_inwh  = (__half*)symaddr(g_inwh);
    __half* p_outwh = (__half*)symaddr(g_outwh);
    __half* p_w1h   = (__half*)symaddr(g_w1h);
    __half* p_w2h   = (__half*)symaddr(g_w2h);
    float* p_ao   = (float*)symaddr(g_attnout);
    float* p_x1   = (float*)symaddr(g_x1);
    float* p_eo   = (float*)symaddr(g_eo);
    int*   p_Mpad = (int*)symaddr(g_Mpad);
    int*   p_off  = (int*)symaddr(g_off);

    cudaFuncSetAttribute(gemm_h, cudaFuncAttributeMaxDynamicSharedMemorySize, GSMEMH);
    cudaFuncSetAttribute(k_attn_h, cudaFuncAttributeMaxDynamicSharedMemorySize, ASMEMH);

    // 0. fp32 -> fp16 conversions (weights + x)
    {
        struct { const float* src; __half* dst; long n; } cv[5] = {
            { x,    p_xh,    (long)NTOK * Dv },
            { inw,  p_inwh,  (long)3 * Dv * Dv },
            { outw, p_outwh, (long)Dv * Dv },
            { w1,   p_w1h,   (long)Ev * FFv * Dv },
            { w2,   p_w2h,   (long)Ev * Dv * FFv },
        };
        for (int i = 0; i < 5; i++) {
            int n4 = (int)(cv[i].n / 4);
            k_f2h<<<(n4 + 255) / 256, 256>>>((const float4*)cv[i].src, (__half2*)cv[i].dst, n4);
        }
    }

    // 1. routing state init
    k_init<<<(MAXP + 255) / 256, 256>>>();

    // 2. qkv = x @ in_proj_w^T + b  -> fp16
    gemm_h<<<dim3(3 * Dv / 128, NTOK / 128), 128, GSMEMH>>>(
        p_xh, p_inwh, inb, nullptr, p_qkvh, Dv, Dv, Dv, 3 * Dv,
        nullptr, nullptr, 0, 0, 0);

    // 3. attention -> ctx (fp16)
    k_attn_h<<<dim3(Sv / 128, Bv * Hv), 128, ASMEMH>>>(p_qkvh, p_ctxh);

    // 4. attn_out = ctx @ out_w^T + b  -> fp32
    gemm_h<<<dim3(Dv / 128, NTOK / 128), 128, GSMEMH>>>(
        p_ctxh, p_outwh, outb, p_ao, nullptr, Dv, Dv, Dv, Dv,
        nullptr, nullptr, 0, 0, 0);

    // 5. x1 = LN1(x + attn_out)
    k_addln<<<NTOK, 256>>>(x, p_ao, ln1g, ln1b, p_x1);

    // 6. gate
    k_gate<<<NTOK, 256>>>(p_x1, gw, gb);

    // 7-8. routing
    k_scan<<<1, 32>>>();
    k_assign<<<(NTOK * 2 + 255) / 256, 256>>>();

    // 9. gather tokens -> fp16
    k_gather<<<MAXP, 256>>>(p_x1, p_xgh);

    // 10. h = relu(xg @ w1[e]^T + b1[e]) -> fp16
    gemm_h<<<dim3(FFv / 128, MAXP / 128), 128, GSMEMH>>>(
        p_xgh, p_w1h, b1, nullptr, p_hh, Dv, Dv, Dv, FFv,
        p_Mpad, p_off, (long)FFv * Dv, FFv, 1);

    // 11. eo = h @ w2[e]^T + b2[e] -> fp32
    gemm_h<<<dim3(Dv / 128, MAXP / 128), 128, GSMEMH>>>(
        p_hh, p_w2h, b2, p_eo, nullptr, FFv, FFv, FFv, Dv,
        p_Mpad, p_off, (long)Dv * FFv, Dv, 0);

    // 12. out = LN2(x1 + moe)
    k_scatter_ln2<<<NTOK, 256>>>(p_x1, ln2g, ln2b, out);

    // 13. lb_loss
    if (out_size > NTOK * Dv) {
        k_lb<<<1, 256>>>(out + (size_t)NTOK * Dv);
    }
}

// round 7
// speedup vs baseline: 7.4118x; 1.0110x over previous
#include <cuda_runtime.h>
#include <cuda_fp16.h>
#include <cstdint>

#define Bv 2
#define Sv 2048
#define Dv 1024
#define Hv 16
#define HDv 64
#define FFv 4096
#define Ev 8
#define NTOK (Bv*Sv)          // 4096
#define MAXP 9216             // 2*NTOK + 8*128 padding
#define LNEPS 1e-5f

// ---------------- scratch (device globals; no runtime alloc) ----------------
__device__ __half g_xh[(size_t)NTOK * Dv];
__device__ __half g_qkvh[(size_t)NTOK * 3 * Dv];
__device__ __half g_ctxh[(size_t)NTOK * Dv];
__device__ __half g_xgh[(size_t)MAXP * Dv];
__device__ __half g_hh[(size_t)MAXP * FFv];
__device__ __half g_inwh[(size_t)3 * Dv * Dv];
__device__ __half g_outwh[(size_t)Dv * Dv];
__device__ __half g_w1h[(size_t)Ev * FFv * Dv];
__device__ __half g_w2h[(size_t)Ev * Dv * FFv];
__device__ float g_attnout[(size_t)NTOK * Dv];
__device__ float g_x1[(size_t)NTOK * Dv];
__device__ float g_eo[(size_t)MAXP * Dv];
__device__ float g_logits[(size_t)NTOK * Ev];
__device__ float g_topw[(size_t)NTOK * 2];
__device__ int   g_topE[(size_t)NTOK * 2];
__device__ int   g_pos[(size_t)NTOK * 2];
__device__ int   g_counts[Ev];
__device__ int   g_cursor[Ev];
__device__ int   g_off[Ev + 1];
__device__ int   g_Mpad[1];
__device__ int   g_gather[MAXP];

// ======================= PTX helpers =======================
__device__ __forceinline__ unsigned smem_u32(const void* p) {
    unsigned a;
    asm("{ .reg .u64 t; cvta.to.shared.u64 t, %1; cvt.u32.u64 %0, t; }" : "=r"(a) : "l"(p));
    return a;
}
__device__ __forceinline__ void cpa16(unsigned dst, const void* src) {
    asm volatile("cp.async.cg.shared.global [%0], [%1], 16;" :: "r"(dst), "l"(src));
}
__device__ __forceinline__ void ldsm_x4(unsigned& r0, unsigned& r1, unsigned& r2, unsigned& r3, unsigned a) {
    asm volatile("ldmatrix.sync.aligned.m8n8.x4.shared.b16 {%0,%1,%2,%3}, [%4];"
        : "=r"(r0), "=r"(r1), "=r"(r2), "=r"(r3) : "r"(a));
}
__device__ __forceinline__ void ldsm_x2t(unsigned& r0, unsigned& r1, unsigned a) {
    asm volatile("ldmatrix.sync.aligned.m8n8.x2.trans.shared.b16 {%0,%1}, [%2];"
        : "=r"(r0), "=r"(r1) : "r"(a));
}
__device__ __forceinline__ void mma_f16(float* c,
    unsigned a0, unsigned a1, unsigned a2, unsigned a3, unsigned b0, unsigned b1)
{
    asm volatile(
        "mma.sync.aligned.m16n8k16.row.col.f32.f16.f16.f32 "
        "{%0,%1,%2,%3}, {%4,%5,%6,%7}, {%8,%9}, {%0,%1,%2,%3};"
        : "+f"(c[0]), "+f"(c[1]), "+f"(c[2]), "+f"(c[3])
        : "r"(a0), "r"(a1), "r"(a2), "r"(a3), "r"(b0), "r"(b1));
}
__device__ __forceinline__ unsigned pack_h2(float a, float b) {
    __half2 h = __floats2half2_rn(a, b);
    return *reinterpret_cast<unsigned*>(&h);
}

extern __shared__ float smem_f[];

// ======================= fp32 -> fp16 converter =======================
__global__ __launch_bounds__(256) void k_f2h(const float4* __restrict__ in,
                                             __half2* __restrict__ out, int n4)
{
    int i = blockIdx.x * blockDim.x + threadIdx.x;
    if (i >= n4) return;
    float4 v = in[i];
    out[2 * i]     = __floats2half2_rn(v.x, v.y);
    out[2 * i + 1] = __floats2half2_rn(v.z, v.w);
}

// ======================= fp16 mma GEMM =======================
// C[M,N] = A[M,K]h * B[N,K]h^T + bias. 128x128 CTA, K-tile 64, 3 stages,
// 128 threads: 4 warps in 2x2, each computing 64x64.
#define GSTR 72                         // smem row stride in halfs (144B)
#define GTILE_H (128 * GSTR)            // 9216 halfs per matrix
#define GSTAGE_H (2 * GTILE_H)          // 18432 halfs per stage
#define NST 3
#define GSMEMH (NST * GSTAGE_H * 2)     // 110592 bytes

__device__ __forceinline__ void load_tile_h(unsigned sBase,
    const __half* __restrict__ A, int lda, const __half* __restrict__ Bm, int ldb,
    int row0, int col0, int k0, int tid)
{
    #pragma unroll
    for (int i = 0; i < 8; i++) {
        int idx = i * 128 + tid;
        int r = idx >> 3, c = idx & 7;
        unsigned doff = (unsigned)((r * GSTR + c * 8) * 2);
        cpa16(sBase + doff, A + (long)(row0 + r) * lda + k0 + c * 8);
        cpa16(sBase + GTILE_H * 2 + doff, Bm + (long)(col0 + r) * ldb + k0 + c * 8);
    }
}

__global__ __launch_bounds__(128, 2) void gemm_h(
    const __half* __restrict__ A, const __half* __restrict__ Bm,
    const float* __restrict__ bias, float* __restrict__ C, __half* __restrict__ Ch,
    int Kd, int lda, int ldb, int ldc,
    const int* __restrict__ dM, const int* __restrict__ exp_off,
    long bStride, int biasStride, int relu)
{
    int row0 = blockIdx.y * 128;
    if (dM && row0 >= *dM) return;
    int col0 = blockIdx.x * 128;
    if (exp_off) {
        int e = 0;
        while (row0 >= exp_off[e + 1]) e++;
        Bm += (long)e * bStride;
        bias += (long)e * biasStride;
    }
    int tid = threadIdx.x, lane = tid & 31, wid = tid >> 5;
    int warp_m = wid >> 1, warp_n = wid & 1;
    unsigned sb = smem_u32(smem_f);

    float acc[4][8][4];
    #pragma unroll
    for (int mt = 0; mt < 4; mt++)
        #pragma unroll
        for (int nt = 0; nt < 8; nt++)
            #pragma unroll
            for (int j = 0; j < 4; j++) acc[mt][nt][j] = 0.f;

    int nK = Kd / 64;
    #pragma unroll
    for (int s = 0; s < 2; s++) {
        load_tile_h(sb + s * GSTAGE_H * 2, A, lda, Bm, ldb, row0, col0, s * 64, tid);
        asm volatile("cp.async.commit_group;" ::: "memory");
    }

    // ldmatrix per-lane addressing
    int arow = lane & 15, akb = lane >> 4;
    int bnrow = (lane & 7) + ((lane >> 4) & 1) * 8;
    int bkb = (lane >> 3) & 1;

    for (int kt = 0; kt < nK; kt++) {
        if (kt + 2 < nK)
            load_tile_h(sb + ((kt + 2) % 3) * GSTAGE_H * 2, A, lda, Bm, ldb, row0, col0, (kt + 2) * 64, tid);
        asm volatile("cp.async.commit_group;" ::: "memory");
        asm volatile("cp.async.wait_group 2;" ::: "memory");
        __syncthreads();

        unsigned sA = sb + (kt % 3) * GSTAGE_H * 2;
        unsigned sB = sA + GTILE_H * 2;

        #pragma unroll
        for (int ks = 0; ks < 4; ks++) {
            unsigned af[4][4], bf[4][4];
            #pragma unroll
            for (int mt = 0; mt < 4; mt++) {
                unsigned addr = sA + (unsigned)(((warp_m * 64 + mt * 16 + arow) * GSTR
                                 + ks * 16 + akb * 8) * 2);
                ldsm_x4(af[mt][0], af[mt][1], af[mt][2], af[mt][3], addr);
            }
            #pragma unroll
            for (int nt2 = 0; nt2 < 4; nt2++) {
                unsigned addr = sB + (unsigned)(((warp_n * 64 + nt2 * 16 + bnrow) * GSTR
                                 + ks * 16 + bkb * 8) * 2);
                ldsm_x4(bf[nt2][0], bf[nt2][1], bf[nt2][2], bf[nt2][3], addr);
            }
            #pragma unroll
            for (int mt = 0; mt < 4; mt++)
                #pragma unroll
                for (int nt2 = 0; nt2 < 4; nt2++) {
                    mma_f16(acc[mt][2 * nt2],     af[mt][0], af[mt][1], af[mt][2], af[mt][3],
                            bf[nt2][0], bf[nt2][1]);
                    mma_f16(acc[mt][2 * nt2 + 1], af[mt][0], af[mt][1], af[mt][2], af[mt][3],
                            bf[nt2][2], bf[nt2][3]);
                }
        }
        __syncthreads();
    }

    int g = lane >> 2, j = lane & 3;
    #pragma unroll
    for (int mt = 0; mt < 4; mt++) {
        int r = row0 + warp_m * 64 + mt * 16 + g;
        #pragma unroll
        for (int nt = 0; nt < 8; nt++) {
            int cg = col0 + warp_n * 64 + nt * 8 + j * 2;
            float b0 = bias[cg], b1 = bias[cg + 1];
            float v0 = acc[mt][nt][0] + b0, v1 = acc[mt][nt][1] + b1;
            float v2 = acc[mt][nt][2] + b0, v3 = acc[mt][nt][3] + b1;
            if (relu) {
                v0 = fmaxf(v0, 0.f); v1 = fmaxf(v1, 0.f);
                v2 = fmaxf(v2, 0.f); v3 = fmaxf(v3, 0.f);
            }
            if (Ch) {
                *(__half2*)(Ch + (long)r * ldc + cg) = __floats2half2_rn(v0, v1);
                *(__half2*)(Ch + (long)(r + 8) * ldc + cg) = __floats2half2_rn(v2, v3);
            } else {
                *(float2*)(C + (long)r * ldc + cg) = make_float2(v0, v1);
                *(float2*)(C + (long)(r + 8) * ldc + cg) = make_float2(v2, v3);
            }
        }
    }
}

// ======================= fp16 tensor-core flash attention =======================
// CTA: 128 queries (4 warps x 32 rows), 64-key tiles, double-buffered.
#define ASTR 72
#define AQ_OFF 0
#define AK_OFF (128 * ASTR)                 // 9216
#define AV_OFF (AK_OFF + 2 * 64 * ASTR)     // 18432
#define ASMEMH ((AV_OFF + 2 * 64 * ASTR) * 2)   // 55296 bytes

__global__ __launch_bounds__(128) void k_attn_h(const __half* __restrict__ qkv,
                                                __half* __restrict__ ctx)
{
    __half* sm = (__half*)smem_f;
    int tid = threadIdx.x, lane = tid & 31, wid = tid >> 5;
    int b = blockIdx.y >> 4, h = blockIdx.y & 15;
    int q0 = blockIdx.x * 128;
    const __half* base = qkv + (long)b * Sv * (3 * Dv) + h * HDv;
    unsigned sb = smem_u32(sm);
    int g = lane >> 2, j = lane & 3;
    int qb = wid * 32;
    int arow = lane & 15;
    int akb = lane >> 4;
    int l2 = lane & 15;

    // load Q tile + K/V tile 0
    #pragma unroll
    for (int i = 0; i < 8; i++) {
        int idx = i * 128 + tid;
        int r = idx >> 3, c = idx & 7;
        cpa16(sb + (unsigned)((AQ_OFF + r * ASTR + c * 8) * 2),
              base + (long)(q0 + r) * (3 * Dv) + c * 8);
    }
    #pragma unroll
    for (int i = 0; i < 4; i++) {
        int idx = i * 128 + tid;
        int r = idx >> 3, c = idx & 7;
        cpa16(sb + (unsigned)((AK_OFF + r * ASTR + c * 8) * 2), base + (long)r * (3 * Dv) + Dv + c * 8);
        cpa16(sb + (unsigned)((AV_OFF + r * ASTR + c * 8) * 2), base + (long)r * (3 * Dv) + 2 * Dv + c * 8);
    }
    asm volatile("cp.async.commit_group;" ::: "memory");
    asm volatile("cp.async.wait_group 0;" ::: "memory");
    __syncthreads();

    // hoist Q fragments (constant over key loop)
    unsigned qf[2][4][4];
    #pragma unroll
    for (int mt = 0; mt < 2; mt++)
        #pragma unroll
        for (int ks = 0; ks < 4; ks++) {
            unsigned addr = sb + (unsigned)(((qb + mt * 16 + arow) * ASTR + ks * 16 + akb * 8) * 2);
            ldsm_x4(qf[mt][ks][0], qf[mt][ks][1], qf[mt][ks][2], qf[mt][ks][3], addr);
        }

    float Oa[2][8][4];
    float mrow[4], lrow[4];
    #pragma unroll
    for (int i = 0; i < 4; i++) { mrow[i] = -1e30f; lrow[i] = 0.f; }
    #pragma unroll
    for (int mt = 0; mt < 2; mt++)
        #pragma unroll
        for (int nt = 0; nt < 8; nt++)
            #pragma unroll
            for (int q = 0; q < 4; q++) Oa[mt][nt][q] = 0.f;

    for (int kt = 0; kt < Sv / 64; kt++) {
        int st = kt & 1;
        if (kt + 1 < Sv / 64) {
            int st2 = (kt + 1) & 1;
            #pragma unroll
            for (int i = 0; i < 4; i++) {
                int idx = i * 128 + tid;
                int r = idx >> 3, c = idx & 7;
                long gr = (long)((kt + 1) * 64 + r) * (3 * Dv);
                cpa16(sb + (unsigned)((AK_OFF + st2 * 64 * ASTR + r * ASTR + c * 8) * 2), base + gr + Dv + c * 8);
                cpa16(sb + (unsigned)((AV_OFF + st2 * 64 * ASTR + r * ASTR + c * 8) * 2), base + gr + 2 * Dv + c * 8);
            }
            asm volatile("cp.async.commit_group;" ::: "memory");
            asm volatile("cp.async.wait_group 1;" ::: "memory");
        } else {
            asm volatile("cp.async.wait_group 0;" ::: "memory");
        }
        __syncthreads();

        unsigned sK = sb + (unsigned)((AK_OFF + st * 64 * ASTR) * 2);
        unsigned sV = sb + (unsigned)((AV_OFF + st * 64 * ASTR) * 2);

        // ---- S = Q K^T  (64 keys) ----
        float sacc[2][8][4];
        #pragma unroll
        for (int mt = 0; mt < 2; mt++)
            #pragma unroll
            for (int nt = 0; nt < 8; nt++)
                #pragma unroll
                for (int q = 0; q < 4; q++) sacc[mt][nt][q] = 0.f;

        #pragma unroll
        for (int ks = 0; ks < 4; ks++) {
            unsigned bf[4][4];
            #pragma unroll
            for (int nt2 = 0; nt2 < 4; nt2++) {
                unsigned addr = sK + (unsigned)(((nt2 * 16 + (lane & 7) + ((lane >> 4) & 1) * 8) * ASTR
                                 + ks * 16 + ((lane >> 3) & 1) * 8) * 2);
                ldsm_x4(bf[nt2][0], bf[nt2][1], bf[nt2][2], bf[nt2][3], addr);
            }
            #pragma unroll
            for (int mt = 0; mt < 2; mt++)
                #pragma unroll
                for (int nt2 = 0; nt2 < 4; nt2++) {
                    mma_f16(sacc[mt][2 * nt2],     qf[mt][ks][0], qf[mt][ks][1], qf[mt][ks][2], qf[mt][ks][3],
                            bf[nt2][0], bf[nt2][1]);
                    mma_f16(sacc[mt][2 * nt2 + 1], qf[mt][ks][0], qf[mt][ks][1], qf[mt][ks][2], qf[mt][ks][3],
                            bf[nt2][2], bf[nt2][3]);
                }
        }

        // ---- online softmax (scale 0.125) ----
        #pragma unroll
        for (int mt = 0; mt < 2; mt++)
            #pragma unroll
            for (int hh = 0; hh < 2; hh++) {
                int ri = mt * 2 + hh;
                float rmax = -1e30f;
                #pragma unroll
                for (int nt = 0; nt < 8; nt++) {
                    float v0 = sacc[mt][nt][hh * 2] * 0.125f;
                    float v1 = sacc[mt][nt][hh * 2 + 1] * 0.125f;
                    sacc[mt][nt][hh * 2] = v0; sacc[mt][nt][hh * 2 + 1] = v1;
                    rmax = fmaxf(rmax, fmaxf(v0, v1));
                }
                rmax = fmaxf(rmax, __shfl_xor_sync(0xffffffffu, rmax, 1));
                rmax = fmaxf(rmax, __shfl_xor_sync(0xffffffffu, rmax, 2));
                float mnew = fmaxf(mrow[ri], rmax);
                float corr = __expf(mrow[ri] - mnew);
                mrow[ri] = mnew;
                float ps = 0.f;
                #pragma unroll
                for (int nt = 0; nt < 8; nt++) {
                    float p0 = __expf(sacc[mt][nt][hh * 2] - mnew);
                    float p1 = __expf(sacc[mt][nt][hh * 2 + 1] - mnew);
                    sacc[mt][nt][hh * 2] = p0; sacc[mt][nt][hh * 2 + 1] = p1;
                    ps += p0 + p1;
                }
                ps += __shfl_xor_sync(0xffffffffu, ps, 1);
                ps += __shfl_xor_sync(0xffffffffu, ps, 2);
                lrow[ri] = lrow[ri] * corr + ps;
                #pragma unroll
                for (int nt = 0; nt < 8; nt++) {
                    Oa[mt][nt][hh * 2] *= corr;
                    Oa[mt][nt][hh * 2 + 1] *= corr;
                }
            }

        // ---- O += P V ---- (P packs directly into A fragments)
        #pragma unroll
        for (int ks = 0; ks < 4; ks++) {
            unsigned pa[2][4];
            #pragma unroll
            for (int mt = 0; mt < 2; mt++) {
                pa[mt][0] = pack_h2(sacc[mt][2 * ks][0],     sacc[mt][2 * ks][1]);
                pa[mt][1] = pack_h2(sacc[mt][2 * ks][2],     sacc[mt][2 * ks][3]);
                pa[mt][2] = pack_h2(sacc[mt][2 * ks + 1][0], sacc[mt][2 * ks + 1][1]);
                pa[mt][3] = pack_h2(sacc[mt][2 * ks + 1][2], sacc[mt][2 * ks + 1][3]);
            }
            #pragma unroll
            for (int nt = 0; nt < 8; nt++) {
                unsigned vb0, vb1;
                unsigned addr = sV + (unsigned)(((ks * 16 + (l2 & 7) + (l2 >> 3) * 8) * ASTR + nt * 8) * 2);
                ldsm_x2t(vb0, vb1, addr);
                #pragma unroll
                for (int mt = 0; mt < 2; mt++)
                    mma_f16(Oa[mt][nt], pa[mt][0], pa[mt][1], pa[mt][2], pa[mt][3], vb0, vb1);
            }
        }
        __syncthreads();
    }

    // ---- write ctx (fp16) ----
    #pragma unroll
    for (int mt = 0; mt < 2; mt++)
        #pragma unroll
        for (int hh = 0; hh < 2; hh++) {
            float inv = 1.f / lrow[mt * 2 + hh];
            int qrow = q0 + qb + mt * 16 + g + hh * 8;
            __half* op = ctx + ((long)(b * Sv) + qrow) * Dv + h * HDv;
            #pragma unroll
            for (int nt = 0; nt < 8; nt++) {
                *(__half2*)(op + nt * 8 + 2 * j) =
                    __floats2half2_rn(Oa[mt][nt][hh * 2] * inv, Oa[mt][nt][hh * 2 + 1] * inv);
            }
        }
}

// ======================= small kernels =======================
__global__ void k_init() {
    int i = blockIdx.x * blockDim.x + threadIdx.x;
    if (i < MAXP) g_gather[i] = -1;
    if (i < Ev) g_counts[i] = 0;
}

__global__ __launch_bounds__(256) void k_addln(const float* __restrict__ xa,
                                               const float* __restrict__ xb,
                                               const float* __restrict__ g,
                                               const float* __restrict__ bt,
                                               float* __restrict__ out)
{
    __shared__ float red[256];
    int n = blockIdx.x, tid = threadIdx.x;
    const float* pa = xa + (long)n * Dv;
    const float* pb = xb + (long)n * Dv;
    float v[4]; float s = 0.f;
    #pragma unroll
    for (int i = 0; i < 4; i++) { int d = tid + i * 256; v[i] = pa[d] + pb[d]; s += v[i]; }
    red[tid] = s; __syncthreads();
    for (int st = 128; st > 0; st >>= 1) { if (tid < st) red[tid] += red[tid + st]; __syncthreads(); }
    float mean = red[0] * (1.f / Dv);
    __syncthreads();
    float vs = 0.f;
    #pragma unroll
    for (int i = 0; i < 4; i++) { float t = v[i] - mean; vs += t * t; }
    red[tid] = vs; __syncthreads();
    for (int st = 128; st > 0; st >>= 1) { if (tid < st) red[tid] += red[tid + st]; __syncthreads(); }
    float rstd = rsqrtf(red[0] * (1.f / Dv) + LNEPS);
    #pragma unroll
    for (int i = 0; i < 4; i++) {
        int d = tid + i * 256;
        out[(long)n * Dv + d] = (v[i] - mean) * rstd * g[d] + bt[d];
    }
}

__global__ __launch_bounds__(256) void k_gate(const float* __restrict__ x1,
                                              const float* __restrict__ gw,
                                              const float* __restrict__ gb)
{
    int n = blockIdx.x;
    int w = threadIdx.x >> 5, lane = threadIdx.x & 31;
    const float* xp = x1 + (long)n * Dv;
    const float* wp = gw + (long)w * Dv;
    float s = 0.f;
    for (int d = lane; d < Dv; d += 32) s += xp[d] * wp[d];
    #pragma unroll
    for (int off = 16; off; off >>= 1) s += __shfl_down_sync(0xffffffff, s, off);
    __shared__ float lg[Ev];
    if (lane == 0) lg[w] = s + gb[w];
    __syncthreads();
    if (threadIdx.x == 0) {
        float l[Ev];
        #pragma unroll
        for (int e = 0; e < Ev; e++) { l[e] = lg[e]; g_logits[(long)n * Ev + e] = l[e]; }
        int i0 = 0;
        #pragma unroll
        for (int e = 1; e < Ev; e++) if (l[e] > l[i0]) i0 = e;
        int i1 = -1;
        #pragma unroll
        for (int e = 0; e < Ev; e++) { if (e == i0) continue; if (i1 < 0 || l[e] > l[i1]) i1 = e; }
        float e1 = expf(l[i1] - l[i0]);
        float denom = 1.f + e1;
        g_topE[n * 2 + 0] = i0; g_topE[n * 2 + 1] = i1;
        g_topw[n * 2 + 0] = 1.f / denom; g_topw[n * 2 + 1] = e1 / denom;
        atomicAdd(&g_counts[i0], 1);
        atomicAdd(&g_counts[i1], 1);
    }
}

__global__ void k_scan() {
    if (threadIdx.x == 0) {
        int t = 0;
        for (int e = 0; e < Ev; e++) {
            g_off[e] = t; g_cursor[e] = t;
            t += (g_counts[e] + 127) & ~127;
        }
        g_off[Ev] = t;
        g_Mpad[0] = t;
    }
}

__global__ void k_assign() {
    int i = blockIdx.x * blockDim.x + threadIdx.x;
    if (i >= NTOK * 2) return;
    int e = g_topE[i];
    int p = atomicAdd(&g_cursor[e], 1);
    g_gather[p] = i >> 1;
    g_pos[i] = p;
}

__global__ __launch_bounds__(256) void k_gather(const float* __restrict__ x1,
                                                __half* __restrict__ xg)
{
    int p = blockIdx.x;
    int g = g_gather[p];
    __half2* dst = (__half2*)(xg + (long)p * Dv);
    int t = threadIdx.x;
    if (g >= 0) {
        float4 v = ((const float4*)(x1 + (long)g * Dv))[t];
        dst[2 * t]     = __floats2half2_rn(v.x, v.y);
        dst[2 * t + 1] = __floats2half2_rn(v.z, v.w);
    } else {
        dst[2 * t] = __floats2half2_rn(0.f, 0.f);
        dst[2 * t + 1] = __floats2half2_rn(0.f, 0.f);
    }
}

__global__ __launch_bounds__(256) void k_scatter_ln2(const float* __restrict__ x1,
                                                     const float* __restrict__ g,
                                                     const float* __restrict__ bt,
                                                     float* __restrict__ out)
{
    __shared__ float red[256];
    int n = blockIdx.x, tid = threadIdx.x;
    int p0 = g_pos[n * 2 + 0], p1 = g_pos[n * 2 + 1];
    float w0 = g_topw[n * 2 + 0], w1 = g_topw[n * 2 + 1];
    const float* px = x1 + (long)n * Dv;
    const float* pe0 = g_eo + (long)p0 * Dv;
    const float* pe1 = g_eo + (long)p1 * Dv;
    float v[4]; float s = 0.f;
    #pragma unroll
    for (int i = 0; i < 4; i++) {
        int d = tid + i * 256;
        v[i] = px[d] + w0 * pe0[d] + w1 * pe1[d];
        s += v[i];
    }
    red[tid] = s; __syncthreads();
    for (int st = 128; st > 0; st >>= 1) { if (tid < st) red[tid] += red[tid + st]; __syncthreads(); }
    float mean = red[0] * (1.f / Dv);
    __syncthreads();
    float vs = 0.f;
    #pragma unroll
    for (int i = 0; i < 4; i++) { float t = v[i] - mean; vs += t * t; }
    red[tid] = vs; __syncthreads();
    for (int st = 128; st > 0; st >>= 1) { if (tid < st) red[tid] += red[tid + st]; __syncthreads(); }
    float rstd = rsqrtf(red[0] * (1.f / Dv) + LNEPS);
    #pragma unroll
    for (int i = 0; i < 4; i++) {
        int d = tid + i * 256;
        out[(long)n * Dv + d] = (v[i] - mean) * rstd * g[d] + bt[d];
    }
}

__global__ __launch_bounds__(256) void k_lb(float* __restrict__ out) {
    __shared__ float sm[256][Ev];
    int tid = threadIdx.x;
    float u[Ev];
    #pragma unroll
    for (int e = 0; e < Ev; e++) u[e] = 0.f;
    for (int n = tid; n < NTOK; n += 256) {
        float l[Ev], mx = -1e30f, s = 0.f;
        #pragma unroll
        for (int e = 0; e < Ev; e++) { l[e] = g_logits[(long)n * Ev + e]; mx = fmaxf(mx, l[e]); }
        #pragma unroll
        for (int e = 0; e < Ev; e++) { l[e] = expf(l[e] - mx); s += l[e]; }
        float inv = 1.f / s;
        #pragma unroll
        for (int e = 0; e < Ev; e++) u[e] += l[e] * inv;
    }
    #pragma unroll
    for (int e = 0; e < Ev; e++) sm[tid][e] = u[e];
    __syncthreads();
    for (int st = 128; st > 0; st >>= 1) {
        if (tid < st)
            #pragma unroll
            for (int e = 0; e < Ev; e++) sm[tid][e] += sm[tid + st][e];
        __syncthreads();
    }
    if (tid == 0) {
        float lb = 0.f;
        #pragma unroll
        for (int e = 0; e < Ev; e++) { float us = sm[0][e] * (1.f / NTOK); lb += us * us; }
        out[0] = (float)Ev * lb;
    }
}

// ======================= launch =======================
static void* symaddr(const void* s) { void* p = nullptr; cudaGetSymbolAddress(&p, s); return p; }

extern "C" void kernel_launch(void* const* d_in, const int* in_sizes, int n_in,
                              void* d_out, int out_size)
{
    (void)in_sizes; (void)n_in;
    const float* x    = (const float*)d_in[0];
    const float* inw  = (const float*)d_in[1];
    const float* inb  = (const float*)d_in[2];
    const float* outw = (const float*)d_in[3];
    const float* outb = (const float*)d_in[4];
    const float* ln1g = (const float*)d_in[5];
    const float* ln1b = (const float*)d_in[6];
    const float* gw   = (const float*)d_in[7];
    const float* gb   = (const float*)d_in[8];
    const float* w1   = (const float*)d_in[9];
    const float* b1   = (const float*)d_in[10];
    const float* w2   = (const float*)d_in[11];
    const float* b2   = (const float*)d_in[12];
    const float* ln2g = (const float*)d_in[13];
    const float* ln2b = (const float*)d_in[14];
    float* out = (float*)d_out;

    __half* p_xh    = (__half*)symaddr(g_xh);
    __half* p_qkvh  = (__half*)symaddr(g_qkvh);
    __half* p_ctxh  = (__half*)symaddr(g_ctxh);
    __half* p_xgh   = (__half*)symaddr(g_xgh);
    __half* p_hh    = (__half*)symaddr(g_hh);
    __half* p_inwh  = (__half*)symaddr(g_inwh);
    __half* p_outwh = (__half*)symaddr(g_outwh);
    __half* p_w1h   = (__half*)symaddr(g_w1h);
    __half* p_w2h   = (__half*)symaddr(g_w2h);
    float* p_ao   = (float*)symaddr(g_attnout);
    float* p_x1   = (float*)symaddr(g_x1);
    float* p_eo   = (float*)symaddr(g_eo);
    int*   p_Mpad = (int*)symaddr(g_Mpad);
    int*   p_off  = (int*)symaddr(g_off);

    cudaFuncSetAttribute(gemm_h, cudaFuncAttributeMaxDynamicSharedMemorySize, GSMEMH);
    cudaFuncSetAttribute(k_attn_h, cudaFuncAttributeMaxDynamicSharedMemorySize, ASMEMH);

    // side stream + events for overlapping the big weight conversions
    // (created once on the first, uncaptured, correctness call)
    static cudaStream_t s_side = nullptr;
    static cudaEvent_t ev_fork = nullptr, ev_join = nullptr;
    if (!s_side) {
        cudaStreamCreateWithFlags(&s_side, cudaStreamNonBlocking);
        cudaEventCreateWithFlags(&ev_fork, cudaEventDisableTiming);
        cudaEventCreateWithFlags(&ev_join, cudaEventDisableTiming);
    }

    // ---- fork: w1/w2 conversions (needed only at step 10) run on side stream
    cudaEventRecord(ev_fork, 0);
    cudaStreamWaitEvent(s_side, ev_fork, 0);
    {
        long n1 = (long)Ev * FFv * Dv;
        int n4 = (int)(n1 / 4);
        k_f2h<<<(n4 + 255) / 256, 256, 0, s_side>>>((const float4*)w1, (__half2*)p_w1h, n4);
        k_f2h<<<(n4 + 255) / 256, 256, 0, s_side>>>((const float4*)w2, (__half2*)p_w2h, n4);
    }
    cudaEventRecord(ev_join, s_side);

    // ---- main stream: conversions needed early
    {
        struct { const float* src; __half* dst; long n; } cv[3] = {
            { x,    p_xh,    (long)NTOK * Dv },
            { inw,  p_inwh,  (long)3 * Dv * Dv },
            { outw, p_outwh, (long)Dv * Dv },
        };
        for (int i = 0; i < 3; i++) {
            int n4 = (int)(cv[i].n / 4);
            k_f2h<<<(n4 + 255) / 256, 256>>>((const float4*)cv[i].src, (__half2*)cv[i].dst, n4);
        }
    }

    // 1. routing state init
    k_init<<<(MAXP + 255) / 256, 256>>>();

    // 2. qkv = x @ in_proj_w^T + b  -> fp16
    gemm_h<<<dim3(3 * Dv / 128, NTOK / 128), 128, GSMEMH>>>(
        p_xh, p_inwh, inb, nullptr, p_qkvh, Dv, Dv, Dv, 3 * Dv,
        nullptr, nullptr, 0, 0, 0);

    // 3. attention -> ctx (fp16)
    k_attn_h<<<dim3(Sv / 128, Bv * Hv), 128, ASMEMH>>>(p_qkvh, p_ctxh);

    // 4. attn_out = ctx @ out_w^T + b  -> fp32
    gemm_h<<<dim3(Dv / 128, NTOK / 128), 128, GSMEMH>>>(
        p_ctxh, p_outwh, outb, p_ao, nullptr, Dv, Dv, Dv, Dv,
        nullptr, nullptr, 0, 0, 0);

    // 5. x1 = LN1(x + attn_out)
    k_addln<<<NTOK, 256>>>(x, p_ao, ln1g, ln1b, p_x1);

    // 6. gate
    k_gate<<<NTOK, 256>>>(p_x1, gw, gb);

    // 7-8. routing
    k_scan<<<1, 32>>>();
    k_assign<<<(NTOK * 2 + 255) / 256, 256>>>();

    // 9. gather tokens -> fp16
    k_gather<<<MAXP, 256>>>(p_x1, p_xgh);

    // ---- join: w1/w2 fp16 must be ready before the MoE GEMMs
    cudaStreamWaitEvent(0, ev_join, 0);

    // 10. h = relu(xg @ w1[e]^T + b1[e]) -> fp16
    gemm_h<<<dim3(FFv / 128, MAXP / 128), 128, GSMEMH>>>(
        p_xgh, p_w1h, b1, nullptr, p_hh, Dv, Dv, Dv, FFv,
        p_Mpad, p_off, (long)FFv * Dv, FFv, 1);

    // 11. eo = h @ w2[e]^T + b2[e] -> fp32
    gemm_h<<<dim3(Dv / 128, MAXP / 128), 128, GSMEMH>>>(
        p_hh, p_w2h, b2, p_eo, nullptr, FFv, FFv, FFv, Dv,
        p_Mpad, p_off, (long)Dv * FFv, Dv, 0);

    // 12. out = LN2(x1 + moe)
    k_scatter_ln2<<<NTOK, 256>>>(p_x1, ln2g, ln2b, out);

    // 13. lb_loss
    if (out_size > NTOK * Dv) {
        k_lb<<<1, 256>>>(out + (size_t)NTOK * Dv);
    }
}

// round 8
// speedup vs baseline: 7.7148x; 1.0409x over previous
#include <cuda_runtime.h>
#include <cuda_fp16.h>
#include <cstdint>

#define Bv 2
#define Sv 2048
#define Dv 1024
#define Hv 16
#define HDv 64
#define FFv 4096
#define Ev 8
#define NTOK (Bv*Sv)          // 4096
#define MAXP 9216             // 2*NTOK + 8*128 padding
#define LNEPS 1e-5f

// ---------------- scratch (device globals; no runtime alloc) ----------------
__device__ __half g_xh[(size_t)NTOK * Dv];
__device__ __half g_qkvh[(size_t)NTOK * 3 * Dv];
__device__ __half g_ctxh[(size_t)NTOK * Dv];
__device__ __half g_xgh[(size_t)MAXP * Dv];
__device__ __half g_hh[(size_t)MAXP * FFv];
__device__ __half g_inwh[(size_t)3 * Dv * Dv];
__device__ __half g_outwh[(size_t)Dv * Dv];
__device__ __half g_w1h[(size_t)Ev * FFv * Dv];
__device__ __half g_w2h[(size_t)Ev * Dv * FFv];
__device__ float g_attnout[(size_t)NTOK * Dv];
__device__ float g_x1[(size_t)NTOK * Dv];
__device__ float g_eo[(size_t)MAXP * Dv];
__device__ float g_logits[(size_t)NTOK * Ev];
__device__ float g_topw[(size_t)NTOK * 2];
__device__ int   g_topE[(size_t)NTOK * 2];
__device__ int   g_pos[(size_t)NTOK * 2];
__device__ int   g_counts[Ev];
__device__ int   g_cursor[Ev];
__device__ int   g_off[Ev + 1];
__device__ int   g_Mpad[1];
__device__ int   g_gather[MAXP];

// ======================= PTX helpers =======================
__device__ __forceinline__ unsigned smem_u32(const void* p) {
    unsigned a;
    asm("{ .reg .u64 t; cvta.to.shared.u64 t, %1; cvt.u32.u64 %0, t; }" : "=r"(a) : "l"(p));
    return a;
}
__device__ __forceinline__ void cpa16(unsigned dst, const void* src) {
    asm volatile("cp.async.cg.shared.global [%0], [%1], 16;" :: "r"(dst), "l"(src));
}
__device__ __forceinline__ void ldsm_x4(unsigned& r0, unsigned& r1, unsigned& r2, unsigned& r3, unsigned a) {
    asm volatile("ldmatrix.sync.aligned.m8n8.x4.shared.b16 {%0,%1,%2,%3}, [%4];"
        : "=r"(r0), "=r"(r1), "=r"(r2), "=r"(r3) : "r"(a));
}
__device__ __forceinline__ void ldsm_x2t(unsigned& r0, unsigned& r1, unsigned a) {
    asm volatile("ldmatrix.sync.aligned.m8n8.x2.trans.shared.b16 {%0,%1}, [%2];"
        : "=r"(r0), "=r"(r1) : "r"(a));
}
__device__ __forceinline__ void mma_f16(float* c,
    unsigned a0, unsigned a1, unsigned a2, unsigned a3, unsigned b0, unsigned b1)
{
    asm volatile(
        "mma.sync.aligned.m16n8k16.row.col.f32.f16.f16.f32 "
        "{%0,%1,%2,%3}, {%4,%5,%6,%7}, {%8,%9}, {%0,%1,%2,%3};"
        : "+f"(c[0]), "+f"(c[1]), "+f"(c[2]), "+f"(c[3])
        : "r"(a0), "r"(a1), "r"(a2), "r"(a3), "r"(b0), "r"(b1));
}
__device__ __forceinline__ unsigned pack_h2(float a, float b) {
    __half2 h = __floats2half2_rn(a, b);
    return *reinterpret_cast<unsigned*>(&h);
}

extern __shared__ float smem_f[];

// ======================= fp32 -> fp16 converter =======================
__global__ __launch_bounds__(256) void k_f2h(const float4* __restrict__ in,
                                             __half2* __restrict__ out, int n4)
{
    int i = blockIdx.x * blockDim.x + threadIdx.x;
    if (i >= n4) return;
    float4 v = in[i];
    out[2 * i]     = __floats2half2_rn(v.x, v.y);
    out[2 * i + 1] = __floats2half2_rn(v.z, v.w);
}

// ======================= fp16 mma GEMM =======================
// C[M,N] = A[M,K]h * B[N,K]h^T + bias. 128x128 CTA, K-tile 32, 4 stages,
// single __syncthreads per k-iter. 128 threads: 4 warps (2x2), 64x64 each.
#define GSTR 40                         // smem row stride in halfs (80B)
#define GTILE_H (128 * GSTR)            // 5120 halfs per matrix
#define GSTAGE_H (2 * GTILE_H)          // 10240 halfs per stage
#define NST 4
#define GSMEMH (NST * GSTAGE_H * 2)     // 81920 bytes

__device__ __forceinline__ void load_tile_h(unsigned sBase,
    const __half* __restrict__ A, int lda, const __half* __restrict__ Bm, int ldb,
    int row0, int col0, int k0, int tid)
{
    #pragma unroll
    for (int i = 0; i < 4; i++) {
        int idx = i * 128 + tid;
        int r = idx >> 2, c = idx & 3;
        unsigned doff = (unsigned)((r * GSTR + c * 8) * 2);
        cpa16(sBase + doff, A + (long)(row0 + r) * lda + k0 + c * 8);
        cpa16(sBase + GTILE_H * 2 + doff, Bm + (long)(col0 + r) * ldb + k0 + c * 8);
    }
}

__global__ __launch_bounds__(128, 2) void gemm_h(
    const __half* __restrict__ A, const __half* __restrict__ Bm,
    const float* __restrict__ bias, float* __restrict__ C, __half* __restrict__ Ch,
    int Kd, int lda, int ldb, int ldc,
    const int* __restrict__ dM, const int* __restrict__ exp_off,
    long bStride, int biasStride, int relu)
{
    int row0 = blockIdx.y * 128;
    if (dM && row0 >= *dM) return;
    int col0 = blockIdx.x * 128;
    if (exp_off) {
        int e = 0;
        while (row0 >= exp_off[e + 1]) e++;
        Bm += (long)e * bStride;
        bias += (long)e * biasStride;
    }
    int tid = threadIdx.x, lane = tid & 31, wid = tid >> 5;
    int warp_m = wid >> 1, warp_n = wid & 1;
    unsigned sb = smem_u32(smem_f);

    float acc[4][8][4];
    #pragma unroll
    for (int mt = 0; mt < 4; mt++)
        #pragma unroll
        for (int nt = 0; nt < 8; nt++)
            #pragma unroll
            for (int j = 0; j < 4; j++) acc[mt][nt][j] = 0.f;

    int nK = Kd / 32;
    #pragma unroll
    for (int s = 0; s < 3; s++) {
        load_tile_h(sb + s * GSTAGE_H * 2, A, lda, Bm, ldb, row0, col0, s * 32, tid);
        asm volatile("cp.async.commit_group;" ::: "memory");
    }

    // ldmatrix per-lane addressing
    int arow = lane & 15, akb = lane >> 4;
    int bnrow = (lane & 7) + ((lane >> 4) & 1) * 8;
    int bkb = (lane >> 3) & 1;

    for (int kt = 0; kt < nK; kt++) {
        asm volatile("cp.async.wait_group 2;" ::: "memory");
        __syncthreads();
        // issue loads for stage kt+3 (slot (kt+3)&3 == (kt-1)&3, freed by the barrier)
        if (kt + 3 < nK)
            load_tile_h(sb + ((kt + 3) & 3) * GSTAGE_H * 2, A, lda, Bm, ldb, row0, col0, (kt + 3) * 32, tid);
        asm volatile("cp.async.commit_group;" ::: "memory");

        unsigned sA = sb + (kt & 3) * GSTAGE_H * 2;
        unsigned sB = sA + GTILE_H * 2;

        #pragma unroll
        for (int ks = 0; ks < 2; ks++) {
            unsigned af[4][4], bf[4][4];
            #pragma unroll
            for (int mt = 0; mt < 4; mt++) {
                unsigned addr = sA + (unsigned)(((warp_m * 64 + mt * 16 + arow) * GSTR
                                 + ks * 16 + akb * 8) * 2);
                ldsm_x4(af[mt][0], af[mt][1], af[mt][2], af[mt][3], addr);
            }
            #pragma unroll
            for (int nt2 = 0; nt2 < 4; nt2++) {
                unsigned addr = sB + (unsigned)(((warp_n * 64 + nt2 * 16 + bnrow) * GSTR
                                 + ks * 16 + bkb * 8) * 2);
                ldsm_x4(bf[nt2][0], bf[nt2][1], bf[nt2][2], bf[nt2][3], addr);
            }
            #pragma unroll
            for (int mt = 0; mt < 4; mt++)
                #pragma unroll
                for (int nt2 = 0; nt2 < 4; nt2++) {
                    mma_f16(acc[mt][2 * nt2],     af[mt][0], af[mt][1], af[mt][2], af[mt][3],
                            bf[nt2][0], bf[nt2][1]);
                    mma_f16(acc[mt][2 * nt2 + 1], af[mt][0], af[mt][1], af[mt][2], af[mt][3],
                            bf[nt2][2], bf[nt2][3]);
                }
        }
    }

    int g = lane >> 2, j = lane & 3;
    #pragma unroll
    for (int mt = 0; mt < 4; mt++) {
        int r = row0 + warp_m * 64 + mt * 16 + g;
        #pragma unroll
        for (int nt = 0; nt < 8; nt++) {
            int cg = col0 + warp_n * 64 + nt * 8 + j * 2;
            float b0 = bias[cg], b1 = bias[cg + 1];
            float v0 = acc[mt][nt][0] + b0, v1 = acc[mt][nt][1] + b1;
            float v2 = acc[mt][nt][2] + b0, v3 = acc[mt][nt][3] + b1;
            if (relu) {
                v0 = fmaxf(v0, 0.f); v1 = fmaxf(v1, 0.f);
                v2 = fmaxf(v2, 0.f); v3 = fmaxf(v3, 0.f);
            }
            if (Ch) {
                *(__half2*)(Ch + (long)r * ldc + cg) = __floats2half2_rn(v0, v1);
                *(__half2*)(Ch + (long)(r + 8) * ldc + cg) = __floats2half2_rn(v2, v3);
            } else {
                *(float2*)(C + (long)r * ldc + cg) = make_float2(v0, v1);
                *(float2*)(C + (long)(r + 8) * ldc + cg) = make_float2(v2, v3);
            }
        }
    }
}

// ======================= fp16 tensor-core flash attention =======================
// CTA: 128 queries (4 warps x 32 rows), 64-key tiles, double-buffered.
#define ASTR 72
#define AQ_OFF 0
#define AK_OFF (128 * ASTR)                 // 9216
#define AV_OFF (AK_OFF + 2 * 64 * ASTR)     // 18432
#define ASMEMH ((AV_OFF + 2 * 64 * ASTR) * 2)   // 55296 bytes

__global__ __launch_bounds__(128) void k_attn_h(const __half* __restrict__ qkv,
                                                __half* __restrict__ ctx)
{
    __half* sm = (__half*)smem_f;
    int tid = threadIdx.x, lane = tid & 31, wid = tid >> 5;
    int b = blockIdx.y >> 4, h = blockIdx.y & 15;
    int q0 = blockIdx.x * 128;
    const __half* base = qkv + (long)b * Sv * (3 * Dv) + h * HDv;
    unsigned sb = smem_u32(sm);
    int g = lane >> 2, j = lane & 3;
    int qb = wid * 32;
    int arow = lane & 15;
    int akb = lane >> 4;
    int l2 = lane & 15;

    // load Q tile + K/V tile 0
    #pragma unroll
    for (int i = 0; i < 8; i++) {
        int idx = i * 128 + tid;
        int r = idx >> 3, c = idx & 7;
        cpa16(sb + (unsigned)((AQ_OFF + r * ASTR + c * 8) * 2),
              base + (long)(q0 + r) * (3 * Dv) + c * 8);
    }
    #pragma unroll
    for (int i = 0; i < 4; i++) {
        int idx = i * 128 + tid;
        int r = idx >> 3, c = idx & 7;
        cpa16(sb + (unsigned)((AK_OFF + r * ASTR + c * 8) * 2), base + (long)r * (3 * Dv) + Dv + c * 8);
        cpa16(sb + (unsigned)((AV_OFF + r * ASTR + c * 8) * 2), base + (long)r * (3 * Dv) + 2 * Dv + c * 8);
    }
    asm volatile("cp.async.commit_group;" ::: "memory");
    asm volatile("cp.async.wait_group 0;" ::: "memory");
    __syncthreads();

    // hoist Q fragments (constant over key loop)
    unsigned qf[2][4][4];
    #pragma unroll
    for (int mt = 0; mt < 2; mt++)
        #pragma unroll
        for (int ks = 0; ks < 4; ks++) {
            unsigned addr = sb + (unsigned)(((qb + mt * 16 + arow) * ASTR + ks * 16 + akb * 8) * 2);
            ldsm_x4(qf[mt][ks][0], qf[mt][ks][1], qf[mt][ks][2], qf[mt][ks][3], addr);
        }

    float Oa[2][8][4];
    float mrow[4], lrow[4];
    #pragma unroll
    for (int i = 0; i < 4; i++) { mrow[i] = -1e30f; lrow[i] = 0.f; }
    #pragma unroll
    for (int mt = 0; mt < 2; mt++)
        #pragma unroll
        for (int nt = 0; nt < 8; nt++)
            #pragma unroll
            for (int q = 0; q < 4; q++) Oa[mt][nt][q] = 0.f;

    for (int kt = 0; kt < Sv / 64; kt++) {
        int st = kt & 1;
        if (kt + 1 < Sv / 64) {
            int st2 = (kt + 1) & 1;
            #pragma unroll
            for (int i = 0; i < 4; i++) {
                int idx = i * 128 + tid;
                int r = idx >> 3, c = idx & 7;
                long gr = (long)((kt + 1) * 64 + r) * (3 * Dv);
                cpa16(sb + (unsigned)((AK_OFF + st2 * 64 * ASTR + r * ASTR + c * 8) * 2), base + gr + Dv + c * 8);
                cpa16(sb + (unsigned)((AV_OFF + st2 * 64 * ASTR + r * ASTR + c * 8) * 2), base + gr + 2 * Dv + c * 8);
            }
            asm volatile("cp.async.commit_group;" ::: "memory");
            asm volatile("cp.async.wait_group 1;" ::: "memory");
        } else {
            asm volatile("cp.async.wait_group 0;" ::: "memory");
        }
        __syncthreads();

        unsigned sK = sb + (unsigned)((AK_OFF + st * 64 * ASTR) * 2);
        unsigned sV = sb + (unsigned)((AV_OFF + st * 64 * ASTR) * 2);

        // ---- S = Q K^T  (64 keys) ----
        float sacc[2][8][4];
        #pragma unroll
        for (int mt = 0; mt < 2; mt++)
            #pragma unroll
            for (int nt = 0; nt < 8; nt++)
                #pragma unroll
                for (int q = 0; q < 4; q++) sacc[mt][nt][q] = 0.f;

        #pragma unroll
        for (int ks = 0; ks < 4; ks++) {
            unsigned bf[4][4];
            #pragma unroll
            for (int nt2 = 0; nt2 < 4; nt2++) {
                unsigned addr = sK + (unsigned)(((nt2 * 16 + (lane & 7) + ((lane >> 4) & 1) * 8) * ASTR
                                 + ks * 16 + ((lane >> 3) & 1) * 8) * 2);
                ldsm_x4(bf[nt2][0], bf[nt2][1], bf[nt2][2], bf[nt2][3], addr);
            }
            #pragma unroll
            for (int mt = 0; mt < 2; mt++)
                #pragma unroll
                for (int nt2 = 0; nt2 < 4; nt2++) {
                    mma_f16(sacc[mt][2 * nt2],     qf[mt][ks][0], qf[mt][ks][1], qf[mt][ks][2], qf[mt][ks][3],
                            bf[nt2][0], bf[nt2][1]);
                    mma_f16(sacc[mt][2 * nt2 + 1], qf[mt][ks][0], qf[mt][ks][1], qf[mt][ks][2], qf[mt][ks][3],
                            bf[nt2][2], bf[nt2][3]);
                }
        }

        // ---- online softmax (scale 0.125) ----
        #pragma unroll
        for (int mt = 0; mt < 2; mt++)
            #pragma unroll
            for (int hh = 0; hh < 2; hh++) {
                int ri = mt * 2 + hh;
                float rmax = -1e30f;
                #pragma unroll
                for (int nt = 0; nt < 8; nt++) {
                    float v0 = sacc[mt][nt][hh * 2] * 0.125f;
                    float v1 = sacc[mt][nt][hh * 2 + 1] * 0.125f;
                    sacc[mt][nt][hh * 2] = v0; sacc[mt][nt][hh * 2 + 1] = v1;
                    rmax = fmaxf(rmax, fmaxf(v0, v1));
                }
                rmax = fmaxf(rmax, __shfl_xor_sync(0xffffffffu, rmax, 1));
                rmax = fmaxf(rmax, __shfl_xor_sync(0xffffffffu, rmax, 2));
                float mnew = fmaxf(mrow[ri], rmax);
                float corr = __expf(mrow[ri] - mnew);
                mrow[ri] = mnew;
                float ps = 0.f;
                #pragma unroll
                for (int nt = 0; nt < 8; nt++) {
                    float p0 = __expf(sacc[mt][nt][hh * 2] - mnew);
                    float p1 = __expf(sacc[mt][nt][hh * 2 + 1] - mnew);
                    sacc[mt][nt][hh * 2] = p0; sacc[mt][nt][hh * 2 + 1] = p1;
                    ps += p0 + p1;
                }
                ps += __shfl_xor_sync(0xffffffffu, ps, 1);
                ps += __shfl_xor_sync(0xffffffffu, ps, 2);
                lrow[ri] = lrow[ri] * corr + ps;
                #pragma unroll
                for (int nt = 0; nt < 8; nt++) {
                    Oa[mt][nt][hh * 2] *= corr;
                    Oa[mt][nt][hh * 2 + 1] *= corr;
                }
            }

        // ---- O += P V ---- (P packs directly into A fragments)
        #pragma unroll
        for (int ks = 0; ks < 4; ks++) {
            unsigned pa[2][4];
            #pragma unroll
            for (int mt = 0; mt < 2; mt++) {
                pa[mt][0] = pack_h2(sacc[mt][2 * ks][0],     sacc[mt][2 * ks][1]);
                pa[mt][1] = pack_h2(sacc[mt][2 * ks][2],     sacc[mt][2 * ks][3]);
                pa[mt][2] = pack_h2(sacc[mt][2 * ks + 1][0], sacc[mt][2 * ks + 1][1]);
                pa[mt][3] = pack_h2(sacc[mt][2 * ks + 1][2], sacc[mt][2 * ks + 1][3]);
            }
            #pragma unroll
            for (int nt = 0; nt < 8; nt++) {
                unsigned vb0, vb1;
                unsigned addr = sV + (unsigned)(((ks * 16 + (l2 & 7) + (l2 >> 3) * 8) * ASTR + nt * 8) * 2);
                ldsm_x2t(vb0, vb1, addr);
                #pragma unroll
                for (int mt = 0; mt < 2; mt++)
                    mma_f16(Oa[mt][nt], pa[mt][0], pa[mt][1], pa[mt][2], pa[mt][3], vb0, vb1);
            }
        }
        __syncthreads();
    }

    // ---- write ctx (fp16) ----
    #pragma unroll
    for (int mt = 0; mt < 2; mt++)
        #pragma unroll
        for (int hh = 0; hh < 2; hh++) {
            float inv = 1.f / lrow[mt * 2 + hh];
            int qrow = q0 + qb + mt * 16 + g + hh * 8;
            __half* op = ctx + ((long)(b * Sv) + qrow) * Dv + h * HDv;
            #pragma unroll
            for (int nt = 0; nt < 8; nt++) {
                *(__half2*)(op + nt * 8 + 2 * j) =
                    __floats2half2_rn(Oa[mt][nt][hh * 2] * inv, Oa[mt][nt][hh * 2 + 1] * inv);
            }
        }
}

// ======================= small kernels =======================
__global__ void k_init() {
    int i = blockIdx.x * blockDim.x + threadIdx.x;
    if (i < MAXP) g_gather[i] = -1;
    if (i < Ev) g_counts[i] = 0;
}

// fused: x1 = LN1(x + attn_out); logits = x1 @ gw^T + gb; top-2 routing
__global__ __launch_bounds__(256) void k_addln_gate(const float* __restrict__ xa,
                                                    const float* __restrict__ xb,
                                                    const float* __restrict__ g,
                                                    const float* __restrict__ bt,
                                                    const float* __restrict__ gw,
                                                    const float* __restrict__ gb,
                                                    float* __restrict__ x1out)
{
    __shared__ float red[256];
    __shared__ float sm8[256 * Ev];
    int n = blockIdx.x, tid = threadIdx.x;
    const float* pa = xa + (long)n * Dv;
    const float* pb = xb + (long)n * Dv;
    float v[4]; float s = 0.f;
    #pragma unroll
    for (int i = 0; i < 4; i++) { int d = tid + i * 256; v[i] = pa[d] + pb[d]; s += v[i]; }
    red[tid] = s; __syncthreads();
    for (int st = 128; st > 0; st >>= 1) { if (tid < st) red[tid] += red[tid + st]; __syncthreads(); }
    float mean = red[0] * (1.f / Dv);
    __syncthreads();
    float vs = 0.f;
    #pragma unroll
    for (int i = 0; i < 4; i++) { float t = v[i] - mean; vs += t * t; }
    red[tid] = vs; __syncthreads();
    for (int st = 128; st > 0; st >>= 1) { if (tid < st) red[tid] += red[tid + st]; __syncthreads(); }
    float rstd = rsqrtf(red[0] * (1.f / Dv) + LNEPS);

    float p[Ev];
    #pragma unroll
    for (int e = 0; e < Ev; e++) p[e] = 0.f;
    #pragma unroll
    for (int i = 0; i < 4; i++) {
        int d = tid + i * 256;
        float xv = (v[i] - mean) * rstd * g[d] + bt[d];
        x1out[(long)n * Dv + d] = xv;
        #pragma unroll
        for (int e = 0; e < Ev; e++) p[e] += xv * gw[e * Dv + d];
    }
    #pragma unroll
    for (int e = 0; e < Ev; e++) sm8[tid * Ev + e] = p[e];
    __syncthreads();
    for (int st = 128; st > 0; st >>= 1) {
        if (tid < st)
            #pragma unroll
            for (int e = 0; e < Ev; e++) sm8[tid * Ev + e] += sm8[(tid + st) * Ev + e];
        __syncthreads();
    }
    if (tid == 0) {
        float l[Ev];
        #pragma unroll
        for (int e = 0; e < Ev; e++) { l[e] = sm8[e] + gb[e]; g_logits[(long)n * Ev + e] = l[e]; }
        int i0 = 0;
        #pragma unroll
        for (int e = 1; e < Ev; e++) if (l[e] > l[i0]) i0 = e;
        int i1 = -1;
        #pragma unroll
        for (int e = 0; e < Ev; e++) { if (e == i0) continue; if (i1 < 0 || l[e] > l[i1]) i1 = e; }
        float e1 = expf(l[i1] - l[i0]);
        float denom = 1.f + e1;
        g_topE[n * 2 + 0] = i0; g_topE[n * 2 + 1] = i1;
        g_topw[n * 2 + 0] = 1.f / denom; g_topw[n * 2 + 1] = e1 / denom;
        atomicAdd(&g_counts[i0], 1);
        atomicAdd(&g_counts[i1], 1);
    }
}

__global__ void k_scan() {
    if (threadIdx.x == 0) {
        int t = 0;
        for (int e = 0; e < Ev; e++) {
            g_off[e] = t; g_cursor[e] = t;
            t += (g_counts[e] + 127) & ~127;
        }
        g_off[Ev] = t;
        g_Mpad[0] = t;
    }
}

__global__ void k_assign() {
    int i = blockIdx.x * blockDim.x + threadIdx.x;
    if (i >= NTOK * 2) return;
    int e = g_topE[i];
    int p = atomicAdd(&g_cursor[e], 1);
    g_gather[p] = i >> 1;
    g_pos[i] = p;
}

__global__ __launch_bounds__(256) void k_gather(const float* __restrict__ x1,
                                                __half* __restrict__ xg)
{
    int p = blockIdx.x;
    int g = g_gather[p];
    __half2* dst = (__half2*)(xg + (long)p * Dv);
    int t = threadIdx.x;
    if (g >= 0) {
        float4 v = ((const float4*)(x1 + (long)g * Dv))[t];
        dst[2 * t]     = __floats2half2_rn(v.x, v.y);
        dst[2 * t + 1] = __floats2half2_rn(v.z, v.w);
    } else {
        dst[2 * t] = __floats2half2_rn(0.f, 0.f);
        dst[2 * t + 1] = __floats2half2_rn(0.f, 0.f);
    }
}

__global__ __launch_bounds__(256) void k_scatter_ln2(const float* __restrict__ x1,
                                                     const float* __restrict__ g,
                                                     const float* __restrict__ bt,
                                                     float* __restrict__ out)
{
    __shared__ float red[256];
    int n = blockIdx.x, tid = threadIdx.x;
    int p0 = g_pos[n * 2 + 0], p1 = g_pos[n * 2 + 1];
    float w0 = g_topw[n * 2 + 0], w1 = g_topw[n * 2 + 1];
    const float* px = x1 + (long)n * Dv;
    const float* pe0 = g_eo + (long)p0 * Dv;
    const float* pe1 = g_eo + (long)p1 * Dv;
    float v[4]; float s = 0.f;
    #pragma unroll
    for (int i = 0; i < 4; i++) {
        int d = tid + i * 256;
        v[i] = px[d] + w0 * pe0[d] + w1 * pe1[d];
        s += v[i];
    }
    red[tid] = s; __syncthreads();
    for (int st = 128; st > 0; st >>= 1) { if (tid < st) red[tid] += red[tid + st]; __syncthreads(); }
    float mean = red[0] * (1.f / Dv);
    __syncthreads();
    float vs = 0.f;
    #pragma unroll
    for (int i = 0; i < 4; i++) { float t = v[i] - mean; vs += t * t; }
    red[tid] = vs; __syncthreads();
    for (int st = 128; st > 0; st >>= 1) { if (tid < st) red[tid] += red[tid + st]; __syncthreads(); }
    float rstd = rsqrtf(red[0] * (1.f / Dv) + LNEPS);
    #pragma unroll
    for (int i = 0; i < 4; i++) {
        int d = tid + i * 256;
        out[(long)n * Dv + d] = (v[i] - mean) * rstd * g[d] + bt[d];
    }
}

__global__ __launch_bounds__(256) void k_lb(float* __restrict__ out) {
    __shared__ float sm[256][Ev];
    int tid = threadIdx.x;
    float u[Ev];
    #pragma unroll
    for (int e = 0; e < Ev; e++) u[e] = 0.f;
    for (int n = tid; n < NTOK; n += 256) {
        float l[Ev], mx = -1e30f, s = 0.f;
        #pragma unroll
        for (int e = 0; e < Ev; e++) { l[e] = g_logits[(long)n * Ev + e]; mx = fmaxf(mx, l[e]); }
        #pragma unroll
        for (int e = 0; e < Ev; e++) { l[e] = expf(l[e] - mx); s += l[e]; }
        float inv = 1.f / s;
        #pragma unroll
        for (int e = 0; e < Ev; e++) u[e] += l[e] * inv;
    }
    #pragma unroll
    for (int e = 0; e < Ev; e++) sm[tid][e] = u[e];
    __syncthreads();
    for (int st = 128; st > 0; st >>= 1) {
        if (tid < st)
            #pragma unroll
            for (int e = 0; e < Ev; e++) sm[tid][e] += sm[tid + st][e];
        __syncthreads();
    }
    if (tid == 0) {
        float lb = 0.f;
        #pragma unroll
        for (int e = 0; e < Ev; e++) { float us = sm[0][e] * (1.f / NTOK); lb += us * us; }
        out[0] = (float)Ev * lb;
    }
}

// ======================= launch =======================
static void* symaddr(const void* s) { void* p = nullptr; cudaGetSymbolAddress(&p, s); return p; }

extern "C" void kernel_launch(void* const* d_in, const int* in_sizes, int n_in,
                              void* d_out, int out_size)
{
    (void)in_sizes; (void)n_in;
    const float* x    = (const float*)d_in[0];
    const float* inw  = (const float*)d_in[1];
    const float* inb  = (const float*)d_in[2];
    const float* outw = (const float*)d_in[3];
    const float* outb = (const float*)d_in[4];
    const float* ln1g = (const float*)d_in[5];
    const float* ln1b = (const float*)d_in[6];
    const float* gw   = (const float*)d_in[7];
    const float* gb   = (const float*)d_in[8];
    const float* w1   = (const float*)d_in[9];
    const float* b1   = (const float*)d_in[10];
    const float* w2   = (const float*)d_in[11];
    const float* b2   = (const float*)d_in[12];
    const float* ln2g = (const float*)d_in[13];
    const float* ln2b = (const float*)d_in[14];
    float* out = (float*)d_out;

    __half* p_xh    = (__half*)symaddr(g_xh);
    __half* p_qkvh  = (__half*)symaddr(g_qkvh);
    __half* p_ctxh  = (__half*)symaddr(g_ctxh);
    __half* p_xgh   = (__half*)symaddr(g_xgh);
    __half* p_hh    = (__half*)symaddr(g_hh);
    __half* p_inwh  = (__half*)symaddr(g_inwh);
    __half* p_outwh = (__half*)symaddr(g_outwh);
    __half* p_w1h   = (__half*)symaddr(g_w1h);
    __half* p_w2h   = (__half*)symaddr(g_w2h);
    float* p_ao   = (float*)symaddr(g_attnout);
    float* p_x1   = (float*)symaddr(g_x1);
    float* p_eo   = (float*)symaddr(g_eo);
    int*   p_Mpad = (int*)symaddr(g_Mpad);
    int*   p_off  = (int*)symaddr(g_off);

    cudaFuncSetAttribute(gemm_h, cudaFuncAttributeMaxDynamicSharedMemorySize, GSMEMH);
    cudaFuncSetAttribute(k_attn_h, cudaFuncAttributeMaxDynamicSharedMemorySize, ASMEMH);

    // side stream + events (created once on the first, uncaptured call)
    static cudaStream_t s_side = nullptr;
    static cudaEvent_t ev_fork = nullptr, ev_join = nullptr, ev_gate = nullptr, ev_lb = nullptr;
    if (!s_side) {
        cudaStreamCreateWithFlags(&s_side, cudaStreamNonBlocking);
        cudaEventCreateWithFlags(&ev_fork, cudaEventDisableTiming);
        cudaEventCreateWithFlags(&ev_join, cudaEventDisableTiming);
        cudaEventCreateWithFlags(&ev_gate, cudaEventDisableTiming);
        cudaEventCreateWithFlags(&ev_lb, cudaEventDisableTiming);
    }

    // ---- fork: w1/w2 conversions run on side stream (needed at step 10)
    cudaEventRecord(ev_fork, 0);
    cudaStreamWaitEvent(s_side, ev_fork, 0);
    {
        long n1 = (long)Ev * FFv * Dv;
        int n4 = (int)(n1 / 4);
        k_f2h<<<(n4 + 255) / 256, 256, 0, s_side>>>((const float4*)w1, (__half2*)p_w1h, n4);
        k_f2h<<<(n4 + 255) / 256, 256, 0, s_side>>>((const float4*)w2, (__half2*)p_w2h, n4);
    }
    cudaEventRecord(ev_join, s_side);

    // ---- main stream: conversions needed early
    {
        struct { const float* src; __half* dst; long n; } cv[3] = {
            { x,    p_xh,    (long)NTOK * Dv },
            { inw,  p_inwh,  (long)3 * Dv * Dv },
            { outw, p_outwh, (long)Dv * Dv },
        };
        for (int i = 0; i < 3; i++) {
            int n4 = (int)(cv[i].n / 4);
            k_f2h<<<(n4 + 255) / 256, 256>>>((const float4*)cv[i].src, (__half2*)cv[i].dst, n4);
        }
    }

    // 1. routing state init
    k_init<<<(MAXP + 255) / 256, 256>>>();

    // 2. qkv = x @ in_proj_w^T + b  -> fp16
    gemm_h<<<dim3(3 * Dv / 128, NTOK / 128), 128, GSMEMH>>>(
        p_xh, p_inwh, inb, nullptr, p_qkvh, Dv, Dv, Dv, 3 * Dv,
        nullptr, nullptr, 0, 0, 0);

    // 3. attention -> ctx (fp16)
    k_attn_h<<<dim3(Sv / 128, Bv * Hv), 128, ASMEMH>>>(p_qkvh, p_ctxh);

    // 4. attn_out = ctx @ out_w^T + b  -> fp32
    gemm_h<<<dim3(Dv / 128, NTOK / 128), 128, GSMEMH>>>(
        p_ctxh, p_outwh, outb, p_ao, nullptr, Dv, Dv, Dv, Dv,
        nullptr, nullptr, 0, 0, 0);

    // 5+6. x1 = LN1(x + attn_out) fused with gate logits/top-2
    k_addln_gate<<<NTOK, 256>>>(x, p_ao, ln1g, ln1b, gw, gb, p_x1);

    // lb_loss depends only on logits: run it on the side stream, overlapped
    cudaEventRecord(ev_gate, 0);
    cudaStreamWaitEvent(s_side, ev_gate, 0);
    if (out_size > NTOK * Dv) {
        k_lb<<<1, 256, 0, s_side>>>(out + (size_t)NTOK * Dv);
    }
    cudaEventRecord(ev_lb, s_side);

    // 7-8. routing
    k_scan<<<1, 32>>>();
    k_assign<<<(NTOK * 2 + 255) / 256, 256>>>();

    // 9. gather tokens -> fp16
    k_gather<<<MAXP, 256>>>(p_x1, p_xgh);

    // ---- join: w1/w2 fp16 must be ready before the MoE GEMMs
    cudaStreamWaitEvent(0, ev_join, 0);

    // 10. h = relu(xg @ w1[e]^T + b1[e]) -> fp16
    gemm_h<<<dim3(FFv / 128, MAXP / 128), 128, GSMEMH>>>(
        p_xgh, p_w1h, b1, nullptr, p_hh, Dv, Dv, Dv, FFv,
        p_Mpad, p_off, (long)FFv * Dv, FFv, 1);

    // 11. eo = h @ w2[e]^T + b2[e] -> fp32
    gemm_h<<<dim3(Dv / 128, MAXP / 128), 128, GSMEMH>>>(
        p_hh, p_w2h, b2, p_eo, nullptr, FFv, FFv, FFv, Dv,
        p_Mpad, p_off, (long)Dv * FFv, Dv, 0);

    // 12. out = LN2(x1 + moe)
    k_scatter_ln2<<<NTOK, 256>>>(p_x1, ln2g, ln2b, out);

    // rejoin side stream (lb) before capture ends
    cudaStreamWaitEvent(0, ev_lb, 0);
}